// round 7
// baseline (speedup 1.0000x reference)
#include <cuda_runtime.h>
#include <cstdint>
#include <math.h>

#define Bc   2
#define Sc   2048
#define TOK  4096
#define Ec   1024
#define Hc   16
#define HDc  64
#define MLPc 4096

// ---------------- scratch (no allocations allowed) ----------------
__device__ float g_z0[(size_t)TOK * Ec];
__device__ float g_q [(size_t)TOK * Ec];
__device__ float g_k [(size_t)TOK * Ec];
__device__ float g_v [(size_t)TOK * Ec];
__device__ float g_ctx[(size_t)TOK * Ec];
__device__ float g_x1[(size_t)TOK * Ec];
__device__ float g_z1[(size_t)TOK * Ec];
__device__ float g_h [(size_t)TOK * MLPc];
__device__ float g_wqkvT[(size_t)3 * Ec * Ec];
__device__ float g_woT[(size_t)Ec * Ec];
__device__ float g_w1T[(size_t)Ec * MLPc];
__device__ float g_w2T[(size_t)MLPc * Ec];

// ---------------- helpers ----------------
__device__ __forceinline__ unsigned f2tf(float f) {
    unsigned r;
    asm("cvt.rna.tf32.f32 %0, %1;" : "=r"(r) : "f"(f));
    return r;
}
__device__ __forceinline__ float tfround(float f) {
    return __uint_as_float(f2tf(f));
}
__device__ __forceinline__ uint32_t smem_u32(const void* p) {
    uint32_t a;
    asm("{ .reg .u64 t; cvta.to.shared.u64 t, %1; cvt.u32.u64 %0, t; }" : "=r"(a) : "l"(p));
    return a;
}
__device__ __forceinline__ void cp16(uint32_t d, const void* s) {
    asm volatile("cp.async.cg.shared.global [%0], [%1], 16;\n" :: "r"(d), "l"(s));
}
__device__ __forceinline__ void cp_commit() {
    asm volatile("cp.async.commit_group;\n" ::: "memory");
}
#define CP_WAIT(n) asm volatile("cp.async.wait_group %0;\n" :: "n"(n) : "memory")

__device__ __forceinline__ void mma8(float c[4], const unsigned a[4], const unsigned b[2]) {
    asm volatile(
        "mma.sync.aligned.m16n8k8.row.col.f32.tf32.tf32.f32 "
        "{%0,%1,%2,%3}, {%4,%5,%6,%7}, {%8,%9}, {%0,%1,%2,%3};\n"
        : "+f"(c[0]), "+f"(c[1]), "+f"(c[2]), "+f"(c[3])
        : "r"(a[0]), "r"(a[1]), "r"(a[2]), "r"(a[3]),
          "r"(b[0]), "r"(b[1]));
}

// ---------------- weight transposes (+ tf32 rounding) ----------------
__global__ void __launch_bounds__(256) transpose4_kernel(
    const float* __restrict__ i0, const float* __restrict__ i1,
    const float* __restrict__ i2, const float* __restrict__ i3,
    float* __restrict__ o0, float* __restrict__ o1,
    float* __restrict__ o2, float* __restrict__ o3)
{
    const float* in  = (blockIdx.z == 0) ? i0 : (blockIdx.z == 1) ? i1 : (blockIdx.z == 2) ? i2 : i3;
    float*       out = (blockIdx.z == 0) ? o0 : (blockIdx.z == 1) ? o1 : (blockIdx.z == 2) ? o2 : o3;
    __shared__ float tile[32][33];
    const int bx = blockIdx.x * 32, by = blockIdx.y * 32;
    const int tx = threadIdx.x & 31, ty = threadIdx.x >> 5;
    #pragma unroll
    for (int i = 0; i < 32; i += 8)
        tile[ty + i][tx] = tfround(in[(size_t)(by + ty + i) * Ec + bx + tx]);
    __syncthreads();
    #pragma unroll
    for (int i = 0; i < 32; i += 8)
        out[(size_t)(bx + ty + i) * Ec + by + tx] = tile[tx][ty + i];
}

__global__ void __launch_bounds__(256) transpose_kernel(
    const float* __restrict__ in, float* __restrict__ out, int R, int C)
{
    __shared__ float tile[32][33];
    const int bx = blockIdx.x * 32, by = blockIdx.y * 32;
    const int tx = threadIdx.x & 31, ty = threadIdx.x >> 5;
    #pragma unroll
    for (int i = 0; i < 32; i += 8)
        tile[ty + i][tx] = tfround(in[(size_t)(by + ty + i) * C + bx + tx]);
    __syncthreads();
    #pragma unroll
    for (int i = 0; i < 32; i += 8)
        out[(size_t)(bx + ty + i) * R + by + tx] = tile[tx][ty + i];
}

// ---------------- LayerNorm (fp32 exact, tf32-rounded output) ----------------
__global__ void __launch_bounds__(256) ln_kernel(
    const float* __restrict__ x, const float* __restrict__ gam,
    const float* __restrict__ bet, float* __restrict__ y)
{
    const int row = blockIdx.x, t = threadIdx.x;
    const float4* xr = reinterpret_cast<const float4*>(x + (size_t)row * Ec);
    float4 v = xr[t];
    float s  = v.x + v.y + v.z + v.w;
    float ss = v.x*v.x + v.y*v.y + v.z*v.z + v.w*v.w;
    #pragma unroll
    for (int o = 16; o; o >>= 1) {
        s  += __shfl_xor_sync(0xffffffffu, s,  o);
        ss += __shfl_xor_sync(0xffffffffu, ss, o);
    }
    __shared__ float rs[8], rss[8];
    if ((t & 31) == 0) { rs[t >> 5] = s; rss[t >> 5] = ss; }
    __syncthreads();
    if (t < 32) {
        float a = (t < 8) ? rs[t]  : 0.f;
        float b = (t < 8) ? rss[t] : 0.f;
        #pragma unroll
        for (int o = 4; o; o >>= 1) {
            a += __shfl_xor_sync(0xffffffffu, a, o);
            b += __shfl_xor_sync(0xffffffffu, b, o);
        }
        if (t == 0) { rs[0] = a; rss[0] = b; }
    }
    __syncthreads();
    const float mu   = rs[0]  * (1.f / Ec);
    const float var  = rss[0] * (1.f / Ec) - mu * mu;
    const float rstd = rsqrtf(var + 1e-5f);
    float4 gv = reinterpret_cast<const float4*>(gam)[t];
    float4 bv = reinterpret_cast<const float4*>(bet)[t];
    float4 o;
    o.x = tfround((v.x - mu) * rstd * gv.x + bv.x);
    o.y = tfround((v.y - mu) * rstd * gv.y + bv.y);
    o.z = tfround((v.z - mu) * rstd * gv.z + bv.z);
    o.w = tfround((v.w - mu) * rstd * gv.w + bv.w);
    reinterpret_cast<float4*>(y + (size_t)row * Ec)[t] = o;
}

// ---------------- TF32 GEMM mainloop (3-stage, k-tile 32, 256 thr, warp 64x32) --
#define KT   32
#define SW   36                    // words per 32-float row (+4 pad)
#define STG  (128 * SW)            // words per operand stage (4608)
#define NSTG 3
#define SMEM_GEMM (2 * NSTG * STG * 4)   // 110592 bytes

__device__ __forceinline__ void ldstage(uint32_t ab, uint32_t bb,
    const float* __restrict__ Ap, const float* __restrict__ Bp, int K, int kt)
{
    const int t = threadIdx.x;
    const int k0 = kt * KT;
    #pragma unroll
    for (int i = 0; i < 4; i++) {
        const int idx = t + i * 256;
        const int r = idx >> 3, cu = (idx & 7) * 4;
        cp16(ab + (r * SW + cu) * 4, Ap + (size_t)r * K + k0 + cu);
    }
    #pragma unroll
    for (int i = 0; i < 4; i++) {
        const int idx = t + i * 256;
        const int r = idx >> 3, cu = (idx & 7) * 4;
        cp16(bb + (r * SW + cu) * 4, Bp + (size_t)r * K + k0 + cu);
    }
}

__device__ __forceinline__ void gemm_mainloop(
    const float* __restrict__ Ap, const float* __restrict__ Bp, int K,
    float* smem, float acc[4][4][4])
{
    const int t    = threadIdx.x;
    const int lane = t & 31, warp = t >> 5;
    const int wm = warp >> 2, wn = warp & 3;      // 2 x 4 warp grid
    const int g  = lane >> 2, t4 = lane & 3;
    const int NK = K / KT;

    const uint32_t asb = smem_u32(smem);
    const uint32_t bsb = asb + NSTG * STG * 4;

    ldstage(asb, bsb, Ap, Bp, K, 0);
    cp_commit();
    ldstage(asb + STG*4, bsb + STG*4, Ap, Bp, K, 1);
    cp_commit();

    int st = 0;
    for (int kt = 0; kt < NK; kt++) {
        CP_WAIT(1);
        __syncthreads();
        const float* as = smem + st * STG;
        const float* bs = smem + NSTG * STG + st * STG;
        // prefetch stage kt+2
        if (kt + 2 < NK) {
            int ps = st + 2; if (ps >= NSTG) ps -= NSTG;
            ldstage(asb + ps * STG * 4, bsb + ps * STG * 4, Ap, Bp, K, kt + 2);
        }
        cp_commit();
        #pragma unroll
        for (int kb = 0; kb < KT; kb += 8) {
            unsigned af[4][4], bf[4][2];
            #pragma unroll
            for (int mi = 0; mi < 4; mi++) {
                const float* ar = as + (wm*64 + mi*16 + g) * SW + kb + t4;
                af[mi][0] = __float_as_uint(ar[0]);
                af[mi][1] = __float_as_uint(ar[8 * SW]);
                af[mi][2] = __float_as_uint(ar[4]);
                af[mi][3] = __float_as_uint(ar[8 * SW + 4]);
            }
            #pragma unroll
            for (int ni = 0; ni < 4; ni++) {
                const float* br = bs + (wn*32 + ni*8 + g) * SW + kb + t4;
                bf[ni][0] = __float_as_uint(br[0]);
                bf[ni][1] = __float_as_uint(br[4]);
            }
            #pragma unroll
            for (int mi = 0; mi < 4; mi++)
                #pragma unroll
                for (int ni = 0; ni < 4; ni++)
                    mma8(acc[mi][ni], af[mi], bf[ni]);
        }
        st++; if (st == NSTG) st = 0;
    }
}

// EPI: 0 = bias(->tf32), 1 = bias+res (fp32), 2 = bias+gelu(->tf32)
template <int EPI>
__global__ void __launch_bounds__(256, 2) tc_gemm(
    const float* __restrict__ A, const float* __restrict__ BT,
    const float* __restrict__ bias, const float* __restrict__ res,
    float* __restrict__ C, int M, int N, int K)
{
    extern __shared__ float smem[];
    const int t = threadIdx.x;
    const int lane = t & 31, warp = t >> 5;
    const int wm = warp >> 2, wn = warp & 3;
    const int g  = lane >> 2, t4 = lane & 3;
    const int bm = blockIdx.y * 128, bn = blockIdx.x * 128;

    float acc[4][4][4];
    #pragma unroll
    for (int mi = 0; mi < 4; mi++)
        #pragma unroll
        for (int ni = 0; ni < 4; ni++)
            #pragma unroll
            for (int c = 0; c < 4; c++) acc[mi][ni][c] = 0.f;

    gemm_mainloop(A + (size_t)bm * K, BT + (size_t)bn * K, K, smem, acc);

    #pragma unroll
    for (int mi = 0; mi < 4; mi++) {
        #pragma unroll
        for (int half = 0; half < 2; half++) {
            const int row = bm + wm*64 + mi*16 + g + half*8;
            #pragma unroll
            for (int ni = 0; ni < 4; ni++) {
                const int col = bn + wn*32 + ni*8 + t4*2;
                float vx = acc[mi][ni][half*2 + 0] + __ldg(bias + col);
                float vy = acc[mi][ni][half*2 + 1] + __ldg(bias + col + 1);
                if (EPI == 1) {
                    vx += __ldg(res + (size_t)row * N + col);
                    vy += __ldg(res + (size_t)row * N + col + 1);
                } else if (EPI == 2) {
                    vx = 0.5f * vx * (1.f + erff(vx * 0.70710678118654752f));
                    vy = 0.5f * vy * (1.f + erff(vy * 0.70710678118654752f));
                    vx = tfround(vx); vy = tfround(vy);
                } else {
                    vx = tfround(vx); vy = tfround(vy);
                }
                float2 o; o.x = vx; o.y = vy;
                *reinterpret_cast<float2*>(C + (size_t)row * N + col) = o;
            }
        }
    }
}

// fused QKV: BT = wqkvT [3072][1024]; grid.x = 24 (3 outputs x 8 col-blocks)
__global__ void __launch_bounds__(256, 2) tc_gemm_qkv(
    const float* __restrict__ A, const float* __restrict__ BT,
    const float* __restrict__ bq, const float* __restrict__ bk,
    const float* __restrict__ bv,
    float* __restrict__ q, float* __restrict__ k, float* __restrict__ v, int K)
{
    extern __shared__ float smem[];
    const int t = threadIdx.x;
    const int lane = t & 31, warp = t >> 5;
    const int wm = warp >> 2, wn = warp & 3;
    const int g  = lane >> 2, t4 = lane & 3;
    const int which = blockIdx.x >> 3;
    const int bn = (blockIdx.x & 7) * 128;
    const int bm = blockIdx.y * 128;
    const float* bias = (which == 0) ? bq : (which == 1) ? bk : bv;
    float* C = (which == 0) ? q : (which == 1) ? k : v;

    float acc[4][4][4];
    #pragma unroll
    for (int mi = 0; mi < 4; mi++)
        #pragma unroll
        for (int ni = 0; ni < 4; ni++)
            #pragma unroll
            for (int c = 0; c < 4; c++) acc[mi][ni][c] = 0.f;

    gemm_mainloop(A + (size_t)bm * K, BT + (size_t)(which * Ec + bn) * K, K, smem, acc);

    #pragma unroll
    for (int mi = 0; mi < 4; mi++) {
        #pragma unroll
        for (int half = 0; half < 2; half++) {
            const int row = bm + wm*64 + mi*16 + g + half*8;
            #pragma unroll
            for (int ni = 0; ni < 4; ni++) {
                const int col = bn + wn*32 + ni*8 + t4*2;
                float vx = tfround(acc[mi][ni][half*2 + 0] + __ldg(bias + col));
                float vy = tfround(acc[mi][ni][half*2 + 1] + __ldg(bias + col + 1));
                float2 o; o.x = vx; o.y = vy;
                *reinterpret_cast<float2*>(C + (size_t)row * Ec + col) = o;
            }
        }
    }
}

// ---------------- fused flash attention (pipelined cp.async, tf32 mma) ----------
#define QS_LD 68
#define KS_LD 68
#define VS_LD 72
#define PS_LD 132
#define ATTN_SMEM ((128*QS_LD + 2*128*KS_LD + 128*VS_LD + 128*PS_LD) * 4)  // 208896

__global__ void __launch_bounds__(256) attn_kernel(
    const float* __restrict__ q, const float* __restrict__ kg,
    const float* __restrict__ vg, float* __restrict__ ctx)
{
    extern __shared__ unsigned sm[];
    unsigned* Qs = sm;
    unsigned* Ks = Qs + 128 * QS_LD;     // 2 buffers
    unsigned* Vs = Ks + 2 * 128 * KS_LD;
    unsigned* Ps = Vs + 128 * VS_LD;

    const int t = threadIdx.x, lane = t & 31, warp = t >> 5;
    const int g = lane >> 2, t4 = lane & 3;
    const int b = blockIdx.y >> 4, h = blockIdx.y & 15;
    const size_t base = (size_t)b * Sc * Ec + (size_t)h * HDc;
    const float* qp = q  + base + (size_t)blockIdx.x * 128 * Ec;
    const float* kp = kg + base;
    const float* vp = vg + base;

    const uint32_t qb = smem_u32(Qs);
    const uint32_t kb = smem_u32(Ks);
    const uint32_t vb = smem_u32(Vs);

    #pragma unroll
    for (int i = 0; i < 8; i++) {
        const int lin = t + i*256;
        const int r = lin >> 4, c = (lin & 15) * 4;
        cp16(qb + (r*QS_LD + c)*4, qp + (size_t)r * Ec + c);
        cp16(kb + (r*KS_LD + c)*4, kp + (size_t)r * Ec + c);
    }
    cp_commit();

    float o[8][4];
    #pragma unroll
    for (int ni = 0; ni < 8; ni++)
        #pragma unroll
        for (int c = 0; c < 4; c++) o[ni][c] = 0.f;
    float m0 = -INFINITY, m1 = -INFINITY, l0 = 0.f, l1 = 0.f;
    const int pr0 = warp*16 + g;

    for (int kt = 0; kt < 16; kt++) {
        __syncthreads();
        #pragma unroll
        for (int i = 0; i < 8; i++) {
            const int lin = t + i*256;
            const int r = lin >> 4, c = (lin & 15) * 4;
            cp16(vb + (r*VS_LD + c)*4, vp + (size_t)(kt*128 + r) * Ec + c);
        }
        cp_commit();
        if (kt < 15) {
            const uint32_t kbn = kb + ((kt+1)&1) * (128*KS_LD*4);
            #pragma unroll
            for (int i = 0; i < 8; i++) {
                const int lin = t + i*256;
                const int r = lin >> 4, c = (lin & 15) * 4;
                cp16(kbn + (r*KS_LD + c)*4, kp + (size_t)((kt+1)*128 + r) * Ec + c);
            }
        }
        cp_commit();
        CP_WAIT(2);
        __syncthreads();

        const unsigned* Kc = Ks + (kt & 1) * 128 * KS_LD;

        float sacc[16][4];
        #pragma unroll
        for (int ni = 0; ni < 16; ni++)
            #pragma unroll
            for (int c = 0; c < 4; c++) sacc[ni][c] = 0.f;
        #pragma unroll
        for (int kk = 0; kk < 8; kk++) {
            const int kbo = kk * 8;
            unsigned a[4];
            a[0] = Qs[pr0      * QS_LD + kbo + t4];
            a[1] = Qs[(pr0+8)  * QS_LD + kbo + t4];
            a[2] = Qs[pr0      * QS_LD + kbo + t4 + 4];
            a[3] = Qs[(pr0+8)  * QS_LD + kbo + t4 + 4];
            #pragma unroll
            for (int ni = 0; ni < 16; ni++) {
                unsigned bb[2];
                const int j = ni*8 + g;
                bb[0] = Kc[j*KS_LD + kbo + t4];
                bb[1] = Kc[j*KS_LD + kbo + t4 + 4];
                mma8(sacc[ni], a, bb);
            }
        }

        float rm0 = -INFINITY, rm1 = -INFINITY;
        #pragma unroll
        for (int ni = 0; ni < 16; ni++) {
            sacc[ni][0] *= 0.125f; sacc[ni][1] *= 0.125f;
            sacc[ni][2] *= 0.125f; sacc[ni][3] *= 0.125f;
            rm0 = fmaxf(rm0, fmaxf(sacc[ni][0], sacc[ni][1]));
            rm1 = fmaxf(rm1, fmaxf(sacc[ni][2], sacc[ni][3]));
        }
        rm0 = fmaxf(rm0, __shfl_xor_sync(0xffffffffu, rm0, 1));
        rm0 = fmaxf(rm0, __shfl_xor_sync(0xffffffffu, rm0, 2));
        rm1 = fmaxf(rm1, __shfl_xor_sync(0xffffffffu, rm1, 1));
        rm1 = fmaxf(rm1, __shfl_xor_sync(0xffffffffu, rm1, 2));
        const float mn0 = fmaxf(m0, rm0), mn1 = fmaxf(m1, rm1);
        const float al0 = __expf(m0 - mn0), al1 = __expf(m1 - mn1);
        float ps0 = 0.f, ps1 = 0.f;
        #pragma unroll
        for (int ni = 0; ni < 16; ni++) {
            float p0 = __expf(sacc[ni][0] - mn0);
            float p1 = __expf(sacc[ni][1] - mn0);
            float p2 = __expf(sacc[ni][2] - mn1);
            float p3 = __expf(sacc[ni][3] - mn1);
            ps0 += p0 + p1; ps1 += p2 + p3;
            const int col = ni*8 + t4*2;
            Ps[pr0     * PS_LD + col    ] = __float_as_uint(p0);
            Ps[pr0     * PS_LD + col + 1] = __float_as_uint(p1);
            Ps[(pr0+8) * PS_LD + col    ] = __float_as_uint(p2);
            Ps[(pr0+8) * PS_LD + col + 1] = __float_as_uint(p3);
        }
        ps0 += __shfl_xor_sync(0xffffffffu, ps0, 1);
        ps0 += __shfl_xor_sync(0xffffffffu, ps0, 2);
        ps1 += __shfl_xor_sync(0xffffffffu, ps1, 1);
        ps1 += __shfl_xor_sync(0xffffffffu, ps1, 2);
        l0 = l0 * al0 + ps0; l1 = l1 * al1 + ps1;
        m0 = mn0; m1 = mn1;
        #pragma unroll
        for (int ni = 0; ni < 8; ni++) {
            o[ni][0] *= al0; o[ni][1] *= al0;
            o[ni][2] *= al1; o[ni][3] *= al1;
        }
        __syncwarp();

        CP_WAIT(1);
        __syncthreads();

        #pragma unroll
        for (int kk = 0; kk < 16; kk++) {
            const int kbo = kk * 8;
            unsigned a[4];
            a[0] = Ps[pr0     * PS_LD + kbo + t4];
            a[1] = Ps[(pr0+8) * PS_LD + kbo + t4];
            a[2] = Ps[pr0     * PS_LD + kbo + t4 + 4];
            a[3] = Ps[(pr0+8) * PS_LD + kbo + t4 + 4];
            #pragma unroll
            for (int ni = 0; ni < 8; ni++) {
                unsigned bb[2];
                const int d = ni*8 + g;
                bb[0] = Vs[(kbo + t4    ) * VS_LD + d];
                bb[1] = Vs[(kbo + t4 + 4) * VS_LD + d];
                mma8(o[ni], a, bb);
            }
        }
    }

    const float inv0 = 1.f / l0, inv1 = 1.f / l1;
    float* cp = ctx + base + (size_t)blockIdx.x * 128 * Ec;
    #pragma unroll
    for (int ni = 0; ni < 8; ni++) {
        const int d = ni*8 + t4*2;
        float2 u0; u0.x = tfround(o[ni][0] * inv0); u0.y = tfround(o[ni][1] * inv0);
        float2 u1; u1.x = tfround(o[ni][2] * inv1); u1.y = tfround(o[ni][3] * inv1);
        *reinterpret_cast<float2*>(cp + (size_t)pr0     * Ec + d) = u0;
        *reinterpret_cast<float2*>(cp + (size_t)(pr0+8) * Ec + d) = u1;
    }
}

// ---------------- launch ----------------
extern "C" void kernel_launch(void* const* d_in, const int* in_sizes, int n_in,
                              void* d_out, int out_size)
{
    const float* x   = (const float*)d_in[0];
    const float* wq  = (const float*)d_in[1];
    const float* bq  = (const float*)d_in[2];
    const float* wk  = (const float*)d_in[3];
    const float* bk  = (const float*)d_in[4];
    const float* wv  = (const float*)d_in[5];
    const float* bv  = (const float*)d_in[6];
    const float* wo  = (const float*)d_in[7];
    const float* bo  = (const float*)d_in[8];
    const float* w1  = (const float*)d_in[9];
    const float* b1  = (const float*)d_in[10];
    const float* w2  = (const float*)d_in[11];
    const float* b2  = (const float*)d_in[12];
    const float* g1  = (const float*)d_in[13];
    const float* be1 = (const float*)d_in[14];
    const float* g2  = (const float*)d_in[15];
    const float* be2 = (const float*)d_in[16];
    float* out = (float*)d_out;

    float *z0, *q, *k, *v, *ctx, *x1, *z1, *h;
    float *wqkvT, *woT, *w1T, *w2T;
    cudaGetSymbolAddress((void**)&z0,   g_z0);
    cudaGetSymbolAddress((void**)&q,    g_q);
    cudaGetSymbolAddress((void**)&k,    g_k);
    cudaGetSymbolAddress((void**)&v,    g_v);
    cudaGetSymbolAddress((void**)&ctx,  g_ctx);
    cudaGetSymbolAddress((void**)&x1,   g_x1);
    cudaGetSymbolAddress((void**)&z1,   g_z1);
    cudaGetSymbolAddress((void**)&h,    g_h);
    cudaGetSymbolAddress((void**)&wqkvT, g_wqkvT);
    cudaGetSymbolAddress((void**)&woT,  g_woT);
    cudaGetSymbolAddress((void**)&w1T,  g_w1T);
    cudaGetSymbolAddress((void**)&w2T,  g_w2T);

    cudaFuncSetAttribute(attn_kernel,  cudaFuncAttributeMaxDynamicSharedMemorySize, ATTN_SMEM);
    cudaFuncSetAttribute(tc_gemm<0>,   cudaFuncAttributeMaxDynamicSharedMemorySize, SMEM_GEMM);
    cudaFuncSetAttribute(tc_gemm<1>,   cudaFuncAttributeMaxDynamicSharedMemorySize, SMEM_GEMM);
    cudaFuncSetAttribute(tc_gemm<2>,   cudaFuncAttributeMaxDynamicSharedMemorySize, SMEM_GEMM);
    cudaFuncSetAttribute(tc_gemm_qkv,  cudaFuncAttributeMaxDynamicSharedMemorySize, SMEM_GEMM);

    // 1
    ln_kernel<<<TOK, 256>>>(x, g1, be1, z0);
    // 2
    transpose4_kernel<<<dim3(32, 32, 4), 256>>>(
        wq, wk, wv, wo,
        wqkvT, wqkvT + (size_t)Ec*Ec, wqkvT + (size_t)2*Ec*Ec, woT);
    // 3
    transpose_kernel<<<dim3(MLPc/32, Ec/32), 256>>>(w1, w1T, Ec, MLPc);
    // 4
    tc_gemm_qkv<<<dim3(24, TOK/128), 256, SMEM_GEMM>>>(z0, wqkvT, bq, bk, bv, q, k, v, Ec);
    // 5
    attn_kernel<<<dim3(Sc/128, Bc*Hc), 256, ATTN_SMEM>>>(q, k, v, ctx);
    // 6  <- profiled by ncu (-s 5 -c 1)
    tc_gemm<1><<<dim3(Ec/128, TOK/128), 256, SMEM_GEMM>>>(ctx, woT, bo, x, x1, TOK, Ec, Ec);
    // 7
    ln_kernel<<<TOK, 256>>>(x1, g2, be2, z1);
    // 8
    transpose_kernel<<<dim3(Ec/32, MLPc/32), 256>>>(w2, w2T, MLPc, Ec);
    // 9
    tc_gemm<2><<<dim3(MLPc/128, TOK/128), 256, SMEM_GEMM>>>(z1, w1T, b1, nullptr, h, TOK, MLPc, Ec);
    // 10
    tc_gemm<1><<<dim3(Ec/128, TOK/128), 256, SMEM_GEMM>>>(h, w2T, b2, x1, out, TOK, Ec, MLPc);
}

// round 8
// speedup vs baseline: 1.0804x; 1.0804x over previous
#include <cuda_runtime.h>
#include <cstdint>
#include <math.h>

#define Bc   2
#define Sc   2048
#define TOK  4096
#define Ec   1024
#define Hc   16
#define HDc  64
#define MLPc 4096

// ---------------- scratch (no allocations allowed) ----------------
__device__ float g_z0[(size_t)TOK * Ec];
__device__ float g_q [(size_t)TOK * Ec];
__device__ float g_k [(size_t)TOK * Ec];
__device__ float g_v [(size_t)TOK * Ec];
__device__ float g_ctx[(size_t)TOK * Ec];
__device__ float g_x1[(size_t)TOK * Ec];
__device__ float g_z1[(size_t)TOK * Ec];
__device__ float g_h [(size_t)TOK * MLPc];
__device__ float g_wqkvT[(size_t)3 * Ec * Ec];
__device__ float g_woT[(size_t)Ec * Ec];
__device__ float g_w1T[(size_t)Ec * MLPc];
__device__ float g_w2T[(size_t)MLPc * Ec];

// ---------------- helpers ----------------
__device__ __forceinline__ unsigned f2tf(float f) {
    unsigned r;
    asm("cvt.rna.tf32.f32 %0, %1;" : "=r"(r) : "f"(f));
    return r;
}
__device__ __forceinline__ float tfround(float f) {
    return __uint_as_float(f2tf(f));
}
__device__ __forceinline__ uint32_t smem_u32(const void* p) {
    uint32_t a;
    asm("{ .reg .u64 t; cvta.to.shared.u64 t, %1; cvt.u32.u64 %0, t; }" : "=r"(a) : "l"(p));
    return a;
}
__device__ __forceinline__ void cp16(uint32_t d, const void* s) {
    asm volatile("cp.async.cg.shared.global [%0], [%1], 16;\n" :: "r"(d), "l"(s));
}
__device__ __forceinline__ void cp_commit() {
    asm volatile("cp.async.commit_group;\n" ::: "memory");
}
#define CP_WAIT(n) asm volatile("cp.async.wait_group %0;\n" :: "n"(n) : "memory")

__device__ __forceinline__ void mma8(float c[4], const unsigned a[4], const unsigned b[2]) {
    asm volatile(
        "mma.sync.aligned.m16n8k8.row.col.f32.tf32.tf32.f32 "
        "{%0,%1,%2,%3}, {%4,%5,%6,%7}, {%8,%9}, {%0,%1,%2,%3};\n"
        : "+f"(c[0]), "+f"(c[1]), "+f"(c[2]), "+f"(c[3])
        : "r"(a[0]), "r"(a[1]), "r"(a[2]), "r"(a[3]),
          "r"(b[0]), "r"(b[1]));
}
// tf32-as-b16-pairs fragment loads (CUTLASS-style): one x4 = full A-frag, x2 = B-frag
__device__ __forceinline__ void ldmA(unsigned a[4], uint32_t addr) {
    asm volatile("ldmatrix.sync.aligned.m8n8.x4.shared.b16 {%0,%1,%2,%3}, [%4];"
                 : "=r"(a[0]), "=r"(a[1]), "=r"(a[2]), "=r"(a[3]) : "r"(addr));
}
__device__ __forceinline__ void ldmB(unsigned b[2], uint32_t addr) {
    asm volatile("ldmatrix.sync.aligned.m8n8.x2.shared.b16 {%0,%1}, [%2];"
                 : "=r"(b[0]), "=r"(b[1]) : "r"(addr));
}

// ---------------- weight transposes (+ tf32 rounding) ----------------
__global__ void __launch_bounds__(256) transpose4_kernel(
    const float* __restrict__ i0, const float* __restrict__ i1,
    const float* __restrict__ i2, const float* __restrict__ i3,
    float* __restrict__ o0, float* __restrict__ o1,
    float* __restrict__ o2, float* __restrict__ o3)
{
    const float* in  = (blockIdx.z == 0) ? i0 : (blockIdx.z == 1) ? i1 : (blockIdx.z == 2) ? i2 : i3;
    float*       out = (blockIdx.z == 0) ? o0 : (blockIdx.z == 1) ? o1 : (blockIdx.z == 2) ? o2 : o3;
    __shared__ float tile[32][33];
    const int bx = blockIdx.x * 32, by = blockIdx.y * 32;
    const int tx = threadIdx.x & 31, ty = threadIdx.x >> 5;
    #pragma unroll
    for (int i = 0; i < 32; i += 8)
        tile[ty + i][tx] = tfround(in[(size_t)(by + ty + i) * Ec + bx + tx]);
    __syncthreads();
    #pragma unroll
    for (int i = 0; i < 32; i += 8)
        out[(size_t)(bx + ty + i) * Ec + by + tx] = tile[tx][ty + i];
}

__global__ void __launch_bounds__(256) transpose_kernel(
    const float* __restrict__ in, float* __restrict__ out, int R, int C)
{
    __shared__ float tile[32][33];
    const int bx = blockIdx.x * 32, by = blockIdx.y * 32;
    const int tx = threadIdx.x & 31, ty = threadIdx.x >> 5;
    #pragma unroll
    for (int i = 0; i < 32; i += 8)
        tile[ty + i][tx] = tfround(in[(size_t)(by + ty + i) * C + bx + tx]);
    __syncthreads();
    #pragma unroll
    for (int i = 0; i < 32; i += 8)
        out[(size_t)(bx + ty + i) * R + by + tx] = tile[tx][ty + i];
}

// ---------------- LayerNorm (fp32 exact, tf32-rounded output) ----------------
__global__ void __launch_bounds__(256) ln_kernel(
    const float* __restrict__ x, const float* __restrict__ gam,
    const float* __restrict__ bet, float* __restrict__ y)
{
    const int row = blockIdx.x, t = threadIdx.x;
    const float4* xr = reinterpret_cast<const float4*>(x + (size_t)row * Ec);
    float4 v = xr[t];
    float s  = v.x + v.y + v.z + v.w;
    float ss = v.x*v.x + v.y*v.y + v.z*v.z + v.w*v.w;
    #pragma unroll
    for (int o = 16; o; o >>= 1) {
        s  += __shfl_xor_sync(0xffffffffu, s,  o);
        ss += __shfl_xor_sync(0xffffffffu, ss, o);
    }
    __shared__ float rs[8], rss[8];
    if ((t & 31) == 0) { rs[t >> 5] = s; rss[t >> 5] = ss; }
    __syncthreads();
    if (t < 32) {
        float a = (t < 8) ? rs[t]  : 0.f;
        float b = (t < 8) ? rss[t] : 0.f;
        #pragma unroll
        for (int o = 4; o; o >>= 1) {
            a += __shfl_xor_sync(0xffffffffu, a, o);
            b += __shfl_xor_sync(0xffffffffu, b, o);
        }
        if (t == 0) { rs[0] = a; rss[0] = b; }
    }
    __syncthreads();
    const float mu   = rs[0]  * (1.f / Ec);
    const float var  = rss[0] * (1.f / Ec) - mu * mu;
    const float rstd = rsqrtf(var + 1e-5f);
    float4 gv = reinterpret_cast<const float4*>(gam)[t];
    float4 bv = reinterpret_cast<const float4*>(bet)[t];
    float4 o;
    o.x = tfround((v.x - mu) * rstd * gv.x + bv.x);
    o.y = tfround((v.y - mu) * rstd * gv.y + bv.y);
    o.z = tfround((v.z - mu) * rstd * gv.z + bv.z);
    o.w = tfround((v.w - mu) * rstd * gv.w + bv.w);
    reinterpret_cast<float4*>(y + (size_t)row * Ec)[t] = o;
}

// ---------------- TF32 GEMM (3-stage, k-tile 32, 128 thr, warp 64x64, ldmatrix) -
#define KT   32
#define SW   36                    // words per 32-float row (+4 pad)
#define STG  (128 * SW)            // words per operand stage (4608)
#define NSTG 3
#define SMEM_GEMM (2 * NSTG * STG * 4)   // 110592 bytes

__device__ __forceinline__ void ldstage(uint32_t ab, uint32_t bb,
    const float* __restrict__ Ap, const float* __restrict__ Bp, int K, int kt)
{
    const int t = threadIdx.x;
    const int k0 = kt * KT;
    #pragma unroll
    for (int i = 0; i < 8; i++) {
        const int idx = t + i * 128;
        const int r = idx >> 3, cu = (idx & 7) * 4;
        cp16(ab + (r * SW + cu) * 4, Ap + (size_t)r * K + k0 + cu);
    }
    #pragma unroll
    for (int i = 0; i < 8; i++) {
        const int idx = t + i * 128;
        const int r = idx >> 3, cu = (idx & 7) * 4;
        cp16(bb + (r * SW + cu) * 4, Bp + (size_t)r * K + k0 + cu);
    }
}

__device__ __forceinline__ void gemm_mainloop(
    const float* __restrict__ Ap, const float* __restrict__ Bp, int K,
    float* smem, float acc[4][8][4])
{
    const int t    = threadIdx.x;
    const int lane = t & 31, warp = t >> 5;
    const int wm = warp >> 1, wn = warp & 1;     // 2 x 2 warp grid, warp tile 64x64
    const int NK = K / KT;

    const uint32_t asb = smem_u32(smem);
    const uint32_t bsb = asb + NSTG * STG * 4;

    // per-lane ldmatrix address components
    const int arow = lane & 15;                  // rows 0..15 within 16-row block
    const int akof = (lane & 16) ? 4 : 0;        // k halves 0 / 4
    const int brow = lane & 7;
    const int bkof = ((lane >> 3) & 1) * 4;

    ldstage(asb, bsb, Ap, Bp, K, 0);
    cp_commit();
    ldstage(asb + STG*4, bsb + STG*4, Ap, Bp, K, 1);
    cp_commit();

    int st = 0;
    for (int kt = 0; kt < NK; kt++) {
        CP_WAIT(1);
        __syncthreads();
        const uint32_t as = asb + st * STG * 4;
        const uint32_t bs = bsb + st * STG * 4;
        // prefetch stage kt+2
        if (kt + 2 < NK) {
            int ps = st + 2; if (ps >= NSTG) ps -= NSTG;
            ldstage(asb + ps * STG * 4, bsb + ps * STG * 4, Ap, Bp, K, kt + 2);
        }
        cp_commit();

        const uint32_t aB = as + ((wm*64 + arow) * SW + akof) * 4;
        const uint32_t bB = bs + ((wn*64 + brow) * SW + bkof) * 4;
        #pragma unroll
        for (int kb = 0; kb < KT; kb += 8) {
            unsigned af[4][4], bf[8][2];
            #pragma unroll
            for (int mi = 0; mi < 4; mi++)
                ldmA(af[mi], aB + (mi*16*SW + kb) * 4);
            #pragma unroll
            for (int ni = 0; ni < 8; ni++)
                ldmB(bf[ni], bB + (ni*8*SW + kb) * 4);
            #pragma unroll
            for (int mi = 0; mi < 4; mi++)
                #pragma unroll
                for (int ni = 0; ni < 8; ni++)
                    mma8(acc[mi][ni], af[mi], bf[ni]);
        }
        st++; if (st == NSTG) st = 0;
    }
}

// EPI: 0 = bias(->tf32), 1 = bias+res (fp32), 2 = bias+gelu(->tf32)
template <int EPI>
__global__ void __launch_bounds__(128, 2) tc_gemm(
    const float* __restrict__ A, const float* __restrict__ BT,
    const float* __restrict__ bias, const float* __restrict__ res,
    float* __restrict__ C, int M, int N, int K)
{
    extern __shared__ float smem[];
    const int t = threadIdx.x;
    const int lane = t & 31, warp = t >> 5;
    const int wm = warp >> 1, wn = warp & 1;
    const int g  = lane >> 2, t4 = lane & 3;
    const int bm = blockIdx.y * 128, bn = blockIdx.x * 128;

    float acc[4][8][4];
    #pragma unroll
    for (int mi = 0; mi < 4; mi++)
        #pragma unroll
        for (int ni = 0; ni < 8; ni++)
            #pragma unroll
            for (int c = 0; c < 4; c++) acc[mi][ni][c] = 0.f;

    gemm_mainloop(A + (size_t)bm * K, BT + (size_t)bn * K, K, smem, acc);

    #pragma unroll
    for (int mi = 0; mi < 4; mi++) {
        #pragma unroll
        for (int half = 0; half < 2; half++) {
            const int row = bm + wm*64 + mi*16 + g + half*8;
            #pragma unroll
            for (int ni = 0; ni < 8; ni++) {
                const int col = bn + wn*64 + ni*8 + t4*2;
                float vx = acc[mi][ni][half*2 + 0] + __ldg(bias + col);
                float vy = acc[mi][ni][half*2 + 1] + __ldg(bias + col + 1);
                if (EPI == 1) {
                    vx += __ldg(res + (size_t)row * N + col);
                    vy += __ldg(res + (size_t)row * N + col + 1);
                } else if (EPI == 2) {
                    vx = 0.5f * vx * (1.f + erff(vx * 0.70710678118654752f));
                    vy = 0.5f * vy * (1.f + erff(vy * 0.70710678118654752f));
                    vx = tfround(vx); vy = tfround(vy);
                } else {
                    vx = tfround(vx); vy = tfround(vy);
                }
                float2 o; o.x = vx; o.y = vy;
                *reinterpret_cast<float2*>(C + (size_t)row * N + col) = o;
            }
        }
    }
}

// fused QKV: BT = wqkvT [3072][1024]; grid.x = 24 (3 outputs x 8 col-blocks)
__global__ void __launch_bounds__(128, 2) tc_gemm_qkv(
    const float* __restrict__ A, const float* __restrict__ BT,
    const float* __restrict__ bq, const float* __restrict__ bk,
    const float* __restrict__ bv,
    float* __restrict__ q, float* __restrict__ k, float* __restrict__ v, int K)
{
    extern __shared__ float smem[];
    const int t = threadIdx.x;
    const int lane = t & 31, warp = t >> 5;
    const int wm = warp >> 1, wn = warp & 1;
    const int g  = lane >> 2, t4 = lane & 3;
    const int which = blockIdx.x >> 3;
    const int bn = (blockIdx.x & 7) * 128;
    const int bm = blockIdx.y * 128;
    const float* bias = (which == 0) ? bq : (which == 1) ? bk : bv;
    float* C = (which == 0) ? q : (which == 1) ? k : v;

    float acc[4][8][4];
    #pragma unroll
    for (int mi = 0; mi < 4; mi++)
        #pragma unroll
        for (int ni = 0; ni < 8; ni++)
            #pragma unroll
            for (int c = 0; c < 4; c++) acc[mi][ni][c] = 0.f;

    gemm_mainloop(A + (size_t)bm * K, BT + (size_t)(which * Ec + bn) * K, K, smem, acc);

    #pragma unroll
    for (int mi = 0; mi < 4; mi++) {
        #pragma unroll
        for (int half = 0; half < 2; half++) {
            const int row = bm + wm*64 + mi*16 + g + half*8;
            #pragma unroll
            for (int ni = 0; ni < 8; ni++) {
                const int col = bn + wn*64 + ni*8 + t4*2;
                float vx = tfround(acc[mi][ni][half*2 + 0] + __ldg(bias + col));
                float vy = tfround(acc[mi][ni][half*2 + 1] + __ldg(bias + col + 1));
                float2 o; o.x = vx; o.y = vy;
                *reinterpret_cast<float2*>(C + (size_t)row * Ec + col) = o;
            }
        }
    }
}

// ---------------- fused flash attention (cp.async + ldmatrix, tf32 mma) ---------
#define QS_LD 68
#define KS_LD 68
#define VS_LD 72
#define PS_LD 132
#define ATTN_SMEM ((128*QS_LD + 2*128*KS_LD + 128*VS_LD + 128*PS_LD) * 4)  // 208896

__global__ void __launch_bounds__(256) attn_kernel(
    const float* __restrict__ q, const float* __restrict__ kg,
    const float* __restrict__ vg, float* __restrict__ ctx)
{
    extern __shared__ unsigned sm[];
    unsigned* Qs = sm;
    unsigned* Ks = Qs + 128 * QS_LD;     // 2 buffers
    unsigned* Vs = Ks + 2 * 128 * KS_LD;
    unsigned* Ps = Vs + 128 * VS_LD;

    const int t = threadIdx.x, lane = t & 31, warp = t >> 5;
    const int g = lane >> 2, t4 = lane & 3;
    const int b = blockIdx.y >> 4, h = blockIdx.y & 15;
    const size_t base = (size_t)b * Sc * Ec + (size_t)h * HDc;
    const float* qp = q  + base + (size_t)blockIdx.x * 128 * Ec;
    const float* kp = kg + base;
    const float* vp = vg + base;

    const uint32_t qb = smem_u32(Qs);
    const uint32_t kb = smem_u32(Ks);
    const uint32_t vb = smem_u32(Vs);
    const uint32_t pb = smem_u32(Ps);

    const int arow = lane & 15;
    const int akof = (lane & 16) ? 4 : 0;
    const int brow = lane & 7;
    const int bkof = ((lane >> 3) & 1) * 4;

    #pragma unroll
    for (int i = 0; i < 8; i++) {
        const int lin = t + i*256;
        const int r = lin >> 4, c = (lin & 15) * 4;
        cp16(qb + (r*QS_LD + c)*4, qp + (size_t)r * Ec + c);
        cp16(kb + (r*KS_LD + c)*4, kp + (size_t)r * Ec + c);
    }
    cp_commit();

    float o[8][4];
    #pragma unroll
    for (int ni = 0; ni < 8; ni++)
        #pragma unroll
        for (int c = 0; c < 4; c++) o[ni][c] = 0.f;
    float m0 = -INFINITY, m1 = -INFINITY, l0 = 0.f, l1 = 0.f;
    const int pr0 = warp*16 + g;
    const uint32_t qA = qb + ((warp*16 + arow)*QS_LD + akof)*4;   // Q A-frag base
    const uint32_t pA = pb + ((warp*16 + arow)*PS_LD + akof)*4;   // P A-frag base

    for (int kt = 0; kt < 16; kt++) {
        __syncthreads();
        #pragma unroll
        for (int i = 0; i < 8; i++) {
            const int lin = t + i*256;
            const int r = lin >> 4, c = (lin & 15) * 4;
            cp16(vb + (r*VS_LD + c)*4, vp + (size_t)(kt*128 + r) * Ec + c);
        }
        cp_commit();
        if (kt < 15) {
            const uint32_t kbn = kb + ((kt+1)&1) * (128*KS_LD*4);
            #pragma unroll
            for (int i = 0; i < 8; i++) {
                const int lin = t + i*256;
                const int r = lin >> 4, c = (lin & 15) * 4;
                cp16(kbn + (r*KS_LD + c)*4, kp + (size_t)((kt+1)*128 + r) * Ec + c);
            }
        }
        cp_commit();
        CP_WAIT(2);
        __syncthreads();

        const uint32_t kB = kb + (kt & 1) * (128*KS_LD*4) + (brow*KS_LD + bkof)*4;

        float sacc[16][4];
        #pragma unroll
        for (int ni = 0; ni < 16; ni++)
            #pragma unroll
            for (int c = 0; c < 4; c++) sacc[ni][c] = 0.f;
        #pragma unroll
        for (int kk = 0; kk < 8; kk++) {
            const int kbo = kk * 8;
            unsigned a[4];
            ldmA(a, qA + kbo*4);
            #pragma unroll
            for (int ni = 0; ni < 16; ni++) {
                unsigned bbf[2];
                ldmB(bbf, kB + (ni*8*KS_LD + kbo)*4);
                mma8(sacc[ni], a, bbf);
            }
        }

        float rm0 = -INFINITY, rm1 = -INFINITY;
        #pragma unroll
        for (int ni = 0; ni < 16; ni++) {
            sacc[ni][0] *= 0.125f; sacc[ni][1] *= 0.125f;
            sacc[ni][2] *= 0.125f; sacc[ni][3] *= 0.125f;
            rm0 = fmaxf(rm0, fmaxf(sacc[ni][0], sacc[ni][1]));
            rm1 = fmaxf(rm1, fmaxf(sacc[ni][2], sacc[ni][3]));
        }
        rm0 = fmaxf(rm0, __shfl_xor_sync(0xffffffffu, rm0, 1));
        rm0 = fmaxf(rm0, __shfl_xor_sync(0xffffffffu, rm0, 2));
        rm1 = fmaxf(rm1, __shfl_xor_sync(0xffffffffu, rm1, 1));
        rm1 = fmaxf(rm1, __shfl_xor_sync(0xffffffffu, rm1, 2));
        const float mn0 = fmaxf(m0, rm0), mn1 = fmaxf(m1, rm1);
        const float al0 = __expf(m0 - mn0), al1 = __expf(m1 - mn1);
        float ps0 = 0.f, ps1 = 0.f;
        #pragma unroll
        for (int ni = 0; ni < 16; ni++) {
            float p0 = __expf(sacc[ni][0] - mn0);
            float p1 = __expf(sacc[ni][1] - mn0);
            float p2 = __expf(sacc[ni][2] - mn1);
            float p3 = __expf(sacc[ni][3] - mn1);
            ps0 += p0 + p1; ps1 += p2 + p3;
            const int col = ni*8 + t4*2;
            Ps[pr0     * PS_LD + col    ] = __float_as_uint(p0);
            Ps[pr0     * PS_LD + col + 1] = __float_as_uint(p1);
            Ps[(pr0+8) * PS_LD + col    ] = __float_as_uint(p2);
            Ps[(pr0+8) * PS_LD + col + 1] = __float_as_uint(p3);
        }
        ps0 += __shfl_xor_sync(0xffffffffu, ps0, 1);
        ps0 += __shfl_xor_sync(0xffffffffu, ps0, 2);
        ps1 += __shfl_xor_sync(0xffffffffu, ps1, 1);
        ps1 += __shfl_xor_sync(0xffffffffu, ps1, 2);
        l0 = l0 * al0 + ps0; l1 = l1 * al1 + ps1;
        m0 = mn0; m1 = mn1;
        #pragma unroll
        for (int ni = 0; ni < 8; ni++) {
            o[ni][0] *= al0; o[ni][1] *= al0;
            o[ni][2] *= al1; o[ni][3] *= al1;
        }
        __syncwarp();

        CP_WAIT(1);
        __syncthreads();

        #pragma unroll
        for (int kk = 0; kk < 16; kk++) {
            const int kbo = kk * 8;
            unsigned a[4];
            ldmA(a, pA + kbo*4);
            #pragma unroll
            for (int ni = 0; ni < 8; ni++) {
                unsigned bbf[2];
                const int d = ni*8 + g;
                bbf[0] = Vs[(kbo + t4    ) * VS_LD + d];
                bbf[1] = Vs[(kbo + t4 + 4) * VS_LD + d];
                mma8(o[ni], a, bbf);
            }
        }
    }

    const float inv0 = 1.f / l0, inv1 = 1.f / l1;
    float* cp = ctx + base + (size_t)blockIdx.x * 128 * Ec;
    #pragma unroll
    for (int ni = 0; ni < 8; ni++) {
        const int d = ni*8 + t4*2;
        float2 u0; u0.x = tfround(o[ni][0] * inv0); u0.y = tfround(o[ni][1] * inv0);
        float2 u1; u1.x = tfround(o[ni][2] * inv1); u1.y = tfround(o[ni][3] * inv1);
        *reinterpret_cast<float2*>(cp + (size_t)pr0     * Ec + d) = u0;
        *reinterpret_cast<float2*>(cp + (size_t)(pr0+8) * Ec + d) = u1;
    }
}

// ---------------- launch ----------------
extern "C" void kernel_launch(void* const* d_in, const int* in_sizes, int n_in,
                              void* d_out, int out_size)
{
    const float* x   = (const float*)d_in[0];
    const float* wq  = (const float*)d_in[1];
    const float* bq  = (const float*)d_in[2];
    const float* wk  = (const float*)d_in[3];
    const float* bk  = (const float*)d_in[4];
    const float* wv  = (const float*)d_in[5];
    const float* bv  = (const float*)d_in[6];
    const float* wo  = (const float*)d_in[7];
    const float* bo  = (const float*)d_in[8];
    const float* w1  = (const float*)d_in[9];
    const float* b1  = (const float*)d_in[10];
    const float* w2  = (const float*)d_in[11];
    const float* b2  = (const float*)d_in[12];
    const float* g1  = (const float*)d_in[13];
    const float* be1 = (const float*)d_in[14];
    const float* g2  = (const float*)d_in[15];
    const float* be2 = (const float*)d_in[16];
    float* out = (float*)d_out;

    float *z0, *q, *k, *v, *ctx, *x1, *z1, *h;
    float *wqkvT, *woT, *w1T, *w2T;
    cudaGetSymbolAddress((void**)&z0,   g_z0);
    cudaGetSymbolAddress((void**)&q,    g_q);
    cudaGetSymbolAddress((void**)&k,    g_k);
    cudaGetSymbolAddress((void**)&v,    g_v);
    cudaGetSymbolAddress((void**)&ctx,  g_ctx);
    cudaGetSymbolAddress((void**)&x1,   g_x1);
    cudaGetSymbolAddress((void**)&z1,   g_z1);
    cudaGetSymbolAddress((void**)&h,    g_h);
    cudaGetSymbolAddress((void**)&wqkvT, g_wqkvT);
    cudaGetSymbolAddress((void**)&woT,  g_woT);
    cudaGetSymbolAddress((void**)&w1T,  g_w1T);
    cudaGetSymbolAddress((void**)&w2T,  g_w2T);

    cudaFuncSetAttribute(attn_kernel,  cudaFuncAttributeMaxDynamicSharedMemorySize, ATTN_SMEM);
    cudaFuncSetAttribute(tc_gemm<0>,   cudaFuncAttributeMaxDynamicSharedMemorySize, SMEM_GEMM);
    cudaFuncSetAttribute(tc_gemm<1>,   cudaFuncAttributeMaxDynamicSharedMemorySize, SMEM_GEMM);
    cudaFuncSetAttribute(tc_gemm<2>,   cudaFuncAttributeMaxDynamicSharedMemorySize, SMEM_GEMM);
    cudaFuncSetAttribute(tc_gemm_qkv,  cudaFuncAttributeMaxDynamicSharedMemorySize, SMEM_GEMM);

    // 1
    ln_kernel<<<TOK, 256>>>(x, g1, be1, z0);
    // 2
    transpose4_kernel<<<dim3(32, 32, 4), 256>>>(
        wq, wk, wv, wo,
        wqkvT, wqkvT + (size_t)Ec*Ec, wqkvT + (size_t)2*Ec*Ec, woT);
    // 3
    transpose_kernel<<<dim3(MLPc/32, Ec/32), 256>>>(w1, w1T, Ec, MLPc);
    // 4
    tc_gemm_qkv<<<dim3(24, TOK/128), 128, SMEM_GEMM>>>(z0, wqkvT, bq, bk, bv, q, k, v, Ec);
    // 5
    attn_kernel<<<dim3(Sc/128, Bc*Hc), 256, ATTN_SMEM>>>(q, k, v, ctx);
    // 6  <- profiled by ncu (-s 5 -c 1)
    tc_gemm<1><<<dim3(Ec/128, TOK/128), 128, SMEM_GEMM>>>(ctx, woT, bo, x, x1, TOK, Ec, Ec);
    // 7
    ln_kernel<<<TOK, 256>>>(x1, g2, be2, z1);
    // 8
    transpose_kernel<<<dim3(Ec/32, MLPc/32), 256>>>(w2, w2T, MLPc, Ec);
    // 9
    tc_gemm<2><<<dim3(MLPc/128, TOK/128), 128, SMEM_GEMM>>>(z1, w1T, b1, nullptr, h, TOK, MLPc, Ec);
    // 10
    tc_gemm<1><<<dim3(Ec/128, TOK/128), 128, SMEM_GEMM>>>(h, w2T, b2, x1, out, TOK, Ec, MLPc);
}

// round 10
// speedup vs baseline: 1.1289x; 1.0449x over previous
#include <cuda_runtime.h>
#include <cstdint>
#include <math.h>

#define Bc   2
#define Sc   2048
#define TOK  4096
#define Ec   1024
#define Hc   16
#define HDc  64
#define MLPc 4096

// ---------------- scratch (no allocations allowed) ----------------
__device__ float g_z0[(size_t)TOK * Ec];
__device__ float g_q [(size_t)TOK * Ec];
__device__ float g_k [(size_t)TOK * Ec];
__device__ float g_v [(size_t)TOK * Ec];
__device__ float g_ctx[(size_t)TOK * Ec];
__device__ float g_x1[(size_t)TOK * Ec];
__device__ float g_z1[(size_t)TOK * Ec];
__device__ float g_h [(size_t)TOK * MLPc];
__device__ float g_wqkvT[(size_t)3 * Ec * Ec];
__device__ float g_woT[(size_t)Ec * Ec];
__device__ float g_w1T[(size_t)Ec * MLPc];
__device__ float g_w2T[(size_t)MLPc * Ec];

// ---------------- helpers ----------------
__device__ __forceinline__ unsigned f2tf(float f) {
    unsigned r;
    asm("cvt.rna.tf32.f32 %0, %1;" : "=r"(r) : "f"(f));
    return r;
}
__device__ __forceinline__ float tfround(float f) {
    return __uint_as_float(f2tf(f));
}
__device__ __forceinline__ uint32_t smem_u32(const void* p) {
    uint32_t a;
    asm("{ .reg .u64 t; cvta.to.shared.u64 t, %1; cvt.u32.u64 %0, t; }" : "=r"(a) : "l"(p));
    return a;
}
__device__ __forceinline__ void cp16(uint32_t d, const void* s) {
    asm volatile("cp.async.cg.shared.global [%0], [%1], 16;\n" :: "r"(d), "l"(s));
}
__device__ __forceinline__ void cp_commit() {
    asm volatile("cp.async.commit_group;\n" ::: "memory");
}
#define CP_WAIT(n) asm volatile("cp.async.wait_group %0;\n" :: "n"(n) : "memory")

__device__ __forceinline__ void mma8(float c[4], const unsigned a[4], const unsigned b[2]) {
    asm volatile(
        "mma.sync.aligned.m16n8k8.row.col.f32.tf32.tf32.f32 "
        "{%0,%1,%2,%3}, {%4,%5,%6,%7}, {%8,%9}, {%0,%1,%2,%3};\n"
        : "+f"(c[0]), "+f"(c[1]), "+f"(c[2]), "+f"(c[3])
        : "r"(a[0]), "r"(a[1]), "r"(a[2]), "r"(a[3]),
          "r"(b[0]), "r"(b[1]));
}
// tf32-as-b16-pairs fragment loads (CUTLASS-style): one x4 = full A-frag, x2 = B-frag
__device__ __forceinline__ void ldmA(unsigned a[4], uint32_t addr) {
    asm volatile("ldmatrix.sync.aligned.m8n8.x4.shared.b16 {%0,%1,%2,%3}, [%4];"
                 : "=r"(a[0]), "=r"(a[1]), "=r"(a[2]), "=r"(a[3]) : "r"(addr));
}
__device__ __forceinline__ void ldmB(unsigned b[2], uint32_t addr) {
    asm volatile("ldmatrix.sync.aligned.m8n8.x2.shared.b16 {%0,%1}, [%2];"
                 : "=r"(b[0]), "=r"(b[1]) : "r"(addr));
}

// ---------------- weight transposes (+ tf32 rounding) ----------------
__global__ void __launch_bounds__(256) transpose4_kernel(
    const float* __restrict__ i0, const float* __restrict__ i1,
    const float* __restrict__ i2, const float* __restrict__ i3,
    float* __restrict__ o0, float* __restrict__ o1,
    float* __restrict__ o2, float* __restrict__ o3)
{
    const float* in  = (blockIdx.z == 0) ? i0 : (blockIdx.z == 1) ? i1 : (blockIdx.z == 2) ? i2 : i3;
    float*       out = (blockIdx.z == 0) ? o0 : (blockIdx.z == 1) ? o1 : (blockIdx.z == 2) ? o2 : o3;
    __shared__ float tile[32][33];
    const int bx = blockIdx.x * 32, by = blockIdx.y * 32;
    const int tx = threadIdx.x & 31, ty = threadIdx.x >> 5;
    #pragma unroll
    for (int i = 0; i < 32; i += 8)
        tile[ty + i][tx] = tfround(in[(size_t)(by + ty + i) * Ec + bx + tx]);
    __syncthreads();
    #pragma unroll
    for (int i = 0; i < 32; i += 8)
        out[(size_t)(bx + ty + i) * Ec + by + tx] = tile[tx][ty + i];
}

__global__ void __launch_bounds__(256) transpose_kernel(
    const float* __restrict__ in, float* __restrict__ out, int R, int C)
{
    __shared__ float tile[32][33];
    const int bx = blockIdx.x * 32, by = blockIdx.y * 32;
    const int tx = threadIdx.x & 31, ty = threadIdx.x >> 5;
    #pragma unroll
    for (int i = 0; i < 32; i += 8)
        tile[ty + i][tx] = tfround(in[(size_t)(by + ty + i) * C + bx + tx]);
    __syncthreads();
    #pragma unroll
    for (int i = 0; i < 32; i += 8)
        out[(size_t)(bx + ty + i) * R + by + tx] = tile[tx][ty + i];
}

// ---------------- LayerNorm (fp32 exact, tf32-rounded output) ----------------
__global__ void __launch_bounds__(256) ln_kernel(
    const float* __restrict__ x, const float* __restrict__ gam,
    const float* __restrict__ bet, float* __restrict__ y)
{
    const int row = blockIdx.x, t = threadIdx.x;
    const float4* xr = reinterpret_cast<const float4*>(x + (size_t)row * Ec);
    float4 v = xr[t];
    float s  = v.x + v.y + v.z + v.w;
    float ss = v.x*v.x + v.y*v.y + v.z*v.z + v.w*v.w;
    #pragma unroll
    for (int o = 16; o; o >>= 1) {
        s  += __shfl_xor_sync(0xffffffffu, s,  o);
        ss += __shfl_xor_sync(0xffffffffu, ss, o);
    }
    __shared__ float rs[8], rss[8];
    if ((t & 31) == 0) { rs[t >> 5] = s; rss[t >> 5] = ss; }
    __syncthreads();
    if (t < 32) {
        float a = (t < 8) ? rs[t]  : 0.f;
        float b = (t < 8) ? rss[t] : 0.f;
        #pragma unroll
        for (int o = 4; o; o >>= 1) {
            a += __shfl_xor_sync(0xffffffffu, a, o);
            b += __shfl_xor_sync(0xffffffffu, b, o);
        }
        if (t == 0) { rs[0] = a; rss[0] = b; }
    }
    __syncthreads();
    const float mu   = rs[0]  * (1.f / Ec);
    const float var  = rss[0] * (1.f / Ec) - mu * mu;
    const float rstd = rsqrtf(var + 1e-5f);
    float4 gv = reinterpret_cast<const float4*>(gam)[t];
    float4 bv = reinterpret_cast<const float4*>(bet)[t];
    float4 o;
    o.x = tfround((v.x - mu) * rstd * gv.x + bv.x);
    o.y = tfround((v.y - mu) * rstd * gv.y + bv.y);
    o.z = tfround((v.z - mu) * rstd * gv.z + bv.z);
    o.w = tfround((v.w - mu) * rstd * gv.w + bv.w);
    reinterpret_cast<float4*>(y + (size_t)row * Ec)[t] = o;
}

// ---- TF32 GEMM (2-stage, k-tile 32, 128 thr, warp 64x64, ldmatrix, 3 CTA/SM) ---
#define KT   32
#define SW   36                    // words per 32-float row (+4 pad)
#define STG  (128 * SW)            // words per operand stage (4608)
#define NSTG 2
#define SMEM_GEMM (2 * NSTG * STG * 4)   // 73728 bytes -> 3 CTAs/SM

__device__ __forceinline__ void ldstage(uint32_t ab, uint32_t bb,
    const float* __restrict__ Ap, const float* __restrict__ Bp, int K, int kt)
{
    const int t = threadIdx.x;
    const int k0 = kt * KT;
    #pragma unroll
    for (int i = 0; i < 8; i++) {
        const int idx = t + i * 128;
        const int r = idx >> 3, cu = (idx & 7) * 4;
        cp16(ab + (r * SW + cu) * 4, Ap + (size_t)r * K + k0 + cu);
    }
    #pragma unroll
    for (int i = 0; i < 8; i++) {
        const int idx = t + i * 128;
        const int r = idx >> 3, cu = (idx & 7) * 4;
        cp16(bb + (r * SW + cu) * 4, Bp + (size_t)r * K + k0 + cu);
    }
}

__device__ __forceinline__ void gemm_mainloop(
    const float* __restrict__ Ap, const float* __restrict__ Bp, int K,
    float* smem, float acc[4][8][4])
{
    const int t    = threadIdx.x;
    const int lane = t & 31, warp = t >> 5;
    const int wm = warp >> 1, wn = warp & 1;     // 2 x 2 warp grid, warp tile 64x64
    const int NK = K / KT;

    const uint32_t asb = smem_u32(smem);
    const uint32_t bsb = asb + NSTG * STG * 4;

    // per-lane ldmatrix address components
    const int arow = lane & 15;
    const int akof = (lane & 16) ? 4 : 0;
    const int brow = lane & 7;
    const int bkof = ((lane >> 3) & 1) * 4;

    // prologue: stage 0
    ldstage(asb, bsb, Ap, Bp, K, 0);
    cp_commit();

    int st = 0;
    for (int kt = 0; kt < NK; kt++) {
        CP_WAIT(0);
        __syncthreads();
        // prefetch next k-tile into the other buffer (overlaps this tile's compute)
        if (kt + 1 < NK) {
            const int ps = st ^ 1;
            ldstage(asb + ps * STG * 4, bsb + ps * STG * 4, Ap, Bp, K, kt + 1);
        }
        cp_commit();

        const uint32_t as = asb + st * STG * 4;
        const uint32_t bs = bsb + st * STG * 4;
        const uint32_t aB = as + ((wm*64 + arow) * SW + akof) * 4;
        const uint32_t bB = bs + ((wn*64 + brow) * SW + bkof) * 4;
        #pragma unroll
        for (int kb = 0; kb < KT; kb += 8) {
            unsigned af[4][4], bf[8][2];
            #pragma unroll
            for (int mi = 0; mi < 4; mi++)
                ldmA(af[mi], aB + (mi*16*SW + kb) * 4);
            #pragma unroll
            for (int ni = 0; ni < 8; ni++)
                ldmB(bf[ni], bB + (ni*8*SW + kb) * 4);
            #pragma unroll
            for (int mi = 0; mi < 4; mi++)
                #pragma unroll
                for (int ni = 0; ni < 8; ni++)
                    mma8(acc[mi][ni], af[mi], bf[ni]);
        }
        st ^= 1;
    }
}

// EPI: 0 = bias(->tf32), 1 = bias+res (fp32), 2 = bias+gelu(->tf32)
template <int EPI>
__global__ void __launch_bounds__(128, 3) tc_gemm(
    const float* __restrict__ A, const float* __restrict__ BT,
    const float* __restrict__ bias, const float* __restrict__ res,
    float* __restrict__ C, int M, int N, int K)
{
    extern __shared__ float smem[];
    const int t = threadIdx.x;
    const int lane = t & 31, warp = t >> 5;
    const int wm = warp >> 1, wn = warp & 1;
    const int g  = lane >> 2, t4 = lane & 3;
    const int bm = blockIdx.y * 128, bn = blockIdx.x * 128;

    float acc[4][8][4];
    #pragma unroll
    for (int mi = 0; mi < 4; mi++)
        #pragma unroll
        for (int ni = 0; ni < 8; ni++)
            #pragma unroll
            for (int c = 0; c < 4; c++) acc[mi][ni][c] = 0.f;

    gemm_mainloop(A + (size_t)bm * K, BT + (size_t)bn * K, K, smem, acc);

    #pragma unroll
    for (int mi = 0; mi < 4; mi++) {
        #pragma unroll
        for (int half = 0; half < 2; half++) {
            const int row = bm + wm*64 + mi*16 + g + half*8;
            #pragma unroll
            for (int ni = 0; ni < 8; ni++) {
                const int col = bn + wn*64 + ni*8 + t4*2;
                float vx = acc[mi][ni][half*2 + 0] + __ldg(bias + col);
                float vy = acc[mi][ni][half*2 + 1] + __ldg(bias + col + 1);
                if (EPI == 1) {
                    vx += __ldg(res + (size_t)row * N + col);
                    vy += __ldg(res + (size_t)row * N + col + 1);
                } else if (EPI == 2) {
                    vx = 0.5f * vx * (1.f + erff(vx * 0.70710678118654752f));
                    vy = 0.5f * vy * (1.f + erff(vy * 0.70710678118654752f));
                    vx = tfround(vx); vy = tfround(vy);
                } else {
                    vx = tfround(vx); vy = tfround(vy);
                }
                float2 o; o.x = vx; o.y = vy;
                *reinterpret_cast<float2*>(C + (size_t)row * N + col) = o;
            }
        }
    }
}

// fused QKV: BT = wqkvT [3072][1024]; grid.x = 24 (3 outputs x 8 col-blocks)
__global__ void __launch_bounds__(128, 3) tc_gemm_qkv(
    const float* __restrict__ A, const float* __restrict__ BT,
    const float* __restrict__ bq, const float* __restrict__ bk,
    const float* __restrict__ bv,
    float* __restrict__ q, float* __restrict__ k, float* __restrict__ v, int K)
{
    extern __shared__ float smem[];
    const int t = threadIdx.x;
    const int lane = t & 31, warp = t >> 5;
    const int wm = warp >> 1, wn = warp & 1;
    const int g  = lane >> 2, t4 = lane & 3;
    const int which = blockIdx.x >> 3;
    const int bn = (blockIdx.x & 7) * 128;
    const int bm = blockIdx.y * 128;
    const float* bias = (which == 0) ? bq : (which == 1) ? bk : bv;
    float* C = (which == 0) ? q : (which == 1) ? k : v;

    float acc[4][8][4];
    #pragma unroll
    for (int mi = 0; mi < 4; mi++)
        #pragma unroll
        for (int ni = 0; ni < 8; ni++)
            #pragma unroll
            for (int c = 0; c < 4; c++) acc[mi][ni][c] = 0.f;

    gemm_mainloop(A + (size_t)bm * K, BT + (size_t)(which * Ec + bn) * K, K, smem, acc);

    #pragma unroll
    for (int mi = 0; mi < 4; mi++) {
        #pragma unroll
        for (int half = 0; half < 2; half++) {
            const int row = bm + wm*64 + mi*16 + g + half*8;
            #pragma unroll
            for (int ni = 0; ni < 8; ni++) {
                const int col = bn + wn*64 + ni*8 + t4*2;
                float vx = tfround(acc[mi][ni][half*2 + 0] + __ldg(bias + col));
                float vy = tfround(acc[mi][ni][half*2 + 1] + __ldg(bias + col + 1));
                float2 o; o.x = vx; o.y = vy;
                *reinterpret_cast<float2*>(C + (size_t)row * Ec + col) = o;
            }
        }
    }
}

// ---------------- fused flash attention (cp.async + ldmatrix, tf32 mma) ---------
#define QS_LD 68
#define KS_LD 68
#define VS_LD 72
#define PS_LD 132
#define ATTN_SMEM ((128*QS_LD + 2*128*KS_LD + 128*VS_LD + 128*PS_LD) * 4)  // 208896

__global__ void __launch_bounds__(256) attn_kernel(
    const float* __restrict__ q, const float* __restrict__ kg,
    const float* __restrict__ vg, float* __restrict__ ctx)
{
    extern __shared__ unsigned sm[];
    unsigned* Qs = sm;
    unsigned* Ks = Qs + 128 * QS_LD;     // 2 buffers
    unsigned* Vs = Ks + 2 * 128 * KS_LD;
    unsigned* Ps = Vs + 128 * VS_LD;

    const int t = threadIdx.x, lane = t & 31, warp = t >> 5;
    const int g = lane >> 2, t4 = lane & 3;
    const int b = blockIdx.y >> 4, h = blockIdx.y & 15;
    const size_t base = (size_t)b * Sc * Ec + (size_t)h * HDc;
    const float* qp = q  + base + (size_t)blockIdx.x * 128 * Ec;
    const float* kp = kg + base;
    const float* vp = vg + base;

    const uint32_t qb = smem_u32(Qs);
    const uint32_t kb = smem_u32(Ks);
    const uint32_t vb = smem_u32(Vs);
    const uint32_t pb = smem_u32(Ps);

    const int arow = lane & 15;
    const int akof = (lane & 16) ? 4 : 0;
    const int brow = lane & 7;
    const int bkof = ((lane >> 3) & 1) * 4;

    #pragma unroll
    for (int i = 0; i < 8; i++) {
        const int lin = t + i*256;
        const int r = lin >> 4, c = (lin & 15) * 4;
        cp16(qb + (r*QS_LD + c)*4, qp + (size_t)r * Ec + c);
        cp16(kb + (r*KS_LD + c)*4, kp + (size_t)r * Ec + c);
    }
    cp_commit();

    float o[8][4];
    #pragma unroll
    for (int ni = 0; ni < 8; ni++)
        #pragma unroll
        for (int c = 0; c < 4; c++) o[ni][c] = 0.f;
    float m0 = -INFINITY, m1 = -INFINITY, l0 = 0.f, l1 = 0.f;
    const int pr0 = warp*16 + g;
    const uint32_t qA = qb + ((warp*16 + arow)*QS_LD + akof)*4;
    const uint32_t pA = pb + ((warp*16 + arow)*PS_LD + akof)*4;

    for (int kt = 0; kt < 16; kt++) {
        __syncthreads();
        #pragma unroll
        for (int i = 0; i < 8; i++) {
            const int lin = t + i*256;
            const int r = lin >> 4, c = (lin & 15) * 4;
            cp16(vb + (r*VS_LD + c)*4, vp + (size_t)(kt*128 + r) * Ec + c);
        }
        cp_commit();
        if (kt < 15) {
            const uint32_t kbn = kb + ((kt+1)&1) * (128*KS_LD*4);
            #pragma unroll
            for (int i = 0; i < 8; i++) {
                const int lin = t + i*256;
                const int r = lin >> 4, c = (lin & 15) * 4;
                cp16(kbn + (r*KS_LD + c)*4, kp + (size_t)((kt+1)*128 + r) * Ec + c);
            }
        }
        cp_commit();
        CP_WAIT(2);
        __syncthreads();

        const uint32_t kB = kb + (kt & 1) * (128*KS_LD*4) + (brow*KS_LD + bkof)*4;

        float sacc[16][4];
        #pragma unroll
        for (int ni = 0; ni < 16; ni++)
            #pragma unroll
            for (int c = 0; c < 4; c++) sacc[ni][c] = 0.f;
        #pragma unroll
        for (int kk = 0; kk < 8; kk++) {
            const int kbo = kk * 8;
            unsigned a[4];
            ldmA(a, qA + kbo*4);
            #pragma unroll
            for (int ni = 0; ni < 16; ni++) {
                unsigned bbf[2];
                ldmB(bbf, kB + (ni*8*KS_LD + kbo)*4);
                mma8(sacc[ni], a, bbf);
            }
        }

        float rm0 = -INFINITY, rm1 = -INFINITY;
        #pragma unroll
        for (int ni = 0; ni < 16; ni++) {
            sacc[ni][0] *= 0.125f; sacc[ni][1] *= 0.125f;
            sacc[ni][2] *= 0.125f; sacc[ni][3] *= 0.125f;
            rm0 = fmaxf(rm0, fmaxf(sacc[ni][0], sacc[ni][1]));
            rm1 = fmaxf(rm1, fmaxf(sacc[ni][2], sacc[ni][3]));
        }
        rm0 = fmaxf(rm0, __shfl_xor_sync(0xffffffffu, rm0, 1));
        rm0 = fmaxf(rm0, __shfl_xor_sync(0xffffffffu, rm0, 2));
        rm1 = fmaxf(rm1, __shfl_xor_sync(0xffffffffu, rm1, 1));
        rm1 = fmaxf(rm1, __shfl_xor_sync(0xffffffffu, rm1, 2));
        const float mn0 = fmaxf(m0, rm0), mn1 = fmaxf(m1, rm1);
        const float al0 = __expf(m0 - mn0), al1 = __expf(m1 - mn1);
        float ps0 = 0.f, ps1 = 0.f;
        #pragma unroll
        for (int ni = 0; ni < 16; ni++) {
            float p0 = __expf(sacc[ni][0] - mn0);
            float p1 = __expf(sacc[ni][1] - mn0);
            float p2 = __expf(sacc[ni][2] - mn1);
            float p3 = __expf(sacc[ni][3] - mn1);
            ps0 += p0 + p1; ps1 += p2 + p3;
            const int col = ni*8 + t4*2;
            Ps[pr0     * PS_LD + col    ] = __float_as_uint(p0);
            Ps[pr0     * PS_LD + col + 1] = __float_as_uint(p1);
            Ps[(pr0+8) * PS_LD + col    ] = __float_as_uint(p2);
            Ps[(pr0+8) * PS_LD + col + 1] = __float_as_uint(p3);
        }
        ps0 += __shfl_xor_sync(0xffffffffu, ps0, 1);
        ps0 += __shfl_xor_sync(0xffffffffu, ps0, 2);
        ps1 += __shfl_xor_sync(0xffffffffu, ps1, 1);
        ps1 += __shfl_xor_sync(0xffffffffu, ps1, 2);
        l0 = l0 * al0 + ps0; l1 = l1 * al1 + ps1;
        m0 = mn0; m1 = mn1;
        #pragma unroll
        for (int ni = 0; ni < 8; ni++) {
            o[ni][0] *= al0; o[ni][1] *= al0;
            o[ni][2] *= al1; o[ni][3] *= al1;
        }
        __syncwarp();

        CP_WAIT(1);
        __syncthreads();

        #pragma unroll
        for (int kk = 0; kk < 16; kk++) {
            const int kbo = kk * 8;
            unsigned a[4];
            ldmA(a, pA + kbo*4);
            #pragma unroll
            for (int ni = 0; ni < 8; ni++) {
                unsigned bbf[2];
                const int d = ni*8 + g;
                bbf[0] = Vs[(kbo + t4    ) * VS_LD + d];
                bbf[1] = Vs[(kbo + t4 + 4) * VS_LD + d];
                mma8(o[ni], a, bbf);
            }
        }
    }

    const float inv0 = 1.f / l0, inv1 = 1.f / l1;
    float* cp = ctx + base + (size_t)blockIdx.x * 128 * Ec;
    #pragma unroll
    for (int ni = 0; ni < 8; ni++) {
        const int d = ni*8 + t4*2;
        float2 u0; u0.x = tfround(o[ni][0] * inv0); u0.y = tfround(o[ni][1] * inv0);
        float2 u1; u1.x = tfround(o[ni][2] * inv1); u1.y = tfround(o[ni][3] * inv1);
        *reinterpret_cast<float2*>(cp + (size_t)pr0     * Ec + d) = u0;
        *reinterpret_cast<float2*>(cp + (size_t)(pr0+8) * Ec + d) = u1;
    }
}

// ---------------- launch ----------------
extern "C" void kernel_launch(void* const* d_in, const int* in_sizes, int n_in,
                              void* d_out, int out_size)
{
    const float* x   = (const float*)d_in[0];
    const float* wq  = (const float*)d_in[1];
    const float* bq  = (const float*)d_in[2];
    const float* wk  = (const float*)d_in[3];
    const float* bk  = (const float*)d_in[4];
    const float* wv  = (const float*)d_in[5];
    const float* bv  = (const float*)d_in[6];
    const float* wo  = (const float*)d_in[7];
    const float* bo  = (const float*)d_in[8];
    const float* w1  = (const float*)d_in[9];
    const float* b1  = (const float*)d_in[10];
    const float* w2  = (const float*)d_in[11];
    const float* b2  = (const float*)d_in[12];
    const float* g1  = (const float*)d_in[13];
    const float* be1 = (const float*)d_in[14];
    const float* g2  = (const float*)d_in[15];
    const float* be2 = (const float*)d_in[16];
    float* out = (float*)d_out;

    float *z0, *q, *k, *v, *ctx, *x1, *z1, *h;
    float *wqkvT, *woT, *w1T, *w2T;
    cudaGetSymbolAddress((void**)&z0,   g_z0);
    cudaGetSymbolAddress((void**)&q,    g_q);
    cudaGetSymbolAddress((void**)&k,    g_k);
    cudaGetSymbolAddress((void**)&v,    g_v);
    cudaGetSymbolAddress((void**)&ctx,  g_ctx);
    cudaGetSymbolAddress((void**)&x1,   g_x1);
    cudaGetSymbolAddress((void**)&z1,   g_z1);
    cudaGetSymbolAddress((void**)&h,    g_h);
    cudaGetSymbolAddress((void**)&wqkvT, g_wqkvT);
    cudaGetSymbolAddress((void**)&woT,  g_woT);
    cudaGetSymbolAddress((void**)&w1T,  g_w1T);
    cudaGetSymbolAddress((void**)&w2T,  g_w2T);

    cudaFuncSetAttribute(attn_kernel,  cudaFuncAttributeMaxDynamicSharedMemorySize, ATTN_SMEM);
    cudaFuncSetAttribute(tc_gemm<0>,   cudaFuncAttributeMaxDynamicSharedMemorySize, SMEM_GEMM);
    cudaFuncSetAttribute(tc_gemm<1>,   cudaFuncAttributeMaxDynamicSharedMemorySize, SMEM_GEMM);
    cudaFuncSetAttribute(tc_gemm<2>,   cudaFuncAttributeMaxDynamicSharedMemorySize, SMEM_GEMM);
    cudaFuncSetAttribute(tc_gemm_qkv,  cudaFuncAttributeMaxDynamicSharedMemorySize, SMEM_GEMM);

    // 1
    ln_kernel<<<TOK, 256>>>(x, g1, be1, z0);
    // 2
    transpose4_kernel<<<dim3(32, 32, 4), 256>>>(
        wq, wk, wv, wo,
        wqkvT, wqkvT + (size_t)Ec*Ec, wqkvT + (size_t)2*Ec*Ec, woT);
    // 3
    transpose_kernel<<<dim3(MLPc/32, Ec/32), 256>>>(w1, w1T, Ec, MLPc);
    // 4
    tc_gemm_qkv<<<dim3(24, TOK/128), 128, SMEM_GEMM>>>(z0, wqkvT, bq, bk, bv, q, k, v, Ec);
    // 5
    attn_kernel<<<dim3(Sc/128, Bc*Hc), 256, ATTN_SMEM>>>(q, k, v, ctx);
    // 6  <- profiled by ncu (-s 5 -c 1)
    tc_gemm<1><<<dim3(Ec/128, TOK/128), 128, SMEM_GEMM>>>(ctx, woT, bo, x, x1, TOK, Ec, Ec);
    // 7
    ln_kernel<<<TOK, 256>>>(x1, g2, be2, z1);
    // 8
    transpose_kernel<<<dim3(Ec/32, MLPc/32), 256>>>(w2, w2T, MLPc, Ec);
    // 9
    tc_gemm<2><<<dim3(MLPc/128, TOK/128), 128, SMEM_GEMM>>>(z1, w1T, b1, nullptr, h, TOK, MLPc, Ec);
    // 10
    tc_gemm<1><<<dim3(Ec/128, TOK/128), 128, SMEM_GEMM>>>(h, w2T, b2, x1, out, TOK, Ec, MLPc);
}

// round 11
// speedup vs baseline: 1.2221x; 1.0825x over previous
#include <cuda_runtime.h>
#include <cuda_bf16.h>
#include <cstdint>
#include <math.h>

#define Bc   2
#define Sc   2048
#define TOK  4096
#define Ec   1024
#define Hc   16
#define HDc  64
#define MLPc 4096

// ---------------- scratch (no allocations allowed) ----------------
__device__ float g_z0[(size_t)TOK * Ec];
__device__ float g_q [(size_t)TOK * Ec];
__device__ float g_k [(size_t)TOK * Ec];
__device__ __nv_bfloat16 g_v[(size_t)TOK * Ec];
__device__ float g_ctx[(size_t)TOK * Ec];
__device__ float g_x1[(size_t)TOK * Ec];
__device__ float g_z1[(size_t)TOK * Ec];
__device__ float g_h [(size_t)TOK * MLPc];
__device__ float g_wqkvT[(size_t)3 * Ec * Ec];
__device__ float g_woT[(size_t)Ec * Ec];
__device__ float g_w1T[(size_t)Ec * MLPc];
__device__ float g_w2T[(size_t)MLPc * Ec];

// ---------------- helpers ----------------
__device__ __forceinline__ unsigned f2tf(float f) {
    unsigned r;
    asm("cvt.rna.tf32.f32 %0, %1;" : "=r"(r) : "f"(f));
    return r;
}
__device__ __forceinline__ float tfround(float f) {
    return __uint_as_float(f2tf(f));
}
__device__ __forceinline__ unsigned pack_bf16(float lo, float hi) {
    unsigned r;
    asm("cvt.rn.bf16x2.f32 %0, %1, %2;" : "=r"(r) : "f"(hi), "f"(lo));
    return r;
}
__device__ __forceinline__ uint32_t smem_u32(const void* p) {
    uint32_t a;
    asm("{ .reg .u64 t; cvta.to.shared.u64 t, %1; cvt.u32.u64 %0, t; }" : "=r"(a) : "l"(p));
    return a;
}
__device__ __forceinline__ void cp16(uint32_t d, const void* s) {
    asm volatile("cp.async.cg.shared.global [%0], [%1], 16;\n" :: "r"(d), "l"(s));
}
__device__ __forceinline__ void cp_commit() {
    asm volatile("cp.async.commit_group;\n" ::: "memory");
}
#define CP_WAIT(n) asm volatile("cp.async.wait_group %0;\n" :: "n"(n) : "memory")

__device__ __forceinline__ void mma8(float c[4], const unsigned a[4], const unsigned b[2]) {
    asm volatile(
        "mma.sync.aligned.m16n8k8.row.col.f32.tf32.tf32.f32 "
        "{%0,%1,%2,%3}, {%4,%5,%6,%7}, {%8,%9}, {%0,%1,%2,%3};\n"
        : "+f"(c[0]), "+f"(c[1]), "+f"(c[2]), "+f"(c[3])
        : "r"(a[0]), "r"(a[1]), "r"(a[2]), "r"(a[3]),
          "r"(b[0]), "r"(b[1]));
}
__device__ __forceinline__ void mma16bf(float c[4], const unsigned a[4], const unsigned b[2]) {
    asm volatile(
        "mma.sync.aligned.m16n8k16.row.col.f32.bf16.bf16.f32 "
        "{%0,%1,%2,%3}, {%4,%5,%6,%7}, {%8,%9}, {%0,%1,%2,%3};\n"
        : "+f"(c[0]), "+f"(c[1]), "+f"(c[2]), "+f"(c[3])
        : "r"(a[0]), "r"(a[1]), "r"(a[2]), "r"(a[3]),
          "r"(b[0]), "r"(b[1]));
}
// tf32-as-b16-pairs fragment loads (CUTLASS-style); also used natively for bf16
__device__ __forceinline__ void ldmA(unsigned a[4], uint32_t addr) {
    asm volatile("ldmatrix.sync.aligned.m8n8.x4.shared.b16 {%0,%1,%2,%3}, [%4];"
                 : "=r"(a[0]), "=r"(a[1]), "=r"(a[2]), "=r"(a[3]) : "r"(addr));
}
__device__ __forceinline__ void ldmB(unsigned b[2], uint32_t addr) {
    asm volatile("ldmatrix.sync.aligned.m8n8.x2.shared.b16 {%0,%1}, [%2];"
                 : "=r"(b[0]), "=r"(b[1]) : "r"(addr));
}
__device__ __forceinline__ void ldmBT(unsigned b[2], uint32_t addr) {
    asm volatile("ldmatrix.sync.aligned.m8n8.x2.trans.shared.b16 {%0,%1}, [%2];"
                 : "=r"(b[0]), "=r"(b[1]) : "r"(addr));
}

// ---------------- weight transposes (+ tf32 rounding) ----------------
__global__ void __launch_bounds__(256) transpose4_kernel(
    const float* __restrict__ i0, const float* __restrict__ i1,
    const float* __restrict__ i2, const float* __restrict__ i3,
    float* __restrict__ o0, float* __restrict__ o1,
    float* __restrict__ o2, float* __restrict__ o3)
{
    const float* in  = (blockIdx.z == 0) ? i0 : (blockIdx.z == 1) ? i1 : (blockIdx.z == 2) ? i2 : i3;
    float*       out = (blockIdx.z == 0) ? o0 : (blockIdx.z == 1) ? o1 : (blockIdx.z == 2) ? o2 : o3;
    __shared__ float tile[32][33];
    const int bx = blockIdx.x * 32, by = blockIdx.y * 32;
    const int tx = threadIdx.x & 31, ty = threadIdx.x >> 5;
    #pragma unroll
    for (int i = 0; i < 32; i += 8)
        tile[ty + i][tx] = tfround(in[(size_t)(by + ty + i) * Ec + bx + tx]);
    __syncthreads();
    #pragma unroll
    for (int i = 0; i < 32; i += 8)
        out[(size_t)(bx + ty + i) * Ec + by + tx] = tile[tx][ty + i];
}

__global__ void __launch_bounds__(256) transpose_kernel(
    const float* __restrict__ in, float* __restrict__ out, int R, int C)
{
    __shared__ float tile[32][33];
    const int bx = blockIdx.x * 32, by = blockIdx.y * 32;
    const int tx = threadIdx.x & 31, ty = threadIdx.x >> 5;
    #pragma unroll
    for (int i = 0; i < 32; i += 8)
        tile[ty + i][tx] = tfround(in[(size_t)(by + ty + i) * C + bx + tx]);
    __syncthreads();
    #pragma unroll
    for (int i = 0; i < 32; i += 8)
        out[(size_t)(bx + ty + i) * R + by + tx] = tile[tx][ty + i];
}

// ---------------- LayerNorm (fp32 exact, tf32-rounded output) ----------------
__global__ void __launch_bounds__(256) ln_kernel(
    const float* __restrict__ x, const float* __restrict__ gam,
    const float* __restrict__ bet, float* __restrict__ y)
{
    const int row = blockIdx.x, t = threadIdx.x;
    const float4* xr = reinterpret_cast<const float4*>(x + (size_t)row * Ec);
    float4 v = xr[t];
    float s  = v.x + v.y + v.z + v.w;
    float ss = v.x*v.x + v.y*v.y + v.z*v.z + v.w*v.w;
    #pragma unroll
    for (int o = 16; o; o >>= 1) {
        s  += __shfl_xor_sync(0xffffffffu, s,  o);
        ss += __shfl_xor_sync(0xffffffffu, ss, o);
    }
    __shared__ float rs[8], rss[8];
    if ((t & 31) == 0) { rs[t >> 5] = s; rss[t >> 5] = ss; }
    __syncthreads();
    if (t < 32) {
        float a = (t < 8) ? rs[t]  : 0.f;
        float b = (t < 8) ? rss[t] : 0.f;
        #pragma unroll
        for (int o = 4; o; o >>= 1) {
            a += __shfl_xor_sync(0xffffffffu, a, o);
            b += __shfl_xor_sync(0xffffffffu, b, o);
        }
        if (t == 0) { rs[0] = a; rss[0] = b; }
    }
    __syncthreads();
    const float mu   = rs[0]  * (1.f / Ec);
    const float var  = rss[0] * (1.f / Ec) - mu * mu;
    const float rstd = rsqrtf(var + 1e-5f);
    float4 gv = reinterpret_cast<const float4*>(gam)[t];
    float4 bv = reinterpret_cast<const float4*>(bet)[t];
    float4 o;
    o.x = tfround((v.x - mu) * rstd * gv.x + bv.x);
    o.y = tfround((v.y - mu) * rstd * gv.y + bv.y);
    o.z = tfround((v.z - mu) * rstd * gv.z + bv.z);
    o.w = tfround((v.w - mu) * rstd * gv.w + bv.w);
    reinterpret_cast<float4*>(y + (size_t)row * Ec)[t] = o;
}

// ---- TF32 GEMM (2-stage, k-tile 32, 128 thr, warp 64x64, ldmatrix, 3 CTA/SM) ---
#define KT   32
#define SW   36
#define STG  (128 * SW)
#define NSTG 2
#define SMEM_GEMM (2 * NSTG * STG * 4)   // 73728 bytes -> 3 CTAs/SM

__device__ __forceinline__ void ldstage(uint32_t ab, uint32_t bb,
    const float* __restrict__ Ap, const float* __restrict__ Bp, int K, int kt)
{
    const int t = threadIdx.x;
    const int k0 = kt * KT;
    #pragma unroll
    for (int i = 0; i < 8; i++) {
        const int idx = t + i * 128;
        const int r = idx >> 3, cu = (idx & 7) * 4;
        cp16(ab + (r * SW + cu) * 4, Ap + (size_t)r * K + k0 + cu);
    }
    #pragma unroll
    for (int i = 0; i < 8; i++) {
        const int idx = t + i * 128;
        const int r = idx >> 3, cu = (idx & 7) * 4;
        cp16(bb + (r * SW + cu) * 4, Bp + (size_t)r * K + k0 + cu);
    }
}

__device__ __forceinline__ void gemm_mainloop(
    const float* __restrict__ Ap, const float* __restrict__ Bp, int K,
    float* smem, float acc[4][8][4])
{
    const int t    = threadIdx.x;
    const int lane = t & 31, warp = t >> 5;
    const int wm = warp >> 1, wn = warp & 1;
    const int NK = K / KT;

    const uint32_t asb = smem_u32(smem);
    const uint32_t bsb = asb + NSTG * STG * 4;

    const int arow = lane & 15;
    const int akof = (lane & 16) ? 4 : 0;
    const int brow = lane & 7;
    const int bkof = ((lane >> 3) & 1) * 4;

    ldstage(asb, bsb, Ap, Bp, K, 0);
    cp_commit();

    int st = 0;
    for (int kt = 0; kt < NK; kt++) {
        CP_WAIT(0);
        __syncthreads();
        if (kt + 1 < NK) {
            const int ps = st ^ 1;
            ldstage(asb + ps * STG * 4, bsb + ps * STG * 4, Ap, Bp, K, kt + 1);
        }
        cp_commit();

        const uint32_t as = asb + st * STG * 4;
        const uint32_t bs = bsb + st * STG * 4;
        const uint32_t aB = as + ((wm*64 + arow) * SW + akof) * 4;
        const uint32_t bB = bs + ((wn*64 + brow) * SW + bkof) * 4;
        #pragma unroll
        for (int kb = 0; kb < KT; kb += 8) {
            unsigned af[4][4], bf[8][2];
            #pragma unroll
            for (int mi = 0; mi < 4; mi++)
                ldmA(af[mi], aB + (mi*16*SW + kb) * 4);
            #pragma unroll
            for (int ni = 0; ni < 8; ni++)
                ldmB(bf[ni], bB + (ni*8*SW + kb) * 4);
            #pragma unroll
            for (int mi = 0; mi < 4; mi++)
                #pragma unroll
                for (int ni = 0; ni < 8; ni++)
                    mma8(acc[mi][ni], af[mi], bf[ni]);
        }
        st ^= 1;
    }
}

// EPI: 0 = bias(->tf32), 1 = bias+res (fp32), 2 = bias+gelu(->tf32)
template <int EPI>
__global__ void __launch_bounds__(128, 3) tc_gemm(
    const float* __restrict__ A, const float* __restrict__ BT,
    const float* __restrict__ bias, const float* __restrict__ res,
    float* __restrict__ C, int M, int N, int K)
{
    extern __shared__ float smem[];
    const int t = threadIdx.x;
    const int lane = t & 31, warp = t >> 5;
    const int wm = warp >> 1, wn = warp & 1;
    const int g  = lane >> 2, t4 = lane & 3;
    const int bm = blockIdx.y * 128, bn = blockIdx.x * 128;

    float acc[4][8][4];
    #pragma unroll
    for (int mi = 0; mi < 4; mi++)
        #pragma unroll
        for (int ni = 0; ni < 8; ni++)
            #pragma unroll
            for (int c = 0; c < 4; c++) acc[mi][ni][c] = 0.f;

    gemm_mainloop(A + (size_t)bm * K, BT + (size_t)bn * K, K, smem, acc);

    #pragma unroll
    for (int mi = 0; mi < 4; mi++) {
        #pragma unroll
        for (int half = 0; half < 2; half++) {
            const int row = bm + wm*64 + mi*16 + g + half*8;
            #pragma unroll
            for (int ni = 0; ni < 8; ni++) {
                const int col = bn + wn*64 + ni*8 + t4*2;
                float vx = acc[mi][ni][half*2 + 0] + __ldg(bias + col);
                float vy = acc[mi][ni][half*2 + 1] + __ldg(bias + col + 1);
                if (EPI == 1) {
                    vx += __ldg(res + (size_t)row * N + col);
                    vy += __ldg(res + (size_t)row * N + col + 1);
                } else if (EPI == 2) {
                    vx = 0.5f * vx * (1.f + erff(vx * 0.70710678118654752f));
                    vy = 0.5f * vy * (1.f + erff(vy * 0.70710678118654752f));
                    vx = tfround(vx); vy = tfround(vy);
                } else {
                    vx = tfround(vx); vy = tfround(vy);
                }
                float2 o; o.x = vx; o.y = vy;
                *reinterpret_cast<float2*>(C + (size_t)row * N + col) = o;
            }
        }
    }
}

// fused QKV: BT = wqkvT [3072][1024]; grid.x = 24. V output is bf16.
__global__ void __launch_bounds__(128, 3) tc_gemm_qkv(
    const float* __restrict__ A, const float* __restrict__ BT,
    const float* __restrict__ bq, const float* __restrict__ bk,
    const float* __restrict__ bv,
    float* __restrict__ q, float* __restrict__ k,
    __nv_bfloat16* __restrict__ v, int K)
{
    extern __shared__ float smem[];
    const int t = threadIdx.x;
    const int lane = t & 31, warp = t >> 5;
    const int wm = warp >> 1, wn = warp & 1;
    const int g  = lane >> 2, t4 = lane & 3;
    const int which = blockIdx.x >> 3;
    const int bn = (blockIdx.x & 7) * 128;
    const int bm = blockIdx.y * 128;
    const float* bias = (which == 0) ? bq : (which == 1) ? bk : bv;

    float acc[4][8][4];
    #pragma unroll
    for (int mi = 0; mi < 4; mi++)
        #pragma unroll
        for (int ni = 0; ni < 8; ni++)
            #pragma unroll
            for (int c = 0; c < 4; c++) acc[mi][ni][c] = 0.f;

    gemm_mainloop(A + (size_t)bm * K, BT + (size_t)(which * Ec + bn) * K, K, smem, acc);

    float* C = (which == 0) ? q : k;
    #pragma unroll
    for (int mi = 0; mi < 4; mi++) {
        #pragma unroll
        for (int half = 0; half < 2; half++) {
            const int row = bm + wm*64 + mi*16 + g + half*8;
            #pragma unroll
            for (int ni = 0; ni < 8; ni++) {
                const int col = bn + wn*64 + ni*8 + t4*2;
                float vx = acc[mi][ni][half*2 + 0] + __ldg(bias + col);
                float vy = acc[mi][ni][half*2 + 1] + __ldg(bias + col + 1);
                if (which == 2) {
                    *reinterpret_cast<unsigned*>(v + (size_t)row * Ec + col) = pack_bf16(vx, vy);
                } else {
                    float2 o; o.x = tfround(vx); o.y = tfround(vy);
                    *reinterpret_cast<float2*>(C + (size_t)row * Ec + col) = o;
                }
            }
        }
    }
}

// -------- fused flash attention: QK^T tf32, softmax, P.V bf16 (m16n8k16) --------
#define QS_LD  68      // tf32 words
#define KS_LD  68      // tf32 words
#define VS2_LD 72      // bf16 units (64 + 8 pad)
#define PS2_LD 136     // bf16 units (128 + 8 pad)
// words: Q 8704 + K 17408 + V 4608 + P 8704 = 39424 -> 157696 bytes
#define ATTN_SMEM ((128*QS_LD + 2*128*KS_LD + (128*VS2_LD)/2 + (128*PS2_LD)/2) * 4)

__global__ void __launch_bounds__(256) attn_kernel(
    const float* __restrict__ q, const float* __restrict__ kg,
    const __nv_bfloat16* __restrict__ vg, float* __restrict__ ctx)
{
    extern __shared__ unsigned sm[];
    unsigned* Qs = sm;
    unsigned* Ks = Qs + 128 * QS_LD;                 // 2 buffers
    unsigned* Ps2 = Ks + 2 * 128 * KS_LD + (128 * VS2_LD) / 2;  // bf16 pairs

    const int t = threadIdx.x, lane = t & 31, warp = t >> 5;
    const int g = lane >> 2, t4 = lane & 3;
    const int b = blockIdx.y >> 4, h = blockIdx.y & 15;
    const size_t base = (size_t)b * Sc * Ec + (size_t)h * HDc;
    const float* qp = q  + base + (size_t)blockIdx.x * 128 * Ec;
    const float* kp = kg + base;
    const __nv_bfloat16* vp = vg + base;

    const uint32_t qb = smem_u32(Qs);
    const uint32_t kb = qb + 128 * QS_LD * 4;
    const uint32_t vb = kb + 2 * 128 * KS_LD * 4;    // bf16 region
    const uint32_t pb = vb + 128 * VS2_LD * 2;       // bf16 region

    // tf32 ldmatrix lane mapping (QK)
    const int arow = lane & 15;
    const int akof = (lane & 16) ? 4 : 0;
    const int brow = lane & 7;
    const int bkof = ((lane >> 3) & 1) * 4;
    // bf16 ldmatrix lane mappings (PV)
    const int prow = warp*16 + ((lane >> 3) & 1) * 8 + (lane & 7);
    const int pcol = ((lane >> 4) & 1) * 8;
    const int vrow = ((lane & 15) & 7) + 8 * (((lane & 15) >> 3) & 1);

    // prologue: Q tile + K tile 0 (one group)
    #pragma unroll
    for (int i = 0; i < 8; i++) {
        const int lin = t + i*256;
        const int r = lin >> 4, c = (lin & 15) * 4;
        cp16(qb + (r*QS_LD + c)*4, qp + (size_t)r * Ec + c);
        cp16(kb + (r*KS_LD + c)*4, kp + (size_t)r * Ec + c);
    }
    cp_commit();

    float o[8][4];
    #pragma unroll
    for (int ni = 0; ni < 8; ni++)
        #pragma unroll
        for (int c = 0; c < 4; c++) o[ni][c] = 0.f;
    float m0 = -INFINITY, m1 = -INFINITY, l0 = 0.f, l1 = 0.f;
    const int pr0 = warp*16 + g;
    const uint32_t qA = qb + ((warp*16 + arow)*QS_LD + akof)*4;
    const uint32_t pA = pb + (prow*PS2_LD + pcol)*2;
    const uint32_t vBbase = vb + (vrow*VS2_LD)*2;

    for (int kt = 0; kt < 16; kt++) {
        __syncthreads();
        // V(kt) bf16: 128 rows x 64 cols = 1024 16B-chunks
        #pragma unroll
        for (int i = 0; i < 4; i++) {
            const int idx = t + i*256;
            const int r = idx >> 3, cu = (idx & 7) * 8;
            cp16(vb + (r*VS2_LD + cu)*2, vp + (size_t)(kt*128 + r) * Ec + cu);
        }
        cp_commit();
        if (kt < 15) {
            const uint32_t kbn = kb + ((kt+1)&1) * (128*KS_LD*4);
            #pragma unroll
            for (int i = 0; i < 8; i++) {
                const int lin = t + i*256;
                const int r = lin >> 4, c = (lin & 15) * 4;
                cp16(kbn + (r*KS_LD + c)*4, kp + (size_t)((kt+1)*128 + r) * Ec + c);
            }
        }
        cp_commit();
        CP_WAIT(2);
        __syncthreads();

        const uint32_t kB = kb + (kt & 1) * (128*KS_LD*4) + (brow*KS_LD + bkof)*4;

        // S = Q @ K^T (tf32)
        float sacc[16][4];
        #pragma unroll
        for (int ni = 0; ni < 16; ni++)
            #pragma unroll
            for (int c = 0; c < 4; c++) sacc[ni][c] = 0.f;
        #pragma unroll
        for (int kk = 0; kk < 8; kk++) {
            const int kbo = kk * 8;
            unsigned a[4];
            ldmA(a, qA + kbo*4);
            #pragma unroll
            for (int ni = 0; ni < 16; ni++) {
                unsigned bbf[2];
                ldmB(bbf, kB + (ni*8*KS_LD + kbo)*4);
                mma8(sacc[ni], a, bbf);
            }
        }

        // online softmax; P -> bf16 SMEM
        float rm0 = -INFINITY, rm1 = -INFINITY;
        #pragma unroll
        for (int ni = 0; ni < 16; ni++) {
            sacc[ni][0] *= 0.125f; sacc[ni][1] *= 0.125f;
            sacc[ni][2] *= 0.125f; sacc[ni][3] *= 0.125f;
            rm0 = fmaxf(rm0, fmaxf(sacc[ni][0], sacc[ni][1]));
            rm1 = fmaxf(rm1, fmaxf(sacc[ni][2], sacc[ni][3]));
        }
        rm0 = fmaxf(rm0, __shfl_xor_sync(0xffffffffu, rm0, 1));
        rm0 = fmaxf(rm0, __shfl_xor_sync(0xffffffffu, rm0, 2));
        rm1 = fmaxf(rm1, __shfl_xor_sync(0xffffffffu, rm1, 1));
        rm1 = fmaxf(rm1, __shfl_xor_sync(0xffffffffu, rm1, 2));
        const float mn0 = fmaxf(m0, rm0), mn1 = fmaxf(m1, rm1);
        const float al0 = __expf(m0 - mn0), al1 = __expf(m1 - mn1);
        float ps0 = 0.f, ps1 = 0.f;
        unsigned* Pw = Ps2;
        #pragma unroll
        for (int ni = 0; ni < 16; ni++) {
            float p0 = __expf(sacc[ni][0] - mn0);
            float p1 = __expf(sacc[ni][1] - mn0);
            float p2 = __expf(sacc[ni][2] - mn1);
            float p3 = __expf(sacc[ni][3] - mn1);
            ps0 += p0 + p1; ps1 += p2 + p3;
            const int col = ni*8 + t4*2;
            Pw[(pr0     * PS2_LD + col) >> 1] = pack_bf16(p0, p1);
            Pw[((pr0+8) * PS2_LD + col) >> 1] = pack_bf16(p2, p3);
        }
        ps0 += __shfl_xor_sync(0xffffffffu, ps0, 1);
        ps0 += __shfl_xor_sync(0xffffffffu, ps0, 2);
        ps1 += __shfl_xor_sync(0xffffffffu, ps1, 1);
        ps1 += __shfl_xor_sync(0xffffffffu, ps1, 2);
        l0 = l0 * al0 + ps0; l1 = l1 * al1 + ps1;
        m0 = mn0; m1 = mn1;
        #pragma unroll
        for (int ni = 0; ni < 8; ni++) {
            o[ni][0] *= al0; o[ni][1] *= al0;
            o[ni][2] *= al1; o[ni][3] *= al1;
        }
        __syncwarp();

        CP_WAIT(1);
        __syncthreads();

        // O += P @ V  (bf16, m16n8k16: 8 k-chunks of 16 over the 128 kv rows)
        #pragma unroll
        for (int kk = 0; kk < 8; kk++) {
            unsigned a[4];
            ldmA(a, pA + kk*32);
            const uint32_t vB = vBbase + kk*16*VS2_LD*2;
            #pragma unroll
            for (int ni = 0; ni < 8; ni++) {
                unsigned bbf[2];
                ldmBT(bbf, vB + ni*16);
                mma16bf(o[ni], a, bbf);
            }
        }
    }

    const float inv0 = 1.f / l0, inv1 = 1.f / l1;
    float* cp = ctx + base + (size_t)blockIdx.x * 128 * Ec;
    #pragma unroll
    for (int ni = 0; ni < 8; ni++) {
        const int d = ni*8 + t4*2;
        float2 u0; u0.x = tfround(o[ni][0] * inv0); u0.y = tfround(o[ni][1] * inv0);
        float2 u1; u1.x = tfround(o[ni][2] * inv1); u1.y = tfround(o[ni][3] * inv1);
        *reinterpret_cast<float2*>(cp + (size_t)pr0     * Ec + d) = u0;
        *reinterpret_cast<float2*>(cp + (size_t)(pr0+8) * Ec + d) = u1;
    }
}

// ---------------- launch ----------------
extern "C" void kernel_launch(void* const* d_in, const int* in_sizes, int n_in,
                              void* d_out, int out_size)
{
    const float* x   = (const float*)d_in[0];
    const float* wq  = (const float*)d_in[1];
    const float* bq  = (const float*)d_in[2];
    const float* wk  = (const float*)d_in[3];
    const float* bk  = (const float*)d_in[4];
    const float* wv  = (const float*)d_in[5];
    const float* bv  = (const float*)d_in[6];
    const float* wo  = (const float*)d_in[7];
    const float* bo  = (const float*)d_in[8];
    const float* w1  = (const float*)d_in[9];
    const float* b1  = (const float*)d_in[10];
    const float* w2  = (const float*)d_in[11];
    const float* b2  = (const float*)d_in[12];
    const float* g1  = (const float*)d_in[13];
    const float* be1 = (const float*)d_in[14];
    const float* g2  = (const float*)d_in[15];
    const float* be2 = (const float*)d_in[16];
    float* out = (float*)d_out;

    float *z0, *q, *k, *ctx, *x1, *z1, *h;
    __nv_bfloat16* v;
    float *wqkvT, *woT, *w1T, *w2T;
    cudaGetSymbolAddress((void**)&z0,   g_z0);
    cudaGetSymbolAddress((void**)&q,    g_q);
    cudaGetSymbolAddress((void**)&k,    g_k);
    cudaGetSymbolAddress((void**)&v,    g_v);
    cudaGetSymbolAddress((void**)&ctx,  g_ctx);
    cudaGetSymbolAddress((void**)&x1,   g_x1);
    cudaGetSymbolAddress((void**)&z1,   g_z1);
    cudaGetSymbolAddress((void**)&h,    g_h);
    cudaGetSymbolAddress((void**)&wqkvT, g_wqkvT);
    cudaGetSymbolAddress((void**)&woT,  g_woT);
    cudaGetSymbolAddress((void**)&w1T,  g_w1T);
    cudaGetSymbolAddress((void**)&w2T,  g_w2T);

    cudaFuncSetAttribute(attn_kernel,  cudaFuncAttributeMaxDynamicSharedMemorySize, ATTN_SMEM);
    cudaFuncSetAttribute(tc_gemm<0>,   cudaFuncAttributeMaxDynamicSharedMemorySize, SMEM_GEMM);
    cudaFuncSetAttribute(tc_gemm<1>,   cudaFuncAttributeMaxDynamicSharedMemorySize, SMEM_GEMM);
    cudaFuncSetAttribute(tc_gemm<2>,   cudaFuncAttributeMaxDynamicSharedMemorySize, SMEM_GEMM);
    cudaFuncSetAttribute(tc_gemm_qkv,  cudaFuncAttributeMaxDynamicSharedMemorySize, SMEM_GEMM);

    // 1
    ln_kernel<<<TOK, 256>>>(x, g1, be1, z0);
    // 2
    transpose4_kernel<<<dim3(32, 32, 4), 256>>>(
        wq, wk, wv, wo,
        wqkvT, wqkvT + (size_t)Ec*Ec, wqkvT + (size_t)2*Ec*Ec, woT);
    // 3
    transpose_kernel<<<dim3(MLPc/32, Ec/32), 256>>>(w1, w1T, Ec, MLPc);
    // 4
    tc_gemm_qkv<<<dim3(24, TOK/128), 128, SMEM_GEMM>>>(z0, wqkvT, bq, bk, bv, q, k, v, Ec);
    // 5
    attn_kernel<<<dim3(Sc/128, Bc*Hc), 256, ATTN_SMEM>>>(q, k, v, ctx);
    // 6
    tc_gemm<1><<<dim3(Ec/128, TOK/128), 128, SMEM_GEMM>>>(ctx, woT, bo, x, x1, TOK, Ec, Ec);
    // 7
    ln_kernel<<<TOK, 256>>>(x1, g2, be2, z1);
    // 8
    transpose_kernel<<<dim3(Ec/32, MLPc/32), 256>>>(w2, w2T, MLPc, Ec);
    // 9
    tc_gemm<2><<<dim3(MLPc/128, TOK/128), 128, SMEM_GEMM>>>(z1, w1T, b1, nullptr, h, TOK, MLPc, Ec);
    // 10
    tc_gemm<1><<<dim3(Ec/128, TOK/128), 128, SMEM_GEMM>>>(h, w2T, b2, x1, out, TOK, Ec, MLPc);
}

// round 12
// speedup vs baseline: 1.2547x; 1.0267x over previous
#include <cuda_runtime.h>
#include <cuda_bf16.h>
#include <cstdint>
#include <math.h>

#define Bc   2
#define Sc   2048
#define TOK  4096
#define Ec   1024
#define Hc   16
#define HDc  64
#define MLPc 4096

// ---------------- scratch (no allocations allowed) ----------------
__device__ float g_z0[(size_t)TOK * Ec];
__device__ __nv_bfloat16 g_q[(size_t)TOK * Ec];
__device__ __nv_bfloat16 g_k[(size_t)TOK * Ec];
__device__ __nv_bfloat16 g_v[(size_t)TOK * Ec];
__device__ float g_ctx[(size_t)TOK * Ec];
__device__ float g_x1[(size_t)TOK * Ec];
__device__ float g_z1[(size_t)TOK * Ec];
__device__ float g_h [(size_t)TOK * MLPc];

// ---------------- helpers ----------------
__device__ __forceinline__ unsigned f2tf(float f) {
    unsigned r;
    asm("cvt.rna.tf32.f32 %0, %1;" : "=r"(r) : "f"(f));
    return r;
}
__device__ __forceinline__ float tfround(float f) {
    return __uint_as_float(f2tf(f));
}
__device__ __forceinline__ unsigned pack_bf16(float lo, float hi) {
    unsigned r;
    asm("cvt.rn.bf16x2.f32 %0, %1, %2;" : "=r"(r) : "f"(hi), "f"(lo));
    return r;
}
__device__ __forceinline__ uint32_t smem_u32(const void* p) {
    uint32_t a;
    asm("{ .reg .u64 t; cvta.to.shared.u64 t, %1; cvt.u32.u64 %0, t; }" : "=r"(a) : "l"(p));
    return a;
}
__device__ __forceinline__ void cp16(uint32_t d, const void* s) {
    asm volatile("cp.async.cg.shared.global [%0], [%1], 16;\n" :: "r"(d), "l"(s));
}
__device__ __forceinline__ void cp_commit() {
    asm volatile("cp.async.commit_group;\n" ::: "memory");
}
#define CP_WAIT(n) asm volatile("cp.async.wait_group %0;\n" :: "n"(n) : "memory")

__device__ __forceinline__ void mma8(float c[4], const unsigned a[4], const unsigned b[2]) {
    asm volatile(
        "mma.sync.aligned.m16n8k8.row.col.f32.tf32.tf32.f32 "
        "{%0,%1,%2,%3}, {%4,%5,%6,%7}, {%8,%9}, {%0,%1,%2,%3};\n"
        : "+f"(c[0]), "+f"(c[1]), "+f"(c[2]), "+f"(c[3])
        : "r"(a[0]), "r"(a[1]), "r"(a[2]), "r"(a[3]),
          "r"(b[0]), "r"(b[1]));
}
__device__ __forceinline__ void mma16bf(float c[4], const unsigned a[4], const unsigned b[2]) {
    asm volatile(
        "mma.sync.aligned.m16n8k16.row.col.f32.bf16.bf16.f32 "
        "{%0,%1,%2,%3}, {%4,%5,%6,%7}, {%8,%9}, {%0,%1,%2,%3};\n"
        : "+f"(c[0]), "+f"(c[1]), "+f"(c[2]), "+f"(c[3])
        : "r"(a[0]), "r"(a[1]), "r"(a[2]), "r"(a[3]),
          "r"(b[0]), "r"(b[1]));
}
__device__ __forceinline__ void ldmA(unsigned a[4], uint32_t addr) {
    asm volatile("ldmatrix.sync.aligned.m8n8.x4.shared.b16 {%0,%1,%2,%3}, [%4];"
                 : "=r"(a[0]), "=r"(a[1]), "=r"(a[2]), "=r"(a[3]) : "r"(addr));
}
__device__ __forceinline__ void ldmB(unsigned b[2], uint32_t addr) {
    asm volatile("ldmatrix.sync.aligned.m8n8.x2.shared.b16 {%0,%1}, [%2];"
                 : "=r"(b[0]), "=r"(b[1]) : "r"(addr));
}
__device__ __forceinline__ void ldmBT(unsigned b[2], uint32_t addr) {
    asm volatile("ldmatrix.sync.aligned.m8n8.x2.trans.shared.b16 {%0,%1}, [%2];"
                 : "=r"(b[0]), "=r"(b[1]) : "r"(addr));
}

// ---------------- LayerNorm (fp32 exact, tf32-rounded output) ----------------
__global__ void __launch_bounds__(256) ln_kernel(
    const float* __restrict__ x, const float* __restrict__ gam,
    const float* __restrict__ bet, float* __restrict__ y)
{
    const int row = blockIdx.x, t = threadIdx.x;
    const float4* xr = reinterpret_cast<const float4*>(x + (size_t)row * Ec);
    float4 v = xr[t];
    float s  = v.x + v.y + v.z + v.w;
    float ss = v.x*v.x + v.y*v.y + v.z*v.z + v.w*v.w;
    #pragma unroll
    for (int o = 16; o; o >>= 1) {
        s  += __shfl_xor_sync(0xffffffffu, s,  o);
        ss += __shfl_xor_sync(0xffffffffu, ss, o);
    }
    __shared__ float rs[8], rss[8];
    if ((t & 31) == 0) { rs[t >> 5] = s; rss[t >> 5] = ss; }
    __syncthreads();
    if (t < 32) {
        float a = (t < 8) ? rs[t]  : 0.f;
        float b = (t < 8) ? rss[t] : 0.f;
        #pragma unroll
        for (int o = 4; o; o >>= 1) {
            a += __shfl_xor_sync(0xffffffffu, a, o);
            b += __shfl_xor_sync(0xffffffffu, b, o);
        }
        if (t == 0) { rs[0] = a; rss[0] = b; }
    }
    __syncthreads();
    const float mu   = rs[0]  * (1.f / Ec);
    const float var  = rss[0] * (1.f / Ec) - mu * mu;
    const float rstd = rsqrtf(var + 1e-5f);
    float4 gv = reinterpret_cast<const float4*>(gam)[t];
    float4 bv = reinterpret_cast<const float4*>(bet)[t];
    float4 o;
    o.x = tfround((v.x - mu) * rstd * gv.x + bv.x);
    o.y = tfround((v.y - mu) * rstd * gv.y + bv.y);
    o.z = tfround((v.z - mu) * rstd * gv.z + bv.z);
    o.w = tfround((v.w - mu) * rstd * gv.w + bv.w);
    reinterpret_cast<float4*>(y + (size_t)row * Ec)[t] = o;
}

// ---- TF32 GEMM, direct-B (no transpose): A[M,K] @ W[K,N], 2-stage, 3 CTA/SM ----
#define KT    32
#define ASW   36                     // A: words per 32-float row (+4 pad)
#define BSW   136                    // B: words per 128-float n-row (+8 pad) -> bank 8*t4+g
#define ASTG  (128 * ASW)            // 4608 words
#define BSTG  (KT * BSW)             // 4352 words
#define NSTG  2
#define SMEM_GEMM ((NSTG * ASTG + NSTG * BSTG) * 4)   // 71680 bytes -> 3 CTAs/SM

__device__ __forceinline__ void ldstage(uint32_t ab, uint32_t bb,
    const float* __restrict__ Ap, const float* __restrict__ Bp,
    int K, int N, int kt)
{
    const int t = threadIdx.x;
    const int k0 = kt * KT;
    #pragma unroll
    for (int i = 0; i < 8; i++) {
        const int idx = t + i * 128;
        const int r = idx >> 3, cu = (idx & 7) * 4;
        cp16(ab + (r * ASW + cu) * 4, Ap + (size_t)r * K + k0 + cu);
    }
    // B: 32 k-rows x 128 n-cols from W[K][N]
    #pragma unroll
    for (int i = 0; i < 8; i++) {
        const int idx = t + i * 128;
        const int r = idx >> 5, c = (idx & 31) * 4;
        cp16(bb + (r * BSW + c) * 4, Bp + (size_t)(k0 + r) * N + c);
    }
}

__device__ __forceinline__ void gemm_mainloop(
    const float* __restrict__ Ap, const float* __restrict__ Bp,
    int K, int N, float* smem, float acc[4][8][4])
{
    const int t    = threadIdx.x;
    const int lane = t & 31, warp = t >> 5;
    const int wm = warp >> 1, wn = warp & 1;
    const int g  = lane >> 2, t4 = lane & 3;
    const int NK = K / KT;

    const uint32_t asb = smem_u32(smem);
    const uint32_t bsb = asb + NSTG * ASTG * 4;

    const int arow = lane & 15;
    const int akof = (lane & 16) ? 4 : 0;

    ldstage(asb, bsb, Ap, Bp, K, N, 0);
    cp_commit();

    int st = 0;
    for (int kt = 0; kt < NK; kt++) {
        CP_WAIT(0);
        __syncthreads();
        if (kt + 1 < NK) {
            const int ps = st ^ 1;
            ldstage(asb + ps * ASTG * 4, bsb + ps * BSTG * 4, Ap, Bp, K, N, kt + 1);
        }
        cp_commit();

        const uint32_t aB = asb + st * ASTG * 4 + ((wm*64 + arow) * ASW + akof) * 4;
        const float* bsf = smem + NSTG * ASTG + st * BSTG;
        #pragma unroll
        for (int kb = 0; kb < KT; kb += 8) {
            unsigned af[4][4], bf[8][2];
            #pragma unroll
            for (int mi = 0; mi < 4; mi++)
                ldmA(af[mi], aB + (mi*16*ASW + kb) * 4);
            #pragma unroll
            for (int ni = 0; ni < 8; ni++) {
                const int nc = wn*64 + ni*8 + g;
                bf[ni][0] = __float_as_uint(bsf[(kb + t4    ) * BSW + nc]);
                bf[ni][1] = __float_as_uint(bsf[(kb + t4 + 4) * BSW + nc]);
            }
            #pragma unroll
            for (int mi = 0; mi < 4; mi++)
                #pragma unroll
                for (int ni = 0; ni < 8; ni++)
                    mma8(acc[mi][ni], af[mi], bf[ni]);
        }
        st ^= 1;
    }
}

// EPI: 0 = bias(->tf32), 1 = bias+res (fp32), 2 = bias+gelu(->tf32)
template <int EPI>
__global__ void __launch_bounds__(128, 3) tc_gemm(
    const float* __restrict__ A, const float* __restrict__ B,
    const float* __restrict__ bias, const float* __restrict__ res,
    float* __restrict__ C, int M, int N, int K)
{
    extern __shared__ float smem[];
    const int t = threadIdx.x;
    const int lane = t & 31, warp = t >> 5;
    const int wm = warp >> 1, wn = warp & 1;
    const int g  = lane >> 2, t4 = lane & 3;
    const int bm = blockIdx.y * 128, bn = blockIdx.x * 128;

    float acc[4][8][4];
    #pragma unroll
    for (int mi = 0; mi < 4; mi++)
        #pragma unroll
        for (int ni = 0; ni < 8; ni++)
            #pragma unroll
            for (int c = 0; c < 4; c++) acc[mi][ni][c] = 0.f;

    gemm_mainloop(A + (size_t)bm * K, B + bn, K, N, smem, acc);

    #pragma unroll
    for (int mi = 0; mi < 4; mi++) {
        #pragma unroll
        for (int half = 0; half < 2; half++) {
            const int row = bm + wm*64 + mi*16 + g + half*8;
            #pragma unroll
            for (int ni = 0; ni < 8; ni++) {
                const int col = bn + wn*64 + ni*8 + t4*2;
                float vx = acc[mi][ni][half*2 + 0] + __ldg(bias + col);
                float vy = acc[mi][ni][half*2 + 1] + __ldg(bias + col + 1);
                if (EPI == 1) {
                    vx += __ldg(res + (size_t)row * N + col);
                    vy += __ldg(res + (size_t)row * N + col + 1);
                } else if (EPI == 2) {
                    vx = 0.5f * vx * (1.f + erff(vx * 0.70710678118654752f));
                    vy = 0.5f * vy * (1.f + erff(vy * 0.70710678118654752f));
                    vx = tfround(vx); vy = tfround(vy);
                } else {
                    vx = tfround(vx); vy = tfround(vy);
                }
                float2 o; o.x = vx; o.y = vy;
                *reinterpret_cast<float2*>(C + (size_t)row * N + col) = o;
            }
        }
    }
}

// fused QKV: direct weights; q/k/v outputs bf16. grid.x = 24 (3 outputs x 8 nb)
__global__ void __launch_bounds__(128, 3) tc_gemm_qkv(
    const float* __restrict__ A,
    const float* __restrict__ wq, const float* __restrict__ wk,
    const float* __restrict__ wv,
    const float* __restrict__ bq, const float* __restrict__ bk,
    const float* __restrict__ bv,
    __nv_bfloat16* __restrict__ q, __nv_bfloat16* __restrict__ k,
    __nv_bfloat16* __restrict__ v, int K)
{
    extern __shared__ float smem[];
    const int t = threadIdx.x;
    const int lane = t & 31, warp = t >> 5;
    const int wm = warp >> 1, wn = warp & 1;
    const int g  = lane >> 2, t4 = lane & 3;
    const int which = blockIdx.x >> 3;
    const int bn = (blockIdx.x & 7) * 128;
    const int bm = blockIdx.y * 128;
    const float* W    = (which == 0) ? wq : (which == 1) ? wk : wv;
    const float* bias = (which == 0) ? bq : (which == 1) ? bk : bv;
    __nv_bfloat16* C  = (which == 0) ? q  : (which == 1) ? k  : v;

    float acc[4][8][4];
    #pragma unroll
    for (int mi = 0; mi < 4; mi++)
        #pragma unroll
        for (int ni = 0; ni < 8; ni++)
            #pragma unroll
            for (int c = 0; c < 4; c++) acc[mi][ni][c] = 0.f;

    gemm_mainloop(A + (size_t)bm * K, W + bn, K, Ec, smem, acc);

    #pragma unroll
    for (int mi = 0; mi < 4; mi++) {
        #pragma unroll
        for (int half = 0; half < 2; half++) {
            const int row = bm + wm*64 + mi*16 + g + half*8;
            #pragma unroll
            for (int ni = 0; ni < 8; ni++) {
                const int col = bn + wn*64 + ni*8 + t4*2;
                float vx = acc[mi][ni][half*2 + 0] + __ldg(bias + col);
                float vy = acc[mi][ni][half*2 + 1] + __ldg(bias + col + 1);
                *reinterpret_cast<unsigned*>(C + (size_t)row * Ec + col) = pack_bf16(vx, vy);
            }
        }
    }
}

// -------- flash attention: all-bf16 mma (QK^T m16n8k16, P.V m16n8k16) ----------
#define QS2 72                      // bf16 units per row (64 + 8 pad)
#define KS2 72
#define VS2 72
#define PS2 136
#define Q_BYTES (128 * QS2 * 2)     // 18432
#define K_BYTES (128 * KS2 * 2)
#define V_BYTES (128 * VS2 * 2)
#define P_BYTES (128 * PS2 * 2)     // 34816
#define ATTN_SMEM (Q_BYTES + 2*K_BYTES + V_BYTES + P_BYTES)   // 108544

__global__ void __launch_bounds__(256) attn_kernel(
    const __nv_bfloat16* __restrict__ q, const __nv_bfloat16* __restrict__ kg,
    const __nv_bfloat16* __restrict__ vg, float* __restrict__ ctx)
{
    extern __shared__ char smc[];
    const uint32_t qb = smem_u32(smc);
    const uint32_t kb = qb + Q_BYTES;
    const uint32_t vb = kb + 2 * K_BYTES;
    const uint32_t pb = vb + V_BYTES;
    unsigned* Pw = reinterpret_cast<unsigned*>(smc + (2 * K_BYTES + Q_BYTES + V_BYTES));

    const int t = threadIdx.x, lane = t & 31, warp = t >> 5;
    const int g = lane >> 2, t4 = lane & 3;
    const int b = blockIdx.y >> 4, h = blockIdx.y & 15;
    const size_t base = (size_t)b * Sc * Ec + (size_t)h * HDc;
    const __nv_bfloat16* qp = q  + base + (size_t)blockIdx.x * 128 * Ec;
    const __nv_bfloat16* kp = kg + base;
    const __nv_bfloat16* vp = vg + base;

    // bf16 fragment lane mappings (verified in R11 PV path)
    const int frow = ((lane >> 3) & 1) * 8 + (lane & 7);   // rows 0..15
    const int fcol = ((lane >> 4) & 1) * 8;                // k halves 0/8
    const int brow = lane & 7;
    const int bkof = ((lane >> 3) & 1) * 8;

    // prologue: Q + K0 (one group)
    #pragma unroll
    for (int i = 0; i < 4; i++) {
        const int idx = t + i*256;
        const int r = idx >> 3, cu = (idx & 7) * 8;
        cp16(qb + (r*QS2 + cu)*2, qp + (size_t)r * Ec + cu);
        cp16(kb + (r*KS2 + cu)*2, kp + (size_t)r * Ec + cu);
    }
    cp_commit();

    float o[8][4];
    #pragma unroll
    for (int ni = 0; ni < 8; ni++)
        #pragma unroll
        for (int c = 0; c < 4; c++) o[ni][c] = 0.f;
    float m0 = -INFINITY, m1 = -INFINITY, l0 = 0.f, l1 = 0.f;
    const int pr0 = warp*16 + g;
    const uint32_t qA = qb + ((warp*16 + frow)*QS2 + fcol)*2;
    const uint32_t pA = pb + ((warp*16 + frow)*PS2 + fcol)*2;
    const uint32_t vBb = vb + (frow*VS2)*2;    // frow doubles as vrow (same formula)

    for (int kt = 0; kt < 16; kt++) {
        __syncthreads();
        // V(kt)
        #pragma unroll
        for (int i = 0; i < 4; i++) {
            const int idx = t + i*256;
            const int r = idx >> 3, cu = (idx & 7) * 8;
            cp16(vb + (r*VS2 + cu)*2, vp + (size_t)(kt*128 + r) * Ec + cu);
        }
        cp_commit();
        // K(kt+1)
        if (kt < 15) {
            const uint32_t kbn = kb + ((kt+1)&1) * K_BYTES;
            #pragma unroll
            for (int i = 0; i < 4; i++) {
                const int idx = t + i*256;
                const int r = idx >> 3, cu = (idx & 7) * 8;
                cp16(kbn + (r*KS2 + cu)*2, kp + (size_t)((kt+1)*128 + r) * Ec + cu);
            }
        }
        cp_commit();
        CP_WAIT(2);
        __syncthreads();

        const uint32_t kB = kb + (kt & 1) * K_BYTES + (brow*KS2 + bkof)*2;

        // S = Q @ K^T (bf16, 4 k16 chunks over d=64)
        float sacc[16][4];
        #pragma unroll
        for (int ni = 0; ni < 16; ni++)
            #pragma unroll
            for (int c = 0; c < 4; c++) sacc[ni][c] = 0.f;
        #pragma unroll
        for (int kk = 0; kk < 4; kk++) {
            unsigned a[4];
            ldmA(a, qA + kk*32);
            #pragma unroll
            for (int ni = 0; ni < 16; ni++) {
                unsigned bbf[2];
                ldmB(bbf, kB + (ni*8*KS2)*2 + kk*32);
                mma16bf(sacc[ni], a, bbf);
            }
        }

        // online softmax; P -> bf16 SMEM
        float rm0 = -INFINITY, rm1 = -INFINITY;
        #pragma unroll
        for (int ni = 0; ni < 16; ni++) {
            sacc[ni][0] *= 0.125f; sacc[ni][1] *= 0.125f;
            sacc[ni][2] *= 0.125f; sacc[ni][3] *= 0.125f;
            rm0 = fmaxf(rm0, fmaxf(sacc[ni][0], sacc[ni][1]));
            rm1 = fmaxf(rm1, fmaxf(sacc[ni][2], sacc[ni][3]));
        }
        rm0 = fmaxf(rm0, __shfl_xor_sync(0xffffffffu, rm0, 1));
        rm0 = fmaxf(rm0, __shfl_xor_sync(0xffffffffu, rm0, 2));
        rm1 = fmaxf(rm1, __shfl_xor_sync(0xffffffffu, rm1, 1));
        rm1 = fmaxf(rm1, __shfl_xor_sync(0xffffffffu, rm1, 2));
        const float mn0 = fmaxf(m0, rm0), mn1 = fmaxf(m1, rm1);
        const float al0 = __expf(m0 - mn0), al1 = __expf(m1 - mn1);
        float ps0 = 0.f, ps1 = 0.f;
        #pragma unroll
        for (int ni = 0; ni < 16; ni++) {
            float p0 = __expf(sacc[ni][0] - mn0);
            float p1 = __expf(sacc[ni][1] - mn0);
            float p2 = __expf(sacc[ni][2] - mn1);
            float p3 = __expf(sacc[ni][3] - mn1);
            ps0 += p0 + p1; ps1 += p2 + p3;
            const int col = ni*8 + t4*2;
            Pw[(pr0     * PS2 + col) >> 1] = pack_bf16(p0, p1);
            Pw[((pr0+8) * PS2 + col) >> 1] = pack_bf16(p2, p3);
        }
        ps0 += __shfl_xor_sync(0xffffffffu, ps0, 1);
        ps0 += __shfl_xor_sync(0xffffffffu, ps0, 2);
        ps1 += __shfl_xor_sync(0xffffffffu, ps1, 1);
        ps1 += __shfl_xor_sync(0xffffffffu, ps1, 2);
        l0 = l0 * al0 + ps0; l1 = l1 * al1 + ps1;
        m0 = mn0; m1 = mn1;
        #pragma unroll
        for (int ni = 0; ni < 8; ni++) {
            o[ni][0] *= al0; o[ni][1] *= al0;
            o[ni][2] *= al1; o[ni][3] *= al1;
        }
        __syncwarp();

        CP_WAIT(1);
        __syncthreads();

        // O += P @ V (bf16, 8 k16 chunks over 128 kv rows)
        #pragma unroll
        for (int kk = 0; kk < 8; kk++) {
            unsigned a[4];
            ldmA(a, pA + kk*32);
            const uint32_t vB = vBb + kk*16*VS2*2;
            #pragma unroll
            for (int ni = 0; ni < 8; ni++) {
                unsigned bbf[2];
                ldmBT(bbf, vB + ni*16);
                mma16bf(o[ni], a, bbf);
            }
        }
    }

    const float inv0 = 1.f / l0, inv1 = 1.f / l1;
    float* cp = ctx + base + (size_t)blockIdx.x * 128 * Ec;
    #pragma unroll
    for (int ni = 0; ni < 8; ni++) {
        const int d = ni*8 + t4*2;
        float2 u0; u0.x = tfround(o[ni][0] * inv0); u0.y = tfround(o[ni][1] * inv0);
        float2 u1; u1.x = tfround(o[ni][2] * inv1); u1.y = tfround(o[ni][3] * inv1);
        *reinterpret_cast<float2*>(cp + (size_t)pr0     * Ec + d) = u0;
        *reinterpret_cast<float2*>(cp + (size_t)(pr0+8) * Ec + d) = u1;
    }
}

// ---------------- launch ----------------
extern "C" void kernel_launch(void* const* d_in, const int* in_sizes, int n_in,
                              void* d_out, int out_size)
{
    const float* x   = (const float*)d_in[0];
    const float* wq  = (const float*)d_in[1];
    const float* bq  = (const float*)d_in[2];
    const float* wk  = (const float*)d_in[3];
    const float* bk  = (const float*)d_in[4];
    const float* wv  = (const float*)d_in[5];
    const float* bv  = (const float*)d_in[6];
    const float* wo  = (const float*)d_in[7];
    const float* bo  = (const float*)d_in[8];
    const float* w1  = (const float*)d_in[9];
    const float* b1  = (const float*)d_in[10];
    const float* w2  = (const float*)d_in[11];
    const float* b2  = (const float*)d_in[12];
    const float* g1  = (const float*)d_in[13];
    const float* be1 = (const float*)d_in[14];
    const float* g2  = (const float*)d_in[15];
    const float* be2 = (const float*)d_in[16];
    float* out = (float*)d_out;

    float *z0, *ctx, *x1, *z1, *h;
    __nv_bfloat16 *q, *k, *v;
    cudaGetSymbolAddress((void**)&z0,  g_z0);
    cudaGetSymbolAddress((void**)&q,   g_q);
    cudaGetSymbolAddress((void**)&k,   g_k);
    cudaGetSymbolAddress((void**)&v,   g_v);
    cudaGetSymbolAddress((void**)&ctx, g_ctx);
    cudaGetSymbolAddress((void**)&x1,  g_x1);
    cudaGetSymbolAddress((void**)&z1,  g_z1);
    cudaGetSymbolAddress((void**)&h,   g_h);

    cudaFuncSetAttribute(attn_kernel,  cudaFuncAttributeMaxDynamicSharedMemorySize, ATTN_SMEM);
    cudaFuncSetAttribute(tc_gemm<0>,   cudaFuncAttributeMaxDynamicSharedMemorySize, SMEM_GEMM);
    cudaFuncSetAttribute(tc_gemm<1>,   cudaFuncAttributeMaxDynamicSharedMemorySize, SMEM_GEMM);
    cudaFuncSetAttribute(tc_gemm<2>,   cudaFuncAttributeMaxDynamicSharedMemorySize, SMEM_GEMM);
    cudaFuncSetAttribute(tc_gemm_qkv,  cudaFuncAttributeMaxDynamicSharedMemorySize, SMEM_GEMM);

    // 1
    ln_kernel<<<TOK, 256>>>(x, g1, be1, z0);
    // 2
    tc_gemm_qkv<<<dim3(24, TOK/128), 128, SMEM_GEMM>>>(z0, wq, wk, wv, bq, bk, bv, q, k, v, Ec);
    // 3
    attn_kernel<<<dim3(Sc/128, Bc*Hc), 256, ATTN_SMEM>>>(q, k, v, ctx);
    // 4
    tc_gemm<1><<<dim3(Ec/128, TOK/128), 128, SMEM_GEMM>>>(ctx, wo, bo, x, x1, TOK, Ec, Ec);
    // 5
    ln_kernel<<<TOK, 256>>>(x1, g2, be2, z1);
    // 6  <- profiled by ncu (-s 5 -c 1): MLP1 GEMM
    tc_gemm<2><<<dim3(MLPc/128, TOK/128), 128, SMEM_GEMM>>>(z1, w1, b1, nullptr, h, TOK, MLPc, Ec);
    // 7
    tc_gemm<1><<<dim3(Ec/128, TOK/128), 128, SMEM_GEMM>>>(h, w2, b2, x1, out, TOK, Ec, MLPc);
}

// round 13
// speedup vs baseline: 1.7570x; 1.4004x over previous
#include <cuda_runtime.h>
#include <cuda_bf16.h>
#include <cstdint>
#include <math.h>

#define Bc   2
#define Sc   2048
#define TOK  4096
#define Ec   1024
#define Hc   16
#define HDc  64
#define MLPc 4096

// ---------------- scratch (no allocations allowed) ----------------
__device__ __nv_bfloat16 g_z0[(size_t)TOK * Ec];
__device__ __nv_bfloat16 g_z1[(size_t)TOK * Ec];
__device__ __nv_bfloat16 g_q[(size_t)TOK * Ec];
__device__ __nv_bfloat16 g_k[(size_t)TOK * Ec];
__device__ __nv_bfloat16 g_v[(size_t)TOK * Ec];
__device__ __nv_bfloat16 g_ctx[(size_t)TOK * Ec];
__device__ __nv_bfloat16 g_h[(size_t)TOK * MLPc];
__device__ float g_x1[(size_t)TOK * Ec];
__device__ __nv_bfloat16 g_wqkvT[(size_t)3 * Ec * Ec];   // [3N][K]
__device__ __nv_bfloat16 g_woT[(size_t)Ec * Ec];         // [N][K]
__device__ __nv_bfloat16 g_w1T[(size_t)MLPc * Ec];       // [N=4096][K=1024]
__device__ __nv_bfloat16 g_w2T[(size_t)Ec * MLPc];       // [N=1024][K=4096]

// ---------------- helpers ----------------
__device__ __forceinline__ unsigned f2tf(float f) {
    unsigned r;
    asm("cvt.rna.tf32.f32 %0, %1;" : "=r"(r) : "f"(f));
    return r;
}
__device__ __forceinline__ float tfround(float f) {
    return __uint_as_float(f2tf(f));
}
__device__ __forceinline__ unsigned pack_bf16(float lo, float hi) {
    unsigned r;
    asm("cvt.rn.bf16x2.f32 %0, %1, %2;" : "=r"(r) : "f"(hi), "f"(lo));
    return r;
}
__device__ __forceinline__ uint32_t smem_u32(const void* p) {
    uint32_t a;
    asm("{ .reg .u64 t; cvta.to.shared.u64 t, %1; cvt.u32.u64 %0, t; }" : "=r"(a) : "l"(p));
    return a;
}
__device__ __forceinline__ void cp16(uint32_t d, const void* s) {
    asm volatile("cp.async.cg.shared.global [%0], [%1], 16;\n" :: "r"(d), "l"(s));
}
__device__ __forceinline__ void cp_commit() {
    asm volatile("cp.async.commit_group;\n" ::: "memory");
}
#define CP_WAIT(n) asm volatile("cp.async.wait_group %0;\n" :: "n"(n) : "memory")

__device__ __forceinline__ void mma16bf(float c[4], const unsigned a[4], const unsigned b[2]) {
    asm volatile(
        "mma.sync.aligned.m16n8k16.row.col.f32.bf16.bf16.f32 "
        "{%0,%1,%2,%3}, {%4,%5,%6,%7}, {%8,%9}, {%0,%1,%2,%3};\n"
        : "+f"(c[0]), "+f"(c[1]), "+f"(c[2]), "+f"(c[3])
        : "r"(a[0]), "r"(a[1]), "r"(a[2]), "r"(a[3]),
          "r"(b[0]), "r"(b[1]));
}
__device__ __forceinline__ void ldmA(unsigned a[4], uint32_t addr) {
    asm volatile("ldmatrix.sync.aligned.m8n8.x4.shared.b16 {%0,%1,%2,%3}, [%4];"
                 : "=r"(a[0]), "=r"(a[1]), "=r"(a[2]), "=r"(a[3]) : "r"(addr));
}
__device__ __forceinline__ void ldmB(unsigned b[2], uint32_t addr) {
    asm volatile("ldmatrix.sync.aligned.m8n8.x2.shared.b16 {%0,%1}, [%2];"
                 : "=r"(b[0]), "=r"(b[1]) : "r"(addr));
}
__device__ __forceinline__ void ldmBT(unsigned b[2], uint32_t addr) {
    asm volatile("ldmatrix.sync.aligned.m8n8.x2.trans.shared.b16 {%0,%1}, [%2];"
                 : "=r"(b[0]), "=r"(b[1]) : "r"(addr));
}

// -------- weight transpose + bf16 convert: out[C][R] = bf16(in[R][C]) --------
__global__ void __launch_bounds__(256) transpose4_bf(
    const float* __restrict__ i0, const float* __restrict__ i1,
    const float* __restrict__ i2, const float* __restrict__ i3,
    __nv_bfloat16* __restrict__ o0, __nv_bfloat16* __restrict__ o1,
    __nv_bfloat16* __restrict__ o2, __nv_bfloat16* __restrict__ o3)
{
    const float* in = (blockIdx.z == 0) ? i0 : (blockIdx.z == 1) ? i1 : (blockIdx.z == 2) ? i2 : i3;
    __nv_bfloat16* out = (blockIdx.z == 0) ? o0 : (blockIdx.z == 1) ? o1 : (blockIdx.z == 2) ? o2 : o3;
    __shared__ float tile[32][33];
    const int bx = blockIdx.x * 32, by = blockIdx.y * 32;
    const int tx = threadIdx.x & 31, ty = threadIdx.x >> 5;
    #pragma unroll
    for (int i = 0; i < 32; i += 8)
        tile[ty + i][tx] = in[(size_t)(by + ty + i) * Ec + bx + tx];
    __syncthreads();
    #pragma unroll
    for (int i = 0; i < 32; i += 8)
        out[(size_t)(bx + ty + i) * Ec + by + tx] = __float2bfloat16(tile[tx][ty + i]);
}

__global__ void __launch_bounds__(256) transpose_bf(
    const float* __restrict__ in, __nv_bfloat16* __restrict__ out, int R, int C)
{
    __shared__ float tile[32][33];
    const int bx = blockIdx.x * 32, by = blockIdx.y * 32;
    const int tx = threadIdx.x & 31, ty = threadIdx.x >> 5;
    #pragma unroll
    for (int i = 0; i < 32; i += 8)
        tile[ty + i][tx] = in[(size_t)(by + ty + i) * C + bx + tx];
    __syncthreads();
    #pragma unroll
    for (int i = 0; i < 32; i += 8)
        out[(size_t)(bx + ty + i) * R + by + tx] = __float2bfloat16(tile[tx][ty + i]);
}

// ---------------- LayerNorm (fp32 exact, bf16 output) ----------------
__global__ void __launch_bounds__(256) ln_kernel(
    const float* __restrict__ x, const float* __restrict__ gam,
    const float* __restrict__ bet, __nv_bfloat16* __restrict__ y)
{
    const int row = blockIdx.x, t = threadIdx.x;
    const float4* xr = reinterpret_cast<const float4*>(x + (size_t)row * Ec);
    float4 v = xr[t];
    float s  = v.x + v.y + v.z + v.w;
    float ss = v.x*v.x + v.y*v.y + v.z*v.z + v.w*v.w;
    #pragma unroll
    for (int o = 16; o; o >>= 1) {
        s  += __shfl_xor_sync(0xffffffffu, s,  o);
        ss += __shfl_xor_sync(0xffffffffu, ss, o);
    }
    __shared__ float rs[8], rss[8];
    if ((t & 31) == 0) { rs[t >> 5] = s; rss[t >> 5] = ss; }
    __syncthreads();
    if (t < 32) {
        float a = (t < 8) ? rs[t]  : 0.f;
        float b = (t < 8) ? rss[t] : 0.f;
        #pragma unroll
        for (int o = 4; o; o >>= 1) {
            a += __shfl_xor_sync(0xffffffffu, a, o);
            b += __shfl_xor_sync(0xffffffffu, b, o);
        }
        if (t == 0) { rs[0] = a; rss[0] = b; }
    }
    __syncthreads();
    const float mu   = rs[0]  * (1.f / Ec);
    const float var  = rss[0] * (1.f / Ec) - mu * mu;
    const float rstd = rsqrtf(var + 1e-5f);
    float4 gv = reinterpret_cast<const float4*>(gam)[t];
    float4 bv = reinterpret_cast<const float4*>(bet)[t];
    uint2 u;
    u.x = pack_bf16((v.x - mu) * rstd * gv.x + bv.x, (v.y - mu) * rstd * gv.y + bv.y);
    u.y = pack_bf16((v.z - mu) * rstd * gv.z + bv.z, (v.w - mu) * rstd * gv.w + bv.w);
    reinterpret_cast<uint2*>(y + (size_t)row * Ec)[t] = u;
}

// ---- BF16 GEMM: A[M,K] bf16 @ BT[N,K]^T bf16; 2-stage, k-tile 64, 3 CTA/SM ----
#define KT2   64
#define SW2   72                         // bf16 units per row (64 + 8 pad) = 36 words
#define STG2  (128 * SW2 * 2)            // bytes per operand stage (18432)
#define NSTG  2
#define SMEM_GEMM (2 * NSTG * STG2)      // 73728 bytes -> 3 CTAs/SM

__device__ __forceinline__ void ldstage_bf(uint32_t ab, uint32_t bb,
    const __nv_bfloat16* __restrict__ Ap, const __nv_bfloat16* __restrict__ Bp,
    int K, int kt)
{
    const int t = threadIdx.x;
    const int k0 = kt * KT2;
    #pragma unroll
    for (int i = 0; i < 8; i++) {
        const int idx = t + i * 128;
        const int r = idx >> 3, cu = (idx & 7) * 8;
        cp16(ab + (r * SW2 + cu) * 2, Ap + (size_t)r * K + k0 + cu);
    }
    #pragma unroll
    for (int i = 0; i < 8; i++) {
        const int idx = t + i * 128;
        const int r = idx >> 3, cu = (idx & 7) * 8;
        cp16(bb + (r * SW2 + cu) * 2, Bp + (size_t)r * K + k0 + cu);
    }
}

__device__ __forceinline__ void gemm_mainloop_bf(
    const __nv_bfloat16* __restrict__ Ap, const __nv_bfloat16* __restrict__ Bp,
    int K, char* smem, float acc[4][8][4])
{
    const int t    = threadIdx.x;
    const int lane = t & 31, warp = t >> 5;
    const int wm = warp >> 1, wn = warp & 1;     // 2x2 warps, warp tile 64x64
    const int NK = K / KT2;

    const uint32_t asb = smem_u32(smem);
    const uint32_t bsb = asb + NSTG * STG2;

    // bf16 ldmatrix lane mappings (numerically verified in R11/R12 attention)
    const int frow = ((lane >> 3) & 1) * 8 + (lane & 7);
    const int fcol = ((lane >> 4) & 1) * 8;
    const int brow = lane & 7;
    const int bkof = ((lane >> 3) & 1) * 8;

    ldstage_bf(asb, bsb, Ap, Bp, K, 0);
    cp_commit();

    int st = 0;
    for (int kt = 0; kt < NK; kt++) {
        CP_WAIT(0);
        __syncthreads();
        if (kt + 1 < NK) {
            const int ps = st ^ 1;
            ldstage_bf(asb + ps * STG2, bsb + ps * STG2, Ap, Bp, K, kt + 1);
        }
        cp_commit();

        const uint32_t aB = asb + st * STG2 + ((wm*64 + frow) * SW2 + fcol) * 2;
        const uint32_t bB = bsb + st * STG2 + ((wn*64 + brow) * SW2 + bkof) * 2;
        #pragma unroll
        for (int kk = 0; kk < 4; kk++) {
            unsigned af[4][4], bf[8][2];
            #pragma unroll
            for (int mi = 0; mi < 4; mi++)
                ldmA(af[mi], aB + mi*16*SW2*2 + kk*32);
            #pragma unroll
            for (int ni = 0; ni < 8; ni++)
                ldmB(bf[ni], bB + ni*8*SW2*2 + kk*32);
            #pragma unroll
            for (int mi = 0; mi < 4; mi++)
                #pragma unroll
                for (int ni = 0; ni < 8; ni++)
                    mma16bf(acc[mi][ni], af[mi], bf[ni]);
        }
        st ^= 1;
    }
}

// fp32 output + residual (O-proj, MLP2)
__global__ void __launch_bounds__(128, 3) tc_gemm_res(
    const __nv_bfloat16* __restrict__ A, const __nv_bfloat16* __restrict__ BT,
    const float* __restrict__ bias, const float* __restrict__ res,
    float* __restrict__ C, int M, int N, int K)
{
    extern __shared__ char smem[];
    const int t = threadIdx.x;
    const int lane = t & 31, warp = t >> 5;
    const int wm = warp >> 1, wn = warp & 1;
    const int g  = lane >> 2, t4 = lane & 3;
    const int bm = blockIdx.y * 128, bn = blockIdx.x * 128;

    float acc[4][8][4];
    #pragma unroll
    for (int mi = 0; mi < 4; mi++)
        #pragma unroll
        for (int ni = 0; ni < 8; ni++)
            #pragma unroll
            for (int c = 0; c < 4; c++) acc[mi][ni][c] = 0.f;

    gemm_mainloop_bf(A + (size_t)bm * K, BT + (size_t)bn * K, K, smem, acc);

    #pragma unroll
    for (int mi = 0; mi < 4; mi++) {
        #pragma unroll
        for (int half = 0; half < 2; half++) {
            const int row = bm + wm*64 + mi*16 + g + half*8;
            #pragma unroll
            for (int ni = 0; ni < 8; ni++) {
                const int col = bn + wn*64 + ni*8 + t4*2;
                float vx = acc[mi][ni][half*2 + 0] + __ldg(bias + col)
                         + __ldg(res + (size_t)row * N + col);
                float vy = acc[mi][ni][half*2 + 1] + __ldg(bias + col + 1)
                         + __ldg(res + (size_t)row * N + col + 1);
                float2 o; o.x = vx; o.y = vy;
                *reinterpret_cast<float2*>(C + (size_t)row * N + col) = o;
            }
        }
    }
}

// gelu epilogue, bf16 output (MLP1)
__global__ void __launch_bounds__(128, 3) tc_gemm_gelu(
    const __nv_bfloat16* __restrict__ A, const __nv_bfloat16* __restrict__ BT,
    const float* __restrict__ bias, __nv_bfloat16* __restrict__ C,
    int M, int N, int K)
{
    extern __shared__ char smem[];
    const int t = threadIdx.x;
    const int lane = t & 31, warp = t >> 5;
    const int wm = warp >> 1, wn = warp & 1;
    const int g  = lane >> 2, t4 = lane & 3;
    const int bm = blockIdx.y * 128, bn = blockIdx.x * 128;

    float acc[4][8][4];
    #pragma unroll
    for (int mi = 0; mi < 4; mi++)
        #pragma unroll
        for (int ni = 0; ni < 8; ni++)
            #pragma unroll
            for (int c = 0; c < 4; c++) acc[mi][ni][c] = 0.f;

    gemm_mainloop_bf(A + (size_t)bm * K, BT + (size_t)bn * K, K, smem, acc);

    #pragma unroll
    for (int mi = 0; mi < 4; mi++) {
        #pragma unroll
        for (int half = 0; half < 2; half++) {
            const int row = bm + wm*64 + mi*16 + g + half*8;
            #pragma unroll
            for (int ni = 0; ni < 8; ni++) {
                const int col = bn + wn*64 + ni*8 + t4*2;
                float vx = acc[mi][ni][half*2 + 0] + __ldg(bias + col);
                float vy = acc[mi][ni][half*2 + 1] + __ldg(bias + col + 1);
                vx = 0.5f * vx * (1.f + erff(vx * 0.70710678118654752f));
                vy = 0.5f * vy * (1.f + erff(vy * 0.70710678118654752f));
                *reinterpret_cast<unsigned*>(C + (size_t)row * N + col) = pack_bf16(vx, vy);
            }
        }
    }
}

// fused QKV: A=z0 bf16, BT=wqkvT bf16 [3N][K]; outputs bf16
__global__ void __launch_bounds__(128, 3) tc_gemm_qkv(
    const __nv_bfloat16* __restrict__ A, const __nv_bfloat16* __restrict__ BT,
    const float* __restrict__ bq, const float* __restrict__ bk,
    const float* __restrict__ bv,
    __nv_bfloat16* __restrict__ q, __nv_bfloat16* __restrict__ k,
    __nv_bfloat16* __restrict__ v, int K)
{
    extern __shared__ char smem[];
    const int t = threadIdx.x;
    const int lane = t & 31, warp = t >> 5;
    const int wm = warp >> 1, wn = warp & 1;
    const int g  = lane >> 2, t4 = lane & 3;
    const int which = blockIdx.x >> 3;
    const int bn = (blockIdx.x & 7) * 128;
    const int bm = blockIdx.y * 128;
    const float* bias = (which == 0) ? bq : (which == 1) ? bk : bv;
    __nv_bfloat16* C  = (which == 0) ? q  : (which == 1) ? k  : v;

    float acc[4][8][4];
    #pragma unroll
    for (int mi = 0; mi < 4; mi++)
        #pragma unroll
        for (int ni = 0; ni < 8; ni++)
            #pragma unroll
            for (int c = 0; c < 4; c++) acc[mi][ni][c] = 0.f;

    gemm_mainloop_bf(A + (size_t)bm * K, BT + (size_t)(which * Ec + bn) * K, K, smem, acc);

    #pragma unroll
    for (int mi = 0; mi < 4; mi++) {
        #pragma unroll
        for (int half = 0; half < 2; half++) {
            const int row = bm + wm*64 + mi*16 + g + half*8;
            #pragma unroll
            for (int ni = 0; ni < 8; ni++) {
                const int col = bn + wn*64 + ni*8 + t4*2;
                float vx = acc[mi][ni][half*2 + 0] + __ldg(bias + col);
                float vy = acc[mi][ni][half*2 + 1] + __ldg(bias + col + 1);
                *reinterpret_cast<unsigned*>(C + (size_t)row * Ec + col) = pack_bf16(vx, vy);
            }
        }
    }
}

// -------- flash attention: all-bf16 mma; ctx output bf16 ----------
#define QS2 72
#define KS2 72
#define VS2 72
#define PS2 136
#define Q_BYTES (128 * QS2 * 2)
#define K_BYTES (128 * KS2 * 2)
#define V_BYTES (128 * VS2 * 2)
#define P_BYTES (128 * PS2 * 2)
#define ATTN_SMEM (Q_BYTES + 2*K_BYTES + V_BYTES + P_BYTES)   // 108544

__global__ void __launch_bounds__(256) attn_kernel(
    const __nv_bfloat16* __restrict__ q, const __nv_bfloat16* __restrict__ kg,
    const __nv_bfloat16* __restrict__ vg, __nv_bfloat16* __restrict__ ctx)
{
    extern __shared__ char smc[];
    const uint32_t qb = smem_u32(smc);
    const uint32_t kb = qb + Q_BYTES;
    const uint32_t vb = kb + 2 * K_BYTES;
    const uint32_t pb = vb + V_BYTES;
    unsigned* Pw = reinterpret_cast<unsigned*>(smc + (Q_BYTES + 2 * K_BYTES + V_BYTES));

    const int t = threadIdx.x, lane = t & 31, warp = t >> 5;
    const int g = lane >> 2, t4 = lane & 3;
    const int b = blockIdx.y >> 4, h = blockIdx.y & 15;
    const size_t base = (size_t)b * Sc * Ec + (size_t)h * HDc;
    const __nv_bfloat16* qp = q  + base + (size_t)blockIdx.x * 128 * Ec;
    const __nv_bfloat16* kp = kg + base;
    const __nv_bfloat16* vp = vg + base;

    const int frow = ((lane >> 3) & 1) * 8 + (lane & 7);
    const int fcol = ((lane >> 4) & 1) * 8;
    const int brow = lane & 7;
    const int bkof = ((lane >> 3) & 1) * 8;

    #pragma unroll
    for (int i = 0; i < 4; i++) {
        const int idx = t + i*256;
        const int r = idx >> 3, cu = (idx & 7) * 8;
        cp16(qb + (r*QS2 + cu)*2, qp + (size_t)r * Ec + cu);
        cp16(kb + (r*KS2 + cu)*2, kp + (size_t)r * Ec + cu);
    }
    cp_commit();

    float o[8][4];
    #pragma unroll
    for (int ni = 0; ni < 8; ni++)
        #pragma unroll
        for (int c = 0; c < 4; c++) o[ni][c] = 0.f;
    float m0 = -INFINITY, m1 = -INFINITY, l0 = 0.f, l1 = 0.f;
    const int pr0 = warp*16 + g;
    const uint32_t qA = qb + ((warp*16 + frow)*QS2 + fcol)*2;
    const uint32_t pA = pb + ((warp*16 + frow)*PS2 + fcol)*2;
    const uint32_t vBb = vb + (frow*VS2)*2;

    for (int kt = 0; kt < 16; kt++) {
        __syncthreads();
        #pragma unroll
        for (int i = 0; i < 4; i++) {
            const int idx = t + i*256;
            const int r = idx >> 3, cu = (idx & 7) * 8;
            cp16(vb + (r*VS2 + cu)*2, vp + (size_t)(kt*128 + r) * Ec + cu);
        }
        cp_commit();
        if (kt < 15) {
            const uint32_t kbn = kb + ((kt+1)&1) * K_BYTES;
            #pragma unroll
            for (int i = 0; i < 4; i++) {
                const int idx = t + i*256;
                const int r = idx >> 3, cu = (idx & 7) * 8;
                cp16(kbn + (r*KS2 + cu)*2, kp + (size_t)((kt+1)*128 + r) * Ec + cu);
            }
        }
        cp_commit();
        CP_WAIT(2);
        __syncthreads();

        const uint32_t kB = kb + (kt & 1) * K_BYTES + (brow*KS2 + bkof)*2;

        float sacc[16][4];
        #pragma unroll
        for (int ni = 0; ni < 16; ni++)
            #pragma unroll
            for (int c = 0; c < 4; c++) sacc[ni][c] = 0.f;
        #pragma unroll
        for (int kk = 0; kk < 4; kk++) {
            unsigned a[4];
            ldmA(a, qA + kk*32);
            #pragma unroll
            for (int ni = 0; ni < 16; ni++) {
                unsigned bbf[2];
                ldmB(bbf, kB + (ni*8*KS2)*2 + kk*32);
                mma16bf(sacc[ni], a, bbf);
            }
        }

        float rm0 = -INFINITY, rm1 = -INFINITY;
        #pragma unroll
        for (int ni = 0; ni < 16; ni++) {
            sacc[ni][0] *= 0.125f; sacc[ni][1] *= 0.125f;
            sacc[ni][2] *= 0.125f; sacc[ni][3] *= 0.125f;
            rm0 = fmaxf(rm0, fmaxf(sacc[ni][0], sacc[ni][1]));
            rm1 = fmaxf(rm1, fmaxf(sacc[ni][2], sacc[ni][3]));
        }
        rm0 = fmaxf(rm0, __shfl_xor_sync(0xffffffffu, rm0, 1));
        rm0 = fmaxf(rm0, __shfl_xor_sync(0xffffffffu, rm0, 2));
        rm1 = fmaxf(rm1, __shfl_xor_sync(0xffffffffu, rm1, 1));
        rm1 = fmaxf(rm1, __shfl_xor_sync(0xffffffffu, rm1, 2));
        const float mn0 = fmaxf(m0, rm0), mn1 = fmaxf(m1, rm1);
        const float al0 = __expf(m0 - mn0), al1 = __expf(m1 - mn1);
        float ps0 = 0.f, ps1 = 0.f;
        #pragma unroll
        for (int ni = 0; ni < 16; ni++) {
            float p0 = __expf(sacc[ni][0] - mn0);
            float p1 = __expf(sacc[ni][1] - mn0);
            float p2 = __expf(sacc[ni][2] - mn1);
            float p3 = __expf(sacc[ni][3] - mn1);
            ps0 += p0 + p1; ps1 += p2 + p3;
            const int col = ni*8 + t4*2;
            Pw[(pr0     * PS2 + col) >> 1] = pack_bf16(p0, p1);
            Pw[((pr0+8) * PS2 + col) >> 1] = pack_bf16(p2, p3);
        }
        ps0 += __shfl_xor_sync(0xffffffffu, ps0, 1);
        ps0 += __shfl_xor_sync(0xffffffffu, ps0, 2);
        ps1 += __shfl_xor_sync(0xffffffffu, ps1, 1);
        ps1 += __shfl_xor_sync(0xffffffffu, ps1, 2);
        l0 = l0 * al0 + ps0; l1 = l1 * al1 + ps1;
        m0 = mn0; m1 = mn1;
        #pragma unroll
        for (int ni = 0; ni < 8; ni++) {
            o[ni][0] *= al0; o[ni][1] *= al0;
            o[ni][2] *= al1; o[ni][3] *= al1;
        }
        __syncwarp();

        CP_WAIT(1);
        __syncthreads();

        #pragma unroll
        for (int kk = 0; kk < 8; kk++) {
            unsigned a[4];
            ldmA(a, pA + kk*32);
            const uint32_t vB = vBb + kk*16*VS2*2;
            #pragma unroll
            for (int ni = 0; ni < 8; ni++) {
                unsigned bbf[2];
                ldmBT(bbf, vB + ni*16);
                mma16bf(o[ni], a, bbf);
            }
        }
    }

    const float inv0 = 1.f / l0, inv1 = 1.f / l1;
    __nv_bfloat16* cp = ctx + base + (size_t)blockIdx.x * 128 * Ec;
    #pragma unroll
    for (int ni = 0; ni < 8; ni++) {
        const int d = ni*8 + t4*2;
        *reinterpret_cast<unsigned*>(cp + (size_t)pr0     * Ec + d) =
            pack_bf16(o[ni][0] * inv0, o[ni][1] * inv0);
        *reinterpret_cast<unsigned*>(cp + (size_t)(pr0+8) * Ec + d) =
            pack_bf16(o[ni][2] * inv1, o[ni][3] * inv1);
    }
}

// ---------------- launch ----------------
extern "C" void kernel_launch(void* const* d_in, const int* in_sizes, int n_in,
                              void* d_out, int out_size)
{
    const float* x   = (const float*)d_in[0];
    const float* wq  = (const float*)d_in[1];
    const float* bq  = (const float*)d_in[2];
    const float* wk  = (const float*)d_in[3];
    const float* bk  = (const float*)d_in[4];
    const float* wv  = (const float*)d_in[5];
    const float* bv  = (const float*)d_in[6];
    const float* wo  = (const float*)d_in[7];
    const float* bo  = (const float*)d_in[8];
    const float* w1  = (const float*)d_in[9];
    const float* b1  = (const float*)d_in[10];
    const float* w2  = (const float*)d_in[11];
    const float* b2  = (const float*)d_in[12];
    const float* g1  = (const float*)d_in[13];
    const float* be1 = (const float*)d_in[14];
    const float* g2  = (const float*)d_in[15];
    const float* be2 = (const float*)d_in[16];
    float* out = (float*)d_out;

    __nv_bfloat16 *z0, *z1, *q, *k, *v, *ctx, *h, *wqkvT, *woT, *w1T, *w2T;
    float* x1;
    cudaGetSymbolAddress((void**)&z0,  g_z0);
    cudaGetSymbolAddress((void**)&z1,  g_z1);
    cudaGetSymbolAddress((void**)&q,   g_q);
    cudaGetSymbolAddress((void**)&k,   g_k);
    cudaGetSymbolAddress((void**)&v,   g_v);
    cudaGetSymbolAddress((void**)&ctx, g_ctx);
    cudaGetSymbolAddress((void**)&h,   g_h);
    cudaGetSymbolAddress((void**)&x1,  g_x1);
    cudaGetSymbolAddress((void**)&wqkvT, g_wqkvT);
    cudaGetSymbolAddress((void**)&woT, g_woT);
    cudaGetSymbolAddress((void**)&w1T, g_w1T);
    cudaGetSymbolAddress((void**)&w2T, g_w2T);

    cudaFuncSetAttribute(attn_kernel,   cudaFuncAttributeMaxDynamicSharedMemorySize, ATTN_SMEM);
    cudaFuncSetAttribute(tc_gemm_res,   cudaFuncAttributeMaxDynamicSharedMemorySize, SMEM_GEMM);
    cudaFuncSetAttribute(tc_gemm_gelu,  cudaFuncAttributeMaxDynamicSharedMemorySize, SMEM_GEMM);
    cudaFuncSetAttribute(tc_gemm_qkv,   cudaFuncAttributeMaxDynamicSharedMemorySize, SMEM_GEMM);

    // 1
    ln_kernel<<<TOK, 256>>>(x, g1, be1, z0);
    // 2: wq,wk,wv -> wqkvT slices, wo -> woT (transpose + bf16)
    transpose4_bf<<<dim3(32, 32, 4), 256>>>(
        wq, wk, wv, wo,
        wqkvT, wqkvT + (size_t)Ec*Ec, wqkvT + (size_t)2*Ec*Ec, woT);
    // 3: w1 [1024][4096] -> w1T [4096][1024]
    transpose_bf<<<dim3(MLPc/32, Ec/32), 256>>>(w1, w1T, Ec, MLPc);
    // 4: w2 [4096][1024] -> w2T [1024][4096]
    transpose_bf<<<dim3(Ec/32, MLPc/32), 256>>>(w2, w2T, MLPc, Ec);
    // 5
    tc_gemm_qkv<<<dim3(24, TOK/128), 128, SMEM_GEMM>>>(z0, wqkvT, bq, bk, bv, q, k, v, Ec);
    // 6  <- profiled by ncu (-s 5 -c 1): attention
    attn_kernel<<<dim3(Sc/128, Bc*Hc), 256, ATTN_SMEM>>>(q, k, v, ctx);
    // 7
    tc_gemm_res<<<dim3(Ec/128, TOK/128), 128, SMEM_GEMM>>>(ctx, woT, bo, x, x1, TOK, Ec, Ec);
    // 8
    ln_kernel<<<TOK, 256>>>(x1, g2, be2, z1);
    // 9
    tc_gemm_gelu<<<dim3(MLPc/128, TOK/128), 128, SMEM_GEMM>>>(z1, w1T, b1, h, TOK, MLPc, Ec);
    // 10
    tc_gemm_res<<<dim3(Ec/128, TOK/128), 128, SMEM_GEMM>>>(h, w2T, b2, x1, out, TOK, Ec, MLPc);
}

// round 14
// speedup vs baseline: 1.7859x; 1.0164x over previous
#include <cuda_runtime.h>
#include <cuda_bf16.h>
#include <cstdint>
#include <math.h>

#define Bc   2
#define Sc   2048
#define TOK  4096
#define Ec   1024
#define Hc   16
#define HDc  64
#define MLPc 4096

// ---------------- scratch (no allocations allowed) ----------------
__device__ __nv_bfloat16 g_z0[(size_t)TOK * Ec];
__device__ __nv_bfloat16 g_z1[(size_t)TOK * Ec];
__device__ __nv_bfloat16 g_q[(size_t)TOK * Ec];
__device__ __nv_bfloat16 g_k[(size_t)TOK * Ec];
__device__ __nv_bfloat16 g_v[(size_t)TOK * Ec];
__device__ __nv_bfloat16 g_ctx[(size_t)TOK * Ec];
__device__ __nv_bfloat16 g_h[(size_t)TOK * MLPc];
__device__ float g_x1[(size_t)TOK * Ec];
__device__ __nv_bfloat16 g_wqkvT[(size_t)3 * Ec * Ec];   // [3N][K]
__device__ __nv_bfloat16 g_woT[(size_t)Ec * Ec];         // [N][K]
__device__ __nv_bfloat16 g_w1T[(size_t)MLPc * Ec];       // [4096][1024]
__device__ __nv_bfloat16 g_w2T[(size_t)Ec * MLPc];       // [1024][4096]

// ---------------- helpers ----------------
__device__ __forceinline__ unsigned pack_bf16(float lo, float hi) {
    unsigned r;
    asm("cvt.rn.bf16x2.f32 %0, %1, %2;" : "=r"(r) : "f"(hi), "f"(lo));
    return r;
}
__device__ __forceinline__ uint32_t smem_u32(const void* p) {
    uint32_t a;
    asm("{ .reg .u64 t; cvta.to.shared.u64 t, %1; cvt.u32.u64 %0, t; }" : "=r"(a) : "l"(p));
    return a;
}
__device__ __forceinline__ void cp16(uint32_t d, const void* s) {
    asm volatile("cp.async.cg.shared.global [%0], [%1], 16;\n" :: "r"(d), "l"(s));
}
__device__ __forceinline__ void cp_commit() {
    asm volatile("cp.async.commit_group;\n" ::: "memory");
}
#define CP_WAIT(n) asm volatile("cp.async.wait_group %0;\n" :: "n"(n) : "memory")

__device__ __forceinline__ void mma16bf(float c[4], const unsigned a[4], const unsigned b[2]) {
    asm volatile(
        "mma.sync.aligned.m16n8k16.row.col.f32.bf16.bf16.f32 "
        "{%0,%1,%2,%3}, {%4,%5,%6,%7}, {%8,%9}, {%0,%1,%2,%3};\n"
        : "+f"(c[0]), "+f"(c[1]), "+f"(c[2]), "+f"(c[3])
        : "r"(a[0]), "r"(a[1]), "r"(a[2]), "r"(a[3]),
          "r"(b[0]), "r"(b[1]));
}
__device__ __forceinline__ void ldmA(unsigned a[4], uint32_t addr) {
    asm volatile("ldmatrix.sync.aligned.m8n8.x4.shared.b16 {%0,%1,%2,%3}, [%4];"
                 : "=r"(a[0]), "=r"(a[1]), "=r"(a[2]), "=r"(a[3]) : "r"(addr));
}
__device__ __forceinline__ void ldmB(unsigned b[2], uint32_t addr) {
    asm volatile("ldmatrix.sync.aligned.m8n8.x2.shared.b16 {%0,%1}, [%2];"
                 : "=r"(b[0]), "=r"(b[1]) : "r"(addr));
}
__device__ __forceinline__ void ldmBT(unsigned b[2], uint32_t addr) {
    asm volatile("ldmatrix.sync.aligned.m8n8.x2.trans.shared.b16 {%0,%1}, [%2];"
                 : "=r"(b[0]), "=r"(b[1]) : "r"(addr));
}

// -------- weight transpose + bf16 convert: out[C][R] = bf16(in[R][C]) --------
__global__ void __launch_bounds__(256) transpose4_bf(
    const float* __restrict__ i0, const float* __restrict__ i1,
    const float* __restrict__ i2, const float* __restrict__ i3,
    __nv_bfloat16* __restrict__ o0, __nv_bfloat16* __restrict__ o1,
    __nv_bfloat16* __restrict__ o2, __nv_bfloat16* __restrict__ o3)
{
    const float* in = (blockIdx.z == 0) ? i0 : (blockIdx.z == 1) ? i1 : (blockIdx.z == 2) ? i2 : i3;
    __nv_bfloat16* out = (blockIdx.z == 0) ? o0 : (blockIdx.z == 1) ? o1 : (blockIdx.z == 2) ? o2 : o3;
    __shared__ float tile[32][33];
    const int bx = blockIdx.x * 32, by = blockIdx.y * 32;
    const int tx = threadIdx.x & 31, ty = threadIdx.x >> 5;
    #pragma unroll
    for (int i = 0; i < 32; i += 8)
        tile[ty + i][tx] = in[(size_t)(by + ty + i) * Ec + bx + tx];
    __syncthreads();
    #pragma unroll
    for (int i = 0; i < 32; i += 8)
        out[(size_t)(bx + ty + i) * Ec + by + tx] = __float2bfloat16(tile[tx][ty + i]);
}

__global__ void __launch_bounds__(256) transpose_bf(
    const float* __restrict__ in, __nv_bfloat16* __restrict__ out, int R, int C)
{
    __shared__ float tile[32][33];
    const int bx = blockIdx.x * 32, by = blockIdx.y * 32;
    const int tx = threadIdx.x & 31, ty = threadIdx.x >> 5;
    #pragma unroll
    for (int i = 0; i < 32; i += 8)
        tile[ty + i][tx] = in[(size_t)(by + ty + i) * C + bx + tx];
    __syncthreads();
    #pragma unroll
    for (int i = 0; i < 32; i += 8)
        out[(size_t)(bx + ty + i) * R + by + tx] = __float2bfloat16(tile[tx][ty + i]);
}

// ---------------- LayerNorm (fp32 exact, bf16 output) ----------------
__global__ void __launch_bounds__(256) ln_kernel(
    const float* __restrict__ x, const float* __restrict__ gam,
    const float* __restrict__ bet, __nv_bfloat16* __restrict__ y)
{
    const int row = blockIdx.x, t = threadIdx.x;
    const float4* xr = reinterpret_cast<const float4*>(x + (size_t)row * Ec);
    float4 v = xr[t];
    float s  = v.x + v.y + v.z + v.w;
    float ss = v.x*v.x + v.y*v.y + v.z*v.z + v.w*v.w;
    #pragma unroll
    for (int o = 16; o; o >>= 1) {
        s  += __shfl_xor_sync(0xffffffffu, s,  o);
        ss += __shfl_xor_sync(0xffffffffu, ss, o);
    }
    __shared__ float rs[8], rss[8];
    if ((t & 31) == 0) { rs[t >> 5] = s; rss[t >> 5] = ss; }
    __syncthreads();
    if (t < 32) {
        float a = (t < 8) ? rs[t]  : 0.f;
        float b = (t < 8) ? rss[t] : 0.f;
        #pragma unroll
        for (int o = 4; o; o >>= 1) {
            a += __shfl_xor_sync(0xffffffffu, a, o);
            b += __shfl_xor_sync(0xffffffffu, b, o);
        }
        if (t == 0) { rs[0] = a; rss[0] = b; }
    }
    __syncthreads();
    const float mu   = rs[0]  * (1.f / Ec);
    const float var  = rss[0] * (1.f / Ec) - mu * mu;
    const float rstd = rsqrtf(var + 1e-5f);
    float4 gv = reinterpret_cast<const float4*>(gam)[t];
    float4 bv = reinterpret_cast<const float4*>(bet)[t];
    uint2 u;
    u.x = pack_bf16((v.x - mu) * rstd * gv.x + bv.x, (v.y - mu) * rstd * gv.y + bv.y);
    u.y = pack_bf16((v.z - mu) * rstd * gv.z + bv.z, (v.w - mu) * rstd * gv.w + bv.w);
    reinterpret_cast<uint2*>(y + (size_t)row * Ec)[t] = u;
}

// ---- BF16 GEMM core (M128 tile): 2-stage, k-tile 64, 3 CTA/SM ----
#define KT2   64
#define SW2   72
#define STG2  (128 * SW2 * 2)
#define NSTG  2
#define SMEM_GEMM (2 * NSTG * STG2)      // 73728 -> 3 CTAs/SM

__device__ __forceinline__ void ldstage_bf(uint32_t ab, uint32_t bb,
    const __nv_bfloat16* __restrict__ Ap, const __nv_bfloat16* __restrict__ Bp,
    int K, int kt)
{
    const int t = threadIdx.x;
    const int k0 = kt * KT2;
    #pragma unroll
    for (int i = 0; i < 8; i++) {
        const int idx = t + i * 128;
        const int r = idx >> 3, cu = (idx & 7) * 8;
        cp16(ab + (r * SW2 + cu) * 2, Ap + (size_t)r * K + k0 + cu);
    }
    #pragma unroll
    for (int i = 0; i < 8; i++) {
        const int idx = t + i * 128;
        const int r = idx >> 3, cu = (idx & 7) * 8;
        cp16(bb + (r * SW2 + cu) * 2, Bp + (size_t)r * K + k0 + cu);
    }
}

__device__ __forceinline__ void gemm_mainloop_bf(
    const __nv_bfloat16* __restrict__ Ap, const __nv_bfloat16* __restrict__ Bp,
    int K, char* smem, float acc[4][8][4])
{
    const int t    = threadIdx.x;
    const int lane = t & 31, warp = t >> 5;
    const int wm = warp >> 1, wn = warp & 1;
    const int NK = K / KT2;

    const uint32_t asb = smem_u32(smem);
    const uint32_t bsb = asb + NSTG * STG2;

    const int frow = ((lane >> 3) & 1) * 8 + (lane & 7);
    const int fcol = ((lane >> 4) & 1) * 8;
    const int brow = lane & 7;
    const int bkof = ((lane >> 3) & 1) * 8;

    ldstage_bf(asb, bsb, Ap, Bp, K, 0);
    cp_commit();

    int st = 0;
    for (int kt = 0; kt < NK; kt++) {
        CP_WAIT(0);
        __syncthreads();
        if (kt + 1 < NK) {
            const int ps = st ^ 1;
            ldstage_bf(asb + ps * STG2, bsb + ps * STG2, Ap, Bp, K, kt + 1);
        }
        cp_commit();

        const uint32_t aB = asb + st * STG2 + ((wm*64 + frow) * SW2 + fcol) * 2;
        const uint32_t bB = bsb + st * STG2 + ((wn*64 + brow) * SW2 + bkof) * 2;
        #pragma unroll
        for (int kk = 0; kk < 4; kk++) {
            unsigned af[4][4], bf[8][2];
            #pragma unroll
            for (int mi = 0; mi < 4; mi++)
                ldmA(af[mi], aB + mi*16*SW2*2 + kk*32);
            #pragma unroll
            for (int ni = 0; ni < 8; ni++)
                ldmB(bf[ni], bB + ni*8*SW2*2 + kk*32);
            #pragma unroll
            for (int mi = 0; mi < 4; mi++)
                #pragma unroll
                for (int ni = 0; ni < 8; ni++)
                    mma16bf(acc[mi][ni], af[mi], bf[ni]);
        }
        st ^= 1;
    }
}

// ---- BF16 GEMM core (M64 tile): for grid-starved N=1024 GEMMs; 4 CTA/SM ----
#define ASTG64 (64 * SW2 * 2)            // 9216 B
#define SMEM_GEMM64 (NSTG * (ASTG64 + STG2))   // 55296 -> 4 CTAs/SM

__device__ __forceinline__ void ldstage_bf64(uint32_t ab, uint32_t bb,
    const __nv_bfloat16* __restrict__ Ap, const __nv_bfloat16* __restrict__ Bp,
    int K, int kt)
{
    const int t = threadIdx.x;
    const int k0 = kt * KT2;
    #pragma unroll
    for (int i = 0; i < 4; i++) {
        const int idx = t + i * 128;
        const int r = idx >> 3, cu = (idx & 7) * 8;
        cp16(ab + (r * SW2 + cu) * 2, Ap + (size_t)r * K + k0 + cu);
    }
    #pragma unroll
    for (int i = 0; i < 8; i++) {
        const int idx = t + i * 128;
        const int r = idx >> 3, cu = (idx & 7) * 8;
        cp16(bb + (r * SW2 + cu) * 2, Bp + (size_t)r * K + k0 + cu);
    }
}

// M=64, N=128 tile; warp tile 32x64; fp32 out + residual
__global__ void __launch_bounds__(128, 4) tc_gemm_res64(
    const __nv_bfloat16* __restrict__ A, const __nv_bfloat16* __restrict__ BT,
    const float* __restrict__ bias, const float* __restrict__ res,
    float* __restrict__ C, int M, int N, int K)
{
    extern __shared__ char smem[];
    const int t = threadIdx.x;
    const int lane = t & 31, warp = t >> 5;
    const int wm = warp >> 1, wn = warp & 1;
    const int g  = lane >> 2, t4 = lane & 3;
    const int bm = blockIdx.y * 64, bn = blockIdx.x * 128;
    const int NK = K / KT2;

    const uint32_t asb = smem_u32(smem);
    const uint32_t bsb = asb + NSTG * ASTG64;

    const int frow = ((lane >> 3) & 1) * 8 + (lane & 7);
    const int fcol = ((lane >> 4) & 1) * 8;
    const int brow = lane & 7;
    const int bkof = ((lane >> 3) & 1) * 8;

    float acc[2][8][4];
    #pragma unroll
    for (int mi = 0; mi < 2; mi++)
        #pragma unroll
        for (int ni = 0; ni < 8; ni++)
            #pragma unroll
            for (int c = 0; c < 4; c++) acc[mi][ni][c] = 0.f;

    const __nv_bfloat16* Ap = A + (size_t)bm * K;
    const __nv_bfloat16* Bp = BT + (size_t)bn * K;

    ldstage_bf64(asb, bsb, Ap, Bp, K, 0);
    cp_commit();

    int st = 0;
    for (int kt = 0; kt < NK; kt++) {
        CP_WAIT(0);
        __syncthreads();
        if (kt + 1 < NK) {
            const int ps = st ^ 1;
            ldstage_bf64(asb + ps * ASTG64, bsb + ps * STG2, Ap, Bp, K, kt + 1);
        }
        cp_commit();

        const uint32_t aB = asb + st * ASTG64 + ((wm*32 + frow) * SW2 + fcol) * 2;
        const uint32_t bB = bsb + st * STG2   + ((wn*64 + brow) * SW2 + bkof) * 2;
        #pragma unroll
        for (int kk = 0; kk < 4; kk++) {
            unsigned af[2][4], bf[8][2];
            #pragma unroll
            for (int mi = 0; mi < 2; mi++)
                ldmA(af[mi], aB + mi*16*SW2*2 + kk*32);
            #pragma unroll
            for (int ni = 0; ni < 8; ni++)
                ldmB(bf[ni], bB + ni*8*SW2*2 + kk*32);
            #pragma unroll
            for (int mi = 0; mi < 2; mi++)
                #pragma unroll
                for (int ni = 0; ni < 8; ni++)
                    mma16bf(acc[mi][ni], af[mi], bf[ni]);
        }
        st ^= 1;
    }

    #pragma unroll
    for (int mi = 0; mi < 2; mi++) {
        #pragma unroll
        for (int half = 0; half < 2; half++) {
            const int row = bm + wm*32 + mi*16 + g + half*8;
            #pragma unroll
            for (int ni = 0; ni < 8; ni++) {
                const int col = bn + wn*64 + ni*8 + t4*2;
                float vx = acc[mi][ni][half*2 + 0] + __ldg(bias + col)
                         + __ldg(res + (size_t)row * N + col);
                float vy = acc[mi][ni][half*2 + 1] + __ldg(bias + col + 1)
                         + __ldg(res + (size_t)row * N + col + 1);
                float2 o; o.x = vx; o.y = vy;
                *reinterpret_cast<float2*>(C + (size_t)row * N + col) = o;
            }
        }
    }
}

// gelu epilogue, bf16 output (MLP1, M128 tile)
__global__ void __launch_bounds__(128, 3) tc_gemm_gelu(
    const __nv_bfloat16* __restrict__ A, const __nv_bfloat16* __restrict__ BT,
    const float* __restrict__ bias, __nv_bfloat16* __restrict__ C,
    int M, int N, int K)
{
    extern __shared__ char smem[];
    const int t = threadIdx.x;
    const int lane = t & 31, warp = t >> 5;
    const int wm = warp >> 1, wn = warp & 1;
    const int g  = lane >> 2, t4 = lane & 3;
    const int bm = blockIdx.y * 128, bn = blockIdx.x * 128;

    float acc[4][8][4];
    #pragma unroll
    for (int mi = 0; mi < 4; mi++)
        #pragma unroll
        for (int ni = 0; ni < 8; ni++)
            #pragma unroll
            for (int c = 0; c < 4; c++) acc[mi][ni][c] = 0.f;

    gemm_mainloop_bf(A + (size_t)bm * K, BT + (size_t)bn * K, K, smem, acc);

    #pragma unroll
    for (int mi = 0; mi < 4; mi++) {
        #pragma unroll
        for (int half = 0; half < 2; half++) {
            const int row = bm + wm*64 + mi*16 + g + half*8;
            #pragma unroll
            for (int ni = 0; ni < 8; ni++) {
                const int col = bn + wn*64 + ni*8 + t4*2;
                float vx = acc[mi][ni][half*2 + 0] + __ldg(bias + col);
                float vy = acc[mi][ni][half*2 + 1] + __ldg(bias + col + 1);
                vx = 0.5f * vx * (1.f + erff(vx * 0.70710678118654752f));
                vy = 0.5f * vy * (1.f + erff(vy * 0.70710678118654752f));
                *reinterpret_cast<unsigned*>(C + (size_t)row * N + col) = pack_bf16(vx, vy);
            }
        }
    }
}

// fused QKV (M128 tile): A=z0 bf16, BT=wqkvT [3N][K]; outputs bf16
__global__ void __launch_bounds__(128, 3) tc_gemm_qkv(
    const __nv_bfloat16* __restrict__ A, const __nv_bfloat16* __restrict__ BT,
    const float* __restrict__ bq, const float* __restrict__ bk,
    const float* __restrict__ bv,
    __nv_bfloat16* __restrict__ q, __nv_bfloat16* __restrict__ k,
    __nv_bfloat16* __restrict__ v, int K)
{
    extern __shared__ char smem[];
    const int t = threadIdx.x;
    const int lane = t & 31, warp = t >> 5;
    const int wm = warp >> 1, wn = warp & 1;
    const int g  = lane >> 2, t4 = lane & 3;
    const int which = blockIdx.x >> 3;
    const int bn = (blockIdx.x & 7) * 128;
    const int bm = blockIdx.y * 128;
    const float* bias = (which == 0) ? bq : (which == 1) ? bk : bv;
    __nv_bfloat16* C  = (which == 0) ? q  : (which == 1) ? k  : v;

    float acc[4][8][4];
    #pragma unroll
    for (int mi = 0; mi < 4; mi++)
        #pragma unroll
        for (int ni = 0; ni < 8; ni++)
            #pragma unroll
            for (int c = 0; c < 4; c++) acc[mi][ni][c] = 0.f;

    gemm_mainloop_bf(A + (size_t)bm * K, BT + (size_t)(which * Ec + bn) * K, K, smem, acc);

    #pragma unroll
    for (int mi = 0; mi < 4; mi++) {
        #pragma unroll
        for (int half = 0; half < 2; half++) {
            const int row = bm + wm*64 + mi*16 + g + half*8;
            #pragma unroll
            for (int ni = 0; ni < 8; ni++) {
                const int col = bn + wn*64 + ni*8 + t4*2;
                float vx = acc[mi][ni][half*2 + 0] + __ldg(bias + col);
                float vy = acc[mi][ni][half*2 + 1] + __ldg(bias + col + 1);
                *reinterpret_cast<unsigned*>(C + (size_t)row * Ec + col) = pack_bf16(vx, vy);
            }
        }
    }
}

// -------- flash attention: all-bf16 mma; ctx output bf16 ----------
#define QS2 72
#define KS2 72
#define VS2 72
#define PS2 136
#define Q_BYTES (128 * QS2 * 2)
#define K_BYTES (128 * KS2 * 2)
#define V_BYTES (128 * VS2 * 2)
#define P_BYTES (128 * PS2 * 2)
#define ATTN_SMEM (Q_BYTES + 2*K_BYTES + V_BYTES + P_BYTES)   // 108544

__global__ void __launch_bounds__(256) attn_kernel(
    const __nv_bfloat16* __restrict__ q, const __nv_bfloat16* __restrict__ kg,
    const __nv_bfloat16* __restrict__ vg, __nv_bfloat16* __restrict__ ctx)
{
    extern __shared__ char smc[];
    const uint32_t qb = smem_u32(smc);
    const uint32_t kb = qb + Q_BYTES;
    const uint32_t vb = kb + 2 * K_BYTES;
    const uint32_t pb = vb + V_BYTES;
    unsigned* Pw = reinterpret_cast<unsigned*>(smc + (Q_BYTES + 2 * K_BYTES + V_BYTES));

    const int t = threadIdx.x, lane = t & 31, warp = t >> 5;
    const int g = lane >> 2, t4 = lane & 3;
    const int b = blockIdx.y >> 4, h = blockIdx.y & 15;
    const size_t base = (size_t)b * Sc * Ec + (size_t)h * HDc;
    const __nv_bfloat16* qp = q  + base + (size_t)blockIdx.x * 128 * Ec;
    const __nv_bfloat16* kp = kg + base;
    const __nv_bfloat16* vp = vg + base;

    const int frow = ((lane >> 3) & 1) * 8 + (lane & 7);
    const int fcol = ((lane >> 4) & 1) * 8;
    const int brow = lane & 7;
    const int bkof = ((lane >> 3) & 1) * 8;

    #pragma unroll
    for (int i = 0; i < 4; i++) {
        const int idx = t + i*256;
        const int r = idx >> 3, cu = (idx & 7) * 8;
        cp16(qb + (r*QS2 + cu)*2, qp + (size_t)r * Ec + cu);
        cp16(kb + (r*KS2 + cu)*2, kp + (size_t)r * Ec + cu);
    }
    cp_commit();

    float o[8][4];
    #pragma unroll
    for (int ni = 0; ni < 8; ni++)
        #pragma unroll
        for (int c = 0; c < 4; c++) o[ni][c] = 0.f;
    float m0 = -INFINITY, m1 = -INFINITY, l0 = 0.f, l1 = 0.f;
    const int pr0 = warp*16 + g;
    const uint32_t qA = qb + ((warp*16 + frow)*QS2 + fcol)*2;
    const uint32_t pA = pb + ((warp*16 + frow)*PS2 + fcol)*2;
    const uint32_t vBb = vb + (frow*VS2)*2;

    for (int kt = 0; kt < 16; kt++) {
        __syncthreads();
        #pragma unroll
        for (int i = 0; i < 4; i++) {
            const int idx = t + i*256;
            const int r = idx >> 3, cu = (idx & 7) * 8;
            cp16(vb + (r*VS2 + cu)*2, vp + (size_t)(kt*128 + r) * Ec + cu);
        }
        cp_commit();
        if (kt < 15) {
            const uint32_t kbn = kb + ((kt+1)&1) * K_BYTES;
            #pragma unroll
            for (int i = 0; i < 4; i++) {
                const int idx = t + i*256;
                const int r = idx >> 3, cu = (idx & 7) * 8;
                cp16(kbn + (r*KS2 + cu)*2, kp + (size_t)((kt+1)*128 + r) * Ec + cu);
            }
        }
        cp_commit();
        CP_WAIT(2);
        __syncthreads();

        const uint32_t kB = kb + (kt & 1) * K_BYTES + (brow*KS2 + bkof)*2;

        float sacc[16][4];
        #pragma unroll
        for (int ni = 0; ni < 16; ni++)
            #pragma unroll
            for (int c = 0; c < 4; c++) sacc[ni][c] = 0.f;
        #pragma unroll
        for (int kk = 0; kk < 4; kk++) {
            unsigned a[4];
            ldmA(a, qA + kk*32);
            #pragma unroll
            for (int ni = 0; ni < 16; ni++) {
                unsigned bbf[2];
                ldmB(bbf, kB + (ni*8*KS2)*2 + kk*32);
                mma16bf(sacc[ni], a, bbf);
            }
        }

        float rm0 = -INFINITY, rm1 = -INFINITY;
        #pragma unroll
        for (int ni = 0; ni < 16; ni++) {
            sacc[ni][0] *= 0.125f; sacc[ni][1] *= 0.125f;
            sacc[ni][2] *= 0.125f; sacc[ni][3] *= 0.125f;
            rm0 = fmaxf(rm0, fmaxf(sacc[ni][0], sacc[ni][1]));
            rm1 = fmaxf(rm1, fmaxf(sacc[ni][2], sacc[ni][3]));
        }
        rm0 = fmaxf(rm0, __shfl_xor_sync(0xffffffffu, rm0, 1));
        rm0 = fmaxf(rm0, __shfl_xor_sync(0xffffffffu, rm0, 2));
        rm1 = fmaxf(rm1, __shfl_xor_sync(0xffffffffu, rm1, 1));
        rm1 = fmaxf(rm1, __shfl_xor_sync(0xffffffffu, rm1, 2));
        const float mn0 = fmaxf(m0, rm0), mn1 = fmaxf(m1, rm1);
        const float al0 = __expf(m0 - mn0), al1 = __expf(m1 - mn1);
        float ps0 = 0.f, ps1 = 0.f;
        #pragma unroll
        for (int ni = 0; ni < 16; ni++) {
            float p0 = __expf(sacc[ni][0] - mn0);
            float p1 = __expf(sacc[ni][1] - mn0);
            float p2 = __expf(sacc[ni][2] - mn1);
            float p3 = __expf(sacc[ni][3] - mn1);
            ps0 += p0 + p1; ps1 += p2 + p3;
            const int col = ni*8 + t4*2;
            Pw[(pr0     * PS2 + col) >> 1] = pack_bf16(p0, p1);
            Pw[((pr0+8) * PS2 + col) >> 1] = pack_bf16(p2, p3);
        }
        ps0 += __shfl_xor_sync(0xffffffffu, ps0, 1);
        ps0 += __shfl_xor_sync(0xffffffffu, ps0, 2);
        ps1 += __shfl_xor_sync(0xffffffffu, ps1, 1);
        ps1 += __shfl_xor_sync(0xffffffffu, ps1, 2);
        l0 = l0 * al0 + ps0; l1 = l1 * al1 + ps1;
        m0 = mn0; m1 = mn1;
        #pragma unroll
        for (int ni = 0; ni < 8; ni++) {
            o[ni][0] *= al0; o[ni][1] *= al0;
            o[ni][2] *= al1; o[ni][3] *= al1;
        }
        __syncwarp();

        CP_WAIT(1);
        __syncthreads();

        #pragma unroll
        for (int kk = 0; kk < 8; kk++) {
            unsigned a[4];
            ldmA(a, pA + kk*32);
            const uint32_t vB = vBb + kk*16*VS2*2;
            #pragma unroll
            for (int ni = 0; ni < 8; ni++) {
                unsigned bbf[2];
                ldmBT(bbf, vB + ni*16);
                mma16bf(o[ni], a, bbf);
            }
        }
    }

    const float inv0 = 1.f / l0, inv1 = 1.f / l1;
    __nv_bfloat16* cp = ctx + base + (size_t)blockIdx.x * 128 * Ec;
    #pragma unroll
    for (int ni = 0; ni < 8; ni++) {
        const int d = ni*8 + t4*2;
        *reinterpret_cast<unsigned*>(cp + (size_t)pr0     * Ec + d) =
            pack_bf16(o[ni][0] * inv0, o[ni][1] * inv0);
        *reinterpret_cast<unsigned*>(cp + (size_t)(pr0+8) * Ec + d) =
            pack_bf16(o[ni][2] * inv1, o[ni][3] * inv1);
    }
}

// ---------------- launch ----------------
extern "C" void kernel_launch(void* const* d_in, const int* in_sizes, int n_in,
                              void* d_out, int out_size)
{
    const float* x   = (const float*)d_in[0];
    const float* wq  = (const float*)d_in[1];
    const float* bq  = (const float*)d_in[2];
    const float* wk  = (const float*)d_in[3];
    const float* bk  = (const float*)d_in[4];
    const float* wv  = (const float*)d_in[5];
    const float* bv  = (const float*)d_in[6];
    const float* wo  = (const float*)d_in[7];
    const float* bo  = (const float*)d_in[8];
    const float* w1  = (const float*)d_in[9];
    const float* b1  = (const float*)d_in[10];
    const float* w2  = (const float*)d_in[11];
    const float* b2  = (const float*)d_in[12];
    const float* g1  = (const float*)d_in[13];
    const float* be1 = (const float*)d_in[14];
    const float* g2  = (const float*)d_in[15];
    const float* be2 = (const float*)d_in[16];
    float* out = (float*)d_out;

    __nv_bfloat16 *z0, *z1, *q, *k, *v, *ctx, *h, *wqkvT, *woT, *w1T, *w2T;
    float* x1;
    cudaGetSymbolAddress((void**)&z0,  g_z0);
    cudaGetSymbolAddress((void**)&z1,  g_z1);
    cudaGetSymbolAddress((void**)&q,   g_q);
    cudaGetSymbolAddress((void**)&k,   g_k);
    cudaGetSymbolAddress((void**)&v,   g_v);
    cudaGetSymbolAddress((void**)&ctx, g_ctx);
    cudaGetSymbolAddress((void**)&h,   g_h);
    cudaGetSymbolAddress((void**)&x1,  g_x1);
    cudaGetSymbolAddress((void**)&wqkvT, g_wqkvT);
    cudaGetSymbolAddress((void**)&woT, g_woT);
    cudaGetSymbolAddress((void**)&w1T, g_w1T);
    cudaGetSymbolAddress((void**)&w2T, g_w2T);

    cudaFuncSetAttribute(attn_kernel,   cudaFuncAttributeMaxDynamicSharedMemorySize, ATTN_SMEM);
    cudaFuncSetAttribute(tc_gemm_res64, cudaFuncAttributeMaxDynamicSharedMemorySize, SMEM_GEMM64);
    cudaFuncSetAttribute(tc_gemm_gelu,  cudaFuncAttributeMaxDynamicSharedMemorySize, SMEM_GEMM);
    cudaFuncSetAttribute(tc_gemm_qkv,   cudaFuncAttributeMaxDynamicSharedMemorySize, SMEM_GEMM);

    // 1
    ln_kernel<<<TOK, 256>>>(x, g1, be1, z0);
    // 2
    transpose4_bf<<<dim3(32, 32, 4), 256>>>(
        wq, wk, wv, wo,
        wqkvT, wqkvT + (size_t)Ec*Ec, wqkvT + (size_t)2*Ec*Ec, woT);
    // 3
    transpose_bf<<<dim3(MLPc/32, Ec/32), 256>>>(w1, w1T, Ec, MLPc);
    // 4
    transpose_bf<<<dim3(Ec/32, MLPc/32), 256>>>(w2, w2T, MLPc, Ec);
    // 5
    tc_gemm_qkv<<<dim3(24, TOK/128), 128, SMEM_GEMM>>>(z0, wqkvT, bq, bk, bv, q, k, v, Ec);
    // 6
    attn_kernel<<<dim3(Sc/128, Bc*Hc), 256, ATTN_SMEM>>>(q, k, v, ctx);
    // 7  O-proj: M64 tile, grid 512
    tc_gemm_res64<<<dim3(Ec/128, TOK/64), 128, SMEM_GEMM64>>>(ctx, woT, bo, x, x1, TOK, Ec, Ec);
    // 8
    ln_kernel<<<TOK, 256>>>(x1, g2, be2, z1);
    // 9
    tc_gemm_gelu<<<dim3(MLPc/128, TOK/128), 128, SMEM_GEMM>>>(z1, w1T, b1, h, TOK, MLPc, Ec);
    // 10  MLP2: M64 tile, grid 512
    tc_gemm_res64<<<dim3(Ec/128, TOK/64), 128, SMEM_GEMM64>>>(h, w2T, b2, x1, out, TOK, Ec, MLPc);
}

// round 15
// speedup vs baseline: 1.9711x; 1.1037x over previous
#include <cuda_runtime.h>
#include <cuda_bf16.h>
#include <cstdint>
#include <math.h>

#define Bc   2
#define Sc   2048
#define TOK  4096
#define Ec   1024
#define Hc   16
#define HDc  64
#define MLPc 4096

// ---------------- scratch (no allocations allowed) ----------------
__device__ __nv_bfloat16 g_z0[(size_t)TOK * Ec];
__device__ __nv_bfloat16 g_z1[(size_t)TOK * Ec];
__device__ __nv_bfloat16 g_q[(size_t)TOK * Ec];
__device__ __nv_bfloat16 g_k[(size_t)TOK * Ec];
__device__ __nv_bfloat16 g_v[(size_t)TOK * Ec];
__device__ __nv_bfloat16 g_ctx[(size_t)TOK * Ec];
__device__ __nv_bfloat16 g_h[(size_t)TOK * MLPc];
__device__ float g_x1[(size_t)TOK * Ec];
__device__ __nv_bfloat16 g_wqkvT[(size_t)3 * Ec * Ec];   // [3N][K]
__device__ __nv_bfloat16 g_woT[(size_t)Ec * Ec];         // [N][K]
__device__ __nv_bfloat16 g_w1T[(size_t)MLPc * Ec];       // [4096][1024]
__device__ __nv_bfloat16 g_w2T[(size_t)Ec * MLPc];       // [1024][4096]

// ---------------- helpers ----------------
__device__ __forceinline__ unsigned pack_bf16(float lo, float hi) {
    unsigned r;
    asm("cvt.rn.bf16x2.f32 %0, %1, %2;" : "=r"(r) : "f"(hi), "f"(lo));
    return r;
}
__device__ __forceinline__ uint32_t smem_u32(const void* p) {
    uint32_t a;
    asm("{ .reg .u64 t; cvta.to.shared.u64 t, %1; cvt.u32.u64 %0, t; }" : "=r"(a) : "l"(p));
    return a;
}
__device__ __forceinline__ void cp16(uint32_t d, const void* s) {
    asm volatile("cp.async.cg.shared.global [%0], [%1], 16;\n" :: "r"(d), "l"(s));
}
__device__ __forceinline__ void cp_commit() {
    asm volatile("cp.async.commit_group;\n" ::: "memory");
}
#define CP_WAIT(n) asm volatile("cp.async.wait_group %0;\n" :: "n"(n) : "memory")

__device__ __forceinline__ void mma16bf(float c[4], const unsigned a[4], const unsigned b[2]) {
    asm volatile(
        "mma.sync.aligned.m16n8k16.row.col.f32.bf16.bf16.f32 "
        "{%0,%1,%2,%3}, {%4,%5,%6,%7}, {%8,%9}, {%0,%1,%2,%3};\n"
        : "+f"(c[0]), "+f"(c[1]), "+f"(c[2]), "+f"(c[3])
        : "r"(a[0]), "r"(a[1]), "r"(a[2]), "r"(a[3]),
          "r"(b[0]), "r"(b[1]));
}
__device__ __forceinline__ void ldmA(unsigned a[4], uint32_t addr) {
    asm volatile("ldmatrix.sync.aligned.m8n8.x4.shared.b16 {%0,%1,%2,%3}, [%4];"
                 : "=r"(a[0]), "=r"(a[1]), "=r"(a[2]), "=r"(a[3]) : "r"(addr));
}
__device__ __forceinline__ void ldmB(unsigned b[2], uint32_t addr) {
    asm volatile("ldmatrix.sync.aligned.m8n8.x2.shared.b16 {%0,%1}, [%2];"
                 : "=r"(b[0]), "=r"(b[1]) : "r"(addr));
}
__device__ __forceinline__ void ldmBT(unsigned b[2], uint32_t addr) {
    asm volatile("ldmatrix.sync.aligned.m8n8.x2.trans.shared.b16 {%0,%1}, [%2];"
                 : "=r"(b[0]), "=r"(b[1]) : "r"(addr));
}

// -------- weight transpose + bf16 convert --------
__global__ void __launch_bounds__(256) transpose4_bf(
    const float* __restrict__ i0, const float* __restrict__ i1,
    const float* __restrict__ i2, const float* __restrict__ i3,
    __nv_bfloat16* __restrict__ o0, __nv_bfloat16* __restrict__ o1,
    __nv_bfloat16* __restrict__ o2, __nv_bfloat16* __restrict__ o3)
{
    const float* in = (blockIdx.z == 0) ? i0 : (blockIdx.z == 1) ? i1 : (blockIdx.z == 2) ? i2 : i3;
    __nv_bfloat16* out = (blockIdx.z == 0) ? o0 : (blockIdx.z == 1) ? o1 : (blockIdx.z == 2) ? o2 : o3;
    __shared__ float tile[32][33];
    const int bx = blockIdx.x * 32, by = blockIdx.y * 32;
    const int tx = threadIdx.x & 31, ty = threadIdx.x >> 5;
    #pragma unroll
    for (int i = 0; i < 32; i += 8)
        tile[ty + i][tx] = in[(size_t)(by + ty + i) * Ec + bx + tx];
    __syncthreads();
    #pragma unroll
    for (int i = 0; i < 32; i += 8)
        out[(size_t)(bx + ty + i) * Ec + by + tx] = __float2bfloat16(tile[tx][ty + i]);
}

__global__ void __launch_bounds__(256) transpose_bf(
    const float* __restrict__ in, __nv_bfloat16* __restrict__ out, int R, int C)
{
    __shared__ float tile[32][33];
    const int bx = blockIdx.x * 32, by = blockIdx.y * 32;
    const int tx = threadIdx.x & 31, ty = threadIdx.x >> 5;
    #pragma unroll
    for (int i = 0; i < 32; i += 8)
        tile[ty + i][tx] = in[(size_t)(by + ty + i) * C + bx + tx];
    __syncthreads();
    #pragma unroll
    for (int i = 0; i < 32; i += 8)
        out[(size_t)(bx + ty + i) * R + by + tx] = __float2bfloat16(tile[tx][ty + i]);
}

// ---------------- LayerNorm (fp32 exact, bf16 output) ----------------
__global__ void __launch_bounds__(256) ln_kernel(
    const float* __restrict__ x, const float* __restrict__ gam,
    const float* __restrict__ bet, __nv_bfloat16* __restrict__ y)
{
    const int row = blockIdx.x, t = threadIdx.x;
    const float4* xr = reinterpret_cast<const float4*>(x + (size_t)row * Ec);
    float4 v = xr[t];
    float s  = v.x + v.y + v.z + v.w;
    float ss = v.x*v.x + v.y*v.y + v.z*v.z + v.w*v.w;
    #pragma unroll
    for (int o = 16; o; o >>= 1) {
        s  += __shfl_xor_sync(0xffffffffu, s,  o);
        ss += __shfl_xor_sync(0xffffffffu, ss, o);
    }
    __shared__ float rs[8], rss[8];
    if ((t & 31) == 0) { rs[t >> 5] = s; rss[t >> 5] = ss; }
    __syncthreads();
    if (t < 32) {
        float a = (t < 8) ? rs[t]  : 0.f;
        float b = (t < 8) ? rss[t] : 0.f;
        #pragma unroll
        for (int o = 4; o; o >>= 1) {
            a += __shfl_xor_sync(0xffffffffu, a, o);
            b += __shfl_xor_sync(0xffffffffu, b, o);
        }
        if (t == 0) { rs[0] = a; rss[0] = b; }
    }
    __syncthreads();
    const float mu   = rs[0]  * (1.f / Ec);
    const float var  = rss[0] * (1.f / Ec) - mu * mu;
    const float rstd = rsqrtf(var + 1e-5f);
    float4 gv = reinterpret_cast<const float4*>(gam)[t];
    float4 bv = reinterpret_cast<const float4*>(bet)[t];
    uint2 u;
    u.x = pack_bf16((v.x - mu) * rstd * gv.x + bv.x, (v.y - mu) * rstd * gv.y + bv.y);
    u.y = pack_bf16((v.z - mu) * rstd * gv.z + bv.z, (v.w - mu) * rstd * gv.w + bv.w);
    reinterpret_cast<uint2*>(y + (size_t)row * Ec)[t] = u;
}

// ---- BF16 GEMM core (M128 tile): 2-stage, k-tile 64, 3 CTA/SM ----
#define KT2   64
#define SW2   72
#define STG2  (128 * SW2 * 2)
#define NSTG  2
#define SMEM_GEMM (2 * NSTG * STG2)      // 73728 -> 3 CTAs/SM

__device__ __forceinline__ void ldstage_bf(uint32_t ab, uint32_t bb,
    const __nv_bfloat16* __restrict__ Ap, const __nv_bfloat16* __restrict__ Bp,
    int K, int kt)
{
    const int t = threadIdx.x;
    const int k0 = kt * KT2;
    #pragma unroll
    for (int i = 0; i < 8; i++) {
        const int idx = t + i * 128;
        const int r = idx >> 3, cu = (idx & 7) * 8;
        cp16(ab + (r * SW2 + cu) * 2, Ap + (size_t)r * K + k0 + cu);
    }
    #pragma unroll
    for (int i = 0; i < 8; i++) {
        const int idx = t + i * 128;
        const int r = idx >> 3, cu = (idx & 7) * 8;
        cp16(bb + (r * SW2 + cu) * 2, Bp + (size_t)r * K + k0 + cu);
    }
}

__device__ __forceinline__ void gemm_mainloop_bf(
    const __nv_bfloat16* __restrict__ Ap, const __nv_bfloat16* __restrict__ Bp,
    int K, char* smem, float acc[4][8][4])
{
    const int t    = threadIdx.x;
    const int lane = t & 31, warp = t >> 5;
    const int wm = warp >> 1, wn = warp & 1;
    const int NK = K / KT2;

    const uint32_t asb = smem_u32(smem);
    const uint32_t bsb = asb + NSTG * STG2;

    const int frow = ((lane >> 3) & 1) * 8 + (lane & 7);
    const int fcol = ((lane >> 4) & 1) * 8;
    const int brow = lane & 7;
    const int bkof = ((lane >> 3) & 1) * 8;

    ldstage_bf(asb, bsb, Ap, Bp, K, 0);
    cp_commit();

    int st = 0;
    for (int kt = 0; kt < NK; kt++) {
        CP_WAIT(0);
        __syncthreads();
        if (kt + 1 < NK) {
            const int ps = st ^ 1;
            ldstage_bf(asb + ps * STG2, bsb + ps * STG2, Ap, Bp, K, kt + 1);
        }
        cp_commit();

        const uint32_t aB = asb + st * STG2 + ((wm*64 + frow) * SW2 + fcol) * 2;
        const uint32_t bB = bsb + st * STG2 + ((wn*64 + brow) * SW2 + bkof) * 2;
        #pragma unroll
        for (int kk = 0; kk < 4; kk++) {
            unsigned af[4][4], bf[8][2];
            #pragma unroll
            for (int mi = 0; mi < 4; mi++)
                ldmA(af[mi], aB + mi*16*SW2*2 + kk*32);
            #pragma unroll
            for (int ni = 0; ni < 8; ni++)
                ldmB(bf[ni], bB + ni*8*SW2*2 + kk*32);
            #pragma unroll
            for (int mi = 0; mi < 4; mi++)
                #pragma unroll
                for (int ni = 0; ni < 8; ni++)
                    mma16bf(acc[mi][ni], af[mi], bf[ni]);
        }
        st ^= 1;
    }
}

// ---- BF16 GEMM core (M64 tile): 4 CTA/SM ----
#define ASTG64 (64 * SW2 * 2)
#define SMEM_GEMM64 (NSTG * (ASTG64 + STG2))   // 55296 -> 4 CTAs/SM

__device__ __forceinline__ void ldstage_bf64(uint32_t ab, uint32_t bb,
    const __nv_bfloat16* __restrict__ Ap, const __nv_bfloat16* __restrict__ Bp,
    int K, int kt)
{
    const int t = threadIdx.x;
    const int k0 = kt * KT2;
    #pragma unroll
    for (int i = 0; i < 4; i++) {
        const int idx = t + i * 128;
        const int r = idx >> 3, cu = (idx & 7) * 8;
        cp16(ab + (r * SW2 + cu) * 2, Ap + (size_t)r * K + k0 + cu);
    }
    #pragma unroll
    for (int i = 0; i < 8; i++) {
        const int idx = t + i * 128;
        const int r = idx >> 3, cu = (idx & 7) * 8;
        cp16(bb + (r * SW2 + cu) * 2, Bp + (size_t)r * K + k0 + cu);
    }
}

__global__ void __launch_bounds__(128, 4) tc_gemm_res64(
    const __nv_bfloat16* __restrict__ A, const __nv_bfloat16* __restrict__ BT,
    const float* __restrict__ bias, const float* __restrict__ res,
    float* __restrict__ C, int M, int N, int K)
{
    extern __shared__ char smem[];
    const int t = threadIdx.x;
    const int lane = t & 31, warp = t >> 5;
    const int wm = warp >> 1, wn = warp & 1;
    const int g  = lane >> 2, t4 = lane & 3;
    const int bm = blockIdx.y * 64, bn = blockIdx.x * 128;
    const int NK = K / KT2;

    const uint32_t asb = smem_u32(smem);
    const uint32_t bsb = asb + NSTG * ASTG64;

    const int frow = ((lane >> 3) & 1) * 8 + (lane & 7);
    const int fcol = ((lane >> 4) & 1) * 8;
    const int brow = lane & 7;
    const int bkof = ((lane >> 3) & 1) * 8;

    float acc[2][8][4];
    #pragma unroll
    for (int mi = 0; mi < 2; mi++)
        #pragma unroll
        for (int ni = 0; ni < 8; ni++)
            #pragma unroll
            for (int c = 0; c < 4; c++) acc[mi][ni][c] = 0.f;

    const __nv_bfloat16* Ap = A + (size_t)bm * K;
    const __nv_bfloat16* Bp = BT + (size_t)bn * K;

    ldstage_bf64(asb, bsb, Ap, Bp, K, 0);
    cp_commit();

    int st = 0;
    for (int kt = 0; kt < NK; kt++) {
        CP_WAIT(0);
        __syncthreads();
        if (kt + 1 < NK) {
            const int ps = st ^ 1;
            ldstage_bf64(asb + ps * ASTG64, bsb + ps * STG2, Ap, Bp, K, kt + 1);
        }
        cp_commit();

        const uint32_t aB = asb + st * ASTG64 + ((wm*32 + frow) * SW2 + fcol) * 2;
        const uint32_t bB = bsb + st * STG2   + ((wn*64 + brow) * SW2 + bkof) * 2;
        #pragma unroll
        for (int kk = 0; kk < 4; kk++) {
            unsigned af[2][4], bf[8][2];
            #pragma unroll
            for (int mi = 0; mi < 2; mi++)
                ldmA(af[mi], aB + mi*16*SW2*2 + kk*32);
            #pragma unroll
            for (int ni = 0; ni < 8; ni++)
                ldmB(bf[ni], bB + ni*8*SW2*2 + kk*32);
            #pragma unroll
            for (int mi = 0; mi < 2; mi++)
                #pragma unroll
                for (int ni = 0; ni < 8; ni++)
                    mma16bf(acc[mi][ni], af[mi], bf[ni]);
        }
        st ^= 1;
    }

    #pragma unroll
    for (int mi = 0; mi < 2; mi++) {
        #pragma unroll
        for (int half = 0; half < 2; half++) {
            const int row = bm + wm*32 + mi*16 + g + half*8;
            #pragma unroll
            for (int ni = 0; ni < 8; ni++) {
                const int col = bn + wn*64 + ni*8 + t4*2;
                float vx = acc[mi][ni][half*2 + 0] + __ldg(bias + col)
                         + __ldg(res + (size_t)row * N + col);
                float vy = acc[mi][ni][half*2 + 1] + __ldg(bias + col + 1)
                         + __ldg(res + (size_t)row * N + col + 1);
                float2 o; o.x = vx; o.y = vy;
                *reinterpret_cast<float2*>(C + (size_t)row * N + col) = o;
            }
        }
    }
}

// gelu epilogue, bf16 output (MLP1, M128 tile)
__global__ void __launch_bounds__(128, 3) tc_gemm_gelu(
    const __nv_bfloat16* __restrict__ A, const __nv_bfloat16* __restrict__ BT,
    const float* __restrict__ bias, __nv_bfloat16* __restrict__ C,
    int M, int N, int K)
{
    extern __shared__ char smem[];
    const int t = threadIdx.x;
    const int lane = t & 31, warp = t >> 5;
    const int wm = warp >> 1, wn = warp & 1;
    const int g  = lane >> 2, t4 = lane & 3;
    const int bm = blockIdx.y * 128, bn = blockIdx.x * 128;

    float acc[4][8][4];
    #pragma unroll
    for (int mi = 0; mi < 4; mi++)
        #pragma unroll
        for (int ni = 0; ni < 8; ni++)
            #pragma unroll
            for (int c = 0; c < 4; c++) acc[mi][ni][c] = 0.f;

    gemm_mainloop_bf(A + (size_t)bm * K, BT + (size_t)bn * K, K, smem, acc);

    #pragma unroll
    for (int mi = 0; mi < 4; mi++) {
        #pragma unroll
        for (int half = 0; half < 2; half++) {
            const int row = bm + wm*64 + mi*16 + g + half*8;
            #pragma unroll
            for (int ni = 0; ni < 8; ni++) {
                const int col = bn + wn*64 + ni*8 + t4*2;
                float vx = acc[mi][ni][half*2 + 0] + __ldg(bias + col);
                float vy = acc[mi][ni][half*2 + 1] + __ldg(bias + col + 1);
                vx = 0.5f * vx * (1.f + erff(vx * 0.70710678118654752f));
                vy = 0.5f * vy * (1.f + erff(vy * 0.70710678118654752f));
                *reinterpret_cast<unsigned*>(C + (size_t)row * N + col) = pack_bf16(vx, vy);
            }
        }
    }
}

// fused QKV (M128 tile)
__global__ void __launch_bounds__(128, 3) tc_gemm_qkv(
    const __nv_bfloat16* __restrict__ A, const __nv_bfloat16* __restrict__ BT,
    const float* __restrict__ bq, const float* __restrict__ bk,
    const float* __restrict__ bv,
    __nv_bfloat16* __restrict__ q, __nv_bfloat16* __restrict__ k,
    __nv_bfloat16* __restrict__ v, int K)
{
    extern __shared__ char smem[];
    const int t = threadIdx.x;
    const int lane = t & 31, warp = t >> 5;
    const int wm = warp >> 1, wn = warp & 1;
    const int g  = lane >> 2, t4 = lane & 3;
    const int which = blockIdx.x >> 3;
    const int bn = (blockIdx.x & 7) * 128;
    const int bm = blockIdx.y * 128;
    const float* bias = (which == 0) ? bq : (which == 1) ? bk : bv;
    __nv_bfloat16* C  = (which == 0) ? q  : (which == 1) ? k  : v;

    float acc[4][8][4];
    #pragma unroll
    for (int mi = 0; mi < 4; mi++)
        #pragma unroll
        for (int ni = 0; ni < 8; ni++)
            #pragma unroll
            for (int c = 0; c < 4; c++) acc[mi][ni][c] = 0.f;

    gemm_mainloop_bf(A + (size_t)bm * K, BT + (size_t)(which * Ec + bn) * K, K, smem, acc);

    #pragma unroll
    for (int mi = 0; mi < 4; mi++) {
        #pragma unroll
        for (int half = 0; half < 2; half++) {
            const int row = bm + wm*64 + mi*16 + g + half*8;
            #pragma unroll
            for (int ni = 0; ni < 8; ni++) {
                const int col = bn + wn*64 + ni*8 + t4*2;
                float vx = acc[mi][ni][half*2 + 0] + __ldg(bias + col);
                float vy = acc[mi][ni][half*2 + 1] + __ldg(bias + col + 1);
                *reinterpret_cast<unsigned*>(C + (size_t)row * Ec + col) = pack_bf16(vx, vy);
            }
        }
    }
}

// -------- flash attention: all-bf16, register-resident P (FA2), 2 CTA/SM -------
#define QS2 72
#define KS2 72
#define VS2 72
#define Q_BYTES (128 * QS2 * 2)
#define K_BYTES (128 * KS2 * 2)
#define V_BYTES (128 * VS2 * 2)
#define ATTN_SMEM (Q_BYTES + 2*K_BYTES + V_BYTES)   // 73728 -> 2+ CTAs/SM

__global__ void __launch_bounds__(256, 2) attn_kernel(
    const __nv_bfloat16* __restrict__ q, const __nv_bfloat16* __restrict__ kg,
    const __nv_bfloat16* __restrict__ vg, __nv_bfloat16* __restrict__ ctx)
{
    extern __shared__ char smc[];
    const uint32_t qb = smem_u32(smc);
    const uint32_t kb = qb + Q_BYTES;
    const uint32_t vb = kb + 2 * K_BYTES;

    const int t = threadIdx.x, lane = t & 31, warp = t >> 5;
    const int g = lane >> 2, t4 = lane & 3;
    const int b = blockIdx.y >> 4, h = blockIdx.y & 15;
    const size_t base = (size_t)b * Sc * Ec + (size_t)h * HDc;
    const __nv_bfloat16* qp = q  + base + (size_t)blockIdx.x * 128 * Ec;
    const __nv_bfloat16* kp = kg + base;
    const __nv_bfloat16* vp = vg + base;

    const int frow = ((lane >> 3) & 1) * 8 + (lane & 7);
    const int fcol = ((lane >> 4) & 1) * 8;
    const int brow = lane & 7;
    const int bkof = ((lane >> 3) & 1) * 8;

    #pragma unroll
    for (int i = 0; i < 4; i++) {
        const int idx = t + i*256;
        const int r = idx >> 3, cu = (idx & 7) * 8;
        cp16(qb + (r*QS2 + cu)*2, qp + (size_t)r * Ec + cu);
        cp16(kb + (r*KS2 + cu)*2, kp + (size_t)r * Ec + cu);
    }
    cp_commit();

    float o[8][4];
    #pragma unroll
    for (int ni = 0; ni < 8; ni++)
        #pragma unroll
        for (int c = 0; c < 4; c++) o[ni][c] = 0.f;
    float m0 = -INFINITY, m1 = -INFINITY, l0 = 0.f, l1 = 0.f;
    const int pr0 = warp*16 + g;
    const uint32_t qA = qb + ((warp*16 + frow)*QS2 + fcol)*2;
    const uint32_t vBb = vb + (frow*VS2)*2;

    for (int kt = 0; kt < 16; kt++) {
        __syncthreads();
        #pragma unroll
        for (int i = 0; i < 4; i++) {
            const int idx = t + i*256;
            const int r = idx >> 3, cu = (idx & 7) * 8;
            cp16(vb + (r*VS2 + cu)*2, vp + (size_t)(kt*128 + r) * Ec + cu);
        }
        cp_commit();
        if (kt < 15) {
            const uint32_t kbn = kb + ((kt+1)&1) * K_BYTES;
            #pragma unroll
            for (int i = 0; i < 4; i++) {
                const int idx = t + i*256;
                const int r = idx >> 3, cu = (idx & 7) * 8;
                cp16(kbn + (r*KS2 + cu)*2, kp + (size_t)((kt+1)*128 + r) * Ec + cu);
            }
        }
        cp_commit();
        CP_WAIT(2);
        __syncthreads();

        const uint32_t kB = kb + (kt & 1) * K_BYTES + (brow*KS2 + bkof)*2;

        // S = Q @ K^T (bf16)
        float sacc[16][4];
        #pragma unroll
        for (int ni = 0; ni < 16; ni++)
            #pragma unroll
            for (int c = 0; c < 4; c++) sacc[ni][c] = 0.f;
        #pragma unroll
        for (int kk = 0; kk < 4; kk++) {
            unsigned a[4];
            ldmA(a, qA + kk*32);
            #pragma unroll
            for (int ni = 0; ni < 16; ni++) {
                unsigned bbf[2];
                ldmB(bbf, kB + (ni*8*KS2)*2 + kk*32);
                mma16bf(sacc[ni], a, bbf);
            }
        }

        // online softmax; P kept in registers (sacc overwritten with exp values)
        float rm0 = -INFINITY, rm1 = -INFINITY;
        #pragma unroll
        for (int ni = 0; ni < 16; ni++) {
            sacc[ni][0] *= 0.125f; sacc[ni][1] *= 0.125f;
            sacc[ni][2] *= 0.125f; sacc[ni][3] *= 0.125f;
            rm0 = fmaxf(rm0, fmaxf(sacc[ni][0], sacc[ni][1]));
            rm1 = fmaxf(rm1, fmaxf(sacc[ni][2], sacc[ni][3]));
        }
        rm0 = fmaxf(rm0, __shfl_xor_sync(0xffffffffu, rm0, 1));
        rm0 = fmaxf(rm0, __shfl_xor_sync(0xffffffffu, rm0, 2));
        rm1 = fmaxf(rm1, __shfl_xor_sync(0xffffffffu, rm1, 1));
        rm1 = fmaxf(rm1, __shfl_xor_sync(0xffffffffu, rm1, 2));
        const float mn0 = fmaxf(m0, rm0), mn1 = fmaxf(m1, rm1);
        const float al0 = __expf(m0 - mn0), al1 = __expf(m1 - mn1);
        float ps0 = 0.f, ps1 = 0.f;
        #pragma unroll
        for (int ni = 0; ni < 16; ni++) {
            float p0 = __expf(sacc[ni][0] - mn0);
            float p1 = __expf(sacc[ni][1] - mn0);
            float p2 = __expf(sacc[ni][2] - mn1);
            float p3 = __expf(sacc[ni][3] - mn1);
            ps0 += p0 + p1; ps1 += p2 + p3;
            sacc[ni][0] = p0; sacc[ni][1] = p1;
            sacc[ni][2] = p2; sacc[ni][3] = p3;
        }
        ps0 += __shfl_xor_sync(0xffffffffu, ps0, 1);
        ps0 += __shfl_xor_sync(0xffffffffu, ps0, 2);
        ps1 += __shfl_xor_sync(0xffffffffu, ps1, 1);
        ps1 += __shfl_xor_sync(0xffffffffu, ps1, 2);
        l0 = l0 * al0 + ps0; l1 = l1 * al1 + ps1;
        m0 = mn0; m1 = mn1;
        #pragma unroll
        for (int ni = 0; ni < 8; ni++) {
            o[ni][0] *= al0; o[ni][1] *= al0;
            o[ni][2] *= al1; o[ni][3] *= al1;
        }

        CP_WAIT(1);
        __syncthreads();

        // O += P @ V   (P A-fragment built directly from S accumulators)
        #pragma unroll
        for (int kk = 0; kk < 8; kk++) {
            unsigned a[4];
            a[0] = pack_bf16(sacc[2*kk  ][0], sacc[2*kk  ][1]);
            a[1] = pack_bf16(sacc[2*kk  ][2], sacc[2*kk  ][3]);
            a[2] = pack_bf16(sacc[2*kk+1][0], sacc[2*kk+1][1]);
            a[3] = pack_bf16(sacc[2*kk+1][2], sacc[2*kk+1][3]);
            const uint32_t vB = vBb + kk*16*VS2*2;
            #pragma unroll
            for (int ni = 0; ni < 8; ni++) {
                unsigned bbf[2];
                ldmBT(bbf, vB + ni*16);
                mma16bf(o[ni], a, bbf);
            }
        }
    }

    const float inv0 = 1.f / l0, inv1 = 1.f / l1;
    __nv_bfloat16* cp = ctx + base + (size_t)blockIdx.x * 128 * Ec;
    #pragma unroll
    for (int ni = 0; ni < 8; ni++) {
        const int d = ni*8 + t4*2;
        *reinterpret_cast<unsigned*>(cp + (size_t)pr0     * Ec + d) =
            pack_bf16(o[ni][0] * inv0, o[ni][1] * inv0);
        *reinterpret_cast<unsigned*>(cp + (size_t)(pr0+8) * Ec + d) =
            pack_bf16(o[ni][2] * inv1, o[ni][3] * inv1);
    }
}

// ---------------- launch ----------------
extern "C" void kernel_launch(void* const* d_in, const int* in_sizes, int n_in,
                              void* d_out, int out_size)
{
    const float* x   = (const float*)d_in[0];
    const float* wq  = (const float*)d_in[1];
    const float* bq  = (const float*)d_in[2];
    const float* wk  = (const float*)d_in[3];
    const float* bk  = (const float*)d_in[4];
    const float* wv  = (const float*)d_in[5];
    const float* bv  = (const float*)d_in[6];
    const float* wo  = (const float*)d_in[7];
    const float* bo  = (const float*)d_in[8];
    const float* w1  = (const float*)d_in[9];
    const float* b1  = (const float*)d_in[10];
    const float* w2  = (const float*)d_in[11];
    const float* b2  = (const float*)d_in[12];
    const float* g1  = (const float*)d_in[13];
    const float* be1 = (const float*)d_in[14];
    const float* g2  = (const float*)d_in[15];
    const float* be2 = (const float*)d_in[16];
    float* out = (float*)d_out;

    __nv_bfloat16 *z0, *z1, *q, *k, *v, *ctx, *h, *wqkvT, *woT, *w1T, *w2T;
    float* x1;
    cudaGetSymbolAddress((void**)&z0,  g_z0);
    cudaGetSymbolAddress((void**)&z1,  g_z1);
    cudaGetSymbolAddress((void**)&q,   g_q);
    cudaGetSymbolAddress((void**)&k,   g_k);
    cudaGetSymbolAddress((void**)&v,   g_v);
    cudaGetSymbolAddress((void**)&ctx, g_ctx);
    cudaGetSymbolAddress((void**)&h,   g_h);
    cudaGetSymbolAddress((void**)&x1,  g_x1);
    cudaGetSymbolAddress((void**)&wqkvT, g_wqkvT);
    cudaGetSymbolAddress((void**)&woT, g_woT);
    cudaGetSymbolAddress((void**)&w1T, g_w1T);
    cudaGetSymbolAddress((void**)&w2T, g_w2T);

    cudaFuncSetAttribute(attn_kernel,   cudaFuncAttributeMaxDynamicSharedMemorySize, ATTN_SMEM);
    cudaFuncSetAttribute(tc_gemm_res64, cudaFuncAttributeMaxDynamicSharedMemorySize, SMEM_GEMM64);
    cudaFuncSetAttribute(tc_gemm_gelu,  cudaFuncAttributeMaxDynamicSharedMemorySize, SMEM_GEMM);
    cudaFuncSetAttribute(tc_gemm_qkv,   cudaFuncAttributeMaxDynamicSharedMemorySize, SMEM_GEMM);

    // 1
    ln_kernel<<<TOK, 256>>>(x, g1, be1, z0);
    // 2
    transpose4_bf<<<dim3(32, 32, 4), 256>>>(
        wq, wk, wv, wo,
        wqkvT, wqkvT + (size_t)Ec*Ec, wqkvT + (size_t)2*Ec*Ec, woT);
    // 3
    transpose_bf<<<dim3(MLPc/32, Ec/32), 256>>>(w1, w1T, Ec, MLPc);
    // 4
    transpose_bf<<<dim3(Ec/32, MLPc/32), 256>>>(w2, w2T, MLPc, Ec);
    // 5
    tc_gemm_qkv<<<dim3(24, TOK/128), 128, SMEM_GEMM>>>(z0, wqkvT, bq, bk, bv, q, k, v, Ec);
    // 6  <- profiled by ncu (-s 5 -c 1): attention
    attn_kernel<<<dim3(Sc/128, Bc*Hc), 256, ATTN_SMEM>>>(q, k, v, ctx);
    // 7
    tc_gemm_res64<<<dim3(Ec/128, TOK/64), 128, SMEM_GEMM64>>>(ctx, woT, bo, x, x1, TOK, Ec, Ec);
    // 8
    ln_kernel<<<TOK, 256>>>(x1, g2, be2, z1);
    // 9
    tc_gemm_gelu<<<dim3(MLPc/128, TOK/128), 128, SMEM_GEMM>>>(z1, w1T, b1, h, TOK, MLPc, Ec);
    // 10
    tc_gemm_res64<<<dim3(Ec/128, TOK/64), 128, SMEM_GEMM64>>>(h, w2T, b2, x1, out, TOK, Ec, MLPc);
}

// round 16
// speedup vs baseline: 2.0072x; 1.0183x over previous
#include <cuda_runtime.h>
#include <cuda_bf16.h>
#include <cstdint>
#include <math.h>

#define Bc   2
#define Sc   2048
#define TOK  4096
#define Ec   1024
#define Hc   16
#define HDc  64
#define MLPc 4096

// ---------------- scratch (no allocations allowed) ----------------
__device__ __nv_bfloat16 g_z0[(size_t)TOK * Ec];
__device__ __nv_bfloat16 g_z1[(size_t)TOK * Ec];
__device__ __nv_bfloat16 g_q[(size_t)TOK * Ec];
__device__ __nv_bfloat16 g_k[(size_t)TOK * Ec];
__device__ __nv_bfloat16 g_v[(size_t)TOK * Ec];
__device__ __nv_bfloat16 g_ctx[(size_t)TOK * Ec];
__device__ __nv_bfloat16 g_h[(size_t)TOK * MLPc];
__device__ float g_x1[(size_t)TOK * Ec];
__device__ __nv_bfloat16 g_wqkvT[(size_t)3 * Ec * Ec];   // [3N][K]
__device__ __nv_bfloat16 g_woT[(size_t)Ec * Ec];         // [N][K]
__device__ __nv_bfloat16 g_w1T[(size_t)MLPc * Ec];       // [4096][1024]
__device__ __nv_bfloat16 g_w2T[(size_t)Ec * MLPc];       // [1024][4096]

// ---------------- helpers ----------------
__device__ __forceinline__ unsigned pack_bf16(float lo, float hi) {
    unsigned r;
    asm("cvt.rn.bf16x2.f32 %0, %1, %2;" : "=r"(r) : "f"(hi), "f"(lo));
    return r;
}
__device__ __forceinline__ uint32_t smem_u32(const void* p) {
    uint32_t a;
    asm("{ .reg .u64 t; cvta.to.shared.u64 t, %1; cvt.u32.u64 %0, t; }" : "=r"(a) : "l"(p));
    return a;
}
__device__ __forceinline__ void cp16(uint32_t d, const void* s) {
    asm volatile("cp.async.cg.shared.global [%0], [%1], 16;\n" :: "r"(d), "l"(s));
}
__device__ __forceinline__ void cp_commit() {
    asm volatile("cp.async.commit_group;\n" ::: "memory");
}
#define CP_WAIT(n) asm volatile("cp.async.wait_group %0;\n" :: "n"(n) : "memory")

__device__ __forceinline__ void mma16bf(float c[4], const unsigned a[4], const unsigned b[2]) {
    asm volatile(
        "mma.sync.aligned.m16n8k16.row.col.f32.bf16.bf16.f32 "
        "{%0,%1,%2,%3}, {%4,%5,%6,%7}, {%8,%9}, {%0,%1,%2,%3};\n"
        : "+f"(c[0]), "+f"(c[1]), "+f"(c[2]), "+f"(c[3])
        : "r"(a[0]), "r"(a[1]), "r"(a[2]), "r"(a[3]),
          "r"(b[0]), "r"(b[1]));
}
__device__ __forceinline__ void ldmA(unsigned a[4], uint32_t addr) {
    asm volatile("ldmatrix.sync.aligned.m8n8.x4.shared.b16 {%0,%1,%2,%3}, [%4];"
                 : "=r"(a[0]), "=r"(a[1]), "=r"(a[2]), "=r"(a[3]) : "r"(addr));
}
__device__ __forceinline__ void ldmB(unsigned b[2], uint32_t addr) {
    asm volatile("ldmatrix.sync.aligned.m8n8.x2.shared.b16 {%0,%1}, [%2];"
                 : "=r"(b[0]), "=r"(b[1]) : "r"(addr));
}
__device__ __forceinline__ void ldmBT(unsigned b[2], uint32_t addr) {
    asm volatile("ldmatrix.sync.aligned.m8n8.x2.trans.shared.b16 {%0,%1}, [%2];"
                 : "=r"(b[0]), "=r"(b[1]) : "r"(addr));
}

// -------- weight transpose + bf16 convert --------
__global__ void __launch_bounds__(256) transpose4_bf(
    const float* __restrict__ i0, const float* __restrict__ i1,
    const float* __restrict__ i2, const float* __restrict__ i3,
    __nv_bfloat16* __restrict__ o0, __nv_bfloat16* __restrict__ o1,
    __nv_bfloat16* __restrict__ o2, __nv_bfloat16* __restrict__ o3)
{
    const float* in = (blockIdx.z == 0) ? i0 : (blockIdx.z == 1) ? i1 : (blockIdx.z == 2) ? i2 : i3;
    __nv_bfloat16* out = (blockIdx.z == 0) ? o0 : (blockIdx.z == 1) ? o1 : (blockIdx.z == 2) ? o2 : o3;
    __shared__ float tile[32][33];
    const int bx = blockIdx.x * 32, by = blockIdx.y * 32;
    const int tx = threadIdx.x & 31, ty = threadIdx.x >> 5;
    #pragma unroll
    for (int i = 0; i < 32; i += 8)
        tile[ty + i][tx] = in[(size_t)(by + ty + i) * Ec + bx + tx];
    __syncthreads();
    #pragma unroll
    for (int i = 0; i < 32; i += 8)
        out[(size_t)(bx + ty + i) * Ec + by + tx] = __float2bfloat16(tile[tx][ty + i]);
}

__global__ void __launch_bounds__(256) transpose_bf(
    const float* __restrict__ in, __nv_bfloat16* __restrict__ out, int R, int C)
{
    __shared__ float tile[32][33];
    const int bx = blockIdx.x * 32, by = blockIdx.y * 32;
    const int tx = threadIdx.x & 31, ty = threadIdx.x >> 5;
    #pragma unroll
    for (int i = 0; i < 32; i += 8)
        tile[ty + i][tx] = in[(size_t)(by + ty + i) * C + bx + tx];
    __syncthreads();
    #pragma unroll
    for (int i = 0; i < 32; i += 8)
        out[(size_t)(bx + ty + i) * R + by + tx] = __float2bfloat16(tile[tx][ty + i]);
}

// ---------------- LayerNorm (fp32 exact, bf16 output) ----------------
__global__ void __launch_bounds__(256) ln_kernel(
    const float* __restrict__ x, const float* __restrict__ gam,
    const float* __restrict__ bet, __nv_bfloat16* __restrict__ y)
{
    const int row = blockIdx.x, t = threadIdx.x;
    const float4* xr = reinterpret_cast<const float4*>(x + (size_t)row * Ec);
    float4 v = xr[t];
    float s  = v.x + v.y + v.z + v.w;
    float ss = v.x*v.x + v.y*v.y + v.z*v.z + v.w*v.w;
    #pragma unroll
    for (int o = 16; o; o >>= 1) {
        s  += __shfl_xor_sync(0xffffffffu, s,  o);
        ss += __shfl_xor_sync(0xffffffffu, ss, o);
    }
    __shared__ float rs[8], rss[8];
    if ((t & 31) == 0) { rs[t >> 5] = s; rss[t >> 5] = ss; }
    __syncthreads();
    if (t < 32) {
        float a = (t < 8) ? rs[t]  : 0.f;
        float b = (t < 8) ? rss[t] : 0.f;
        #pragma unroll
        for (int o = 4; o; o >>= 1) {
            a += __shfl_xor_sync(0xffffffffu, a, o);
            b += __shfl_xor_sync(0xffffffffu, b, o);
        }
        if (t == 0) { rs[0] = a; rss[0] = b; }
    }
    __syncthreads();
    const float mu   = rs[0]  * (1.f / Ec);
    const float var  = rss[0] * (1.f / Ec) - mu * mu;
    const float rstd = rsqrtf(var + 1e-5f);
    float4 gv = reinterpret_cast<const float4*>(gam)[t];
    float4 bv = reinterpret_cast<const float4*>(bet)[t];
    uint2 u;
    u.x = pack_bf16((v.x - mu) * rstd * gv.x + bv.x, (v.y - mu) * rstd * gv.y + bv.y);
    u.y = pack_bf16((v.z - mu) * rstd * gv.z + bv.z, (v.w - mu) * rstd * gv.w + bv.w);
    reinterpret_cast<uint2*>(y + (size_t)row * Ec)[t] = u;
}

// ---- BF16 GEMM core (M128 tile): 2-stage, k-tile 64, 3 CTA/SM ----
#define KT2   64
#define SW2   72
#define STG2  (128 * SW2 * 2)
#define NSTG  2
#define SMEM_GEMM (2 * NSTG * STG2)      // 73728 -> 3 CTAs/SM

__device__ __forceinline__ void ldstage_bf(uint32_t ab, uint32_t bb,
    const __nv_bfloat16* __restrict__ Ap, const __nv_bfloat16* __restrict__ Bp,
    int K, int kt)
{
    const int t = threadIdx.x;
    const int k0 = kt * KT2;
    #pragma unroll
    for (int i = 0; i < 8; i++) {
        const int idx = t + i * 128;
        const int r = idx >> 3, cu = (idx & 7) * 8;
        cp16(ab + (r * SW2 + cu) * 2, Ap + (size_t)r * K + k0 + cu);
    }
    #pragma unroll
    for (int i = 0; i < 8; i++) {
        const int idx = t + i * 128;
        const int r = idx >> 3, cu = (idx & 7) * 8;
        cp16(bb + (r * SW2 + cu) * 2, Bp + (size_t)r * K + k0 + cu);
    }
}

__device__ __forceinline__ void gemm_mainloop_bf(
    const __nv_bfloat16* __restrict__ Ap, const __nv_bfloat16* __restrict__ Bp,
    int K, char* smem, float acc[4][8][4])
{
    const int t    = threadIdx.x;
    const int lane = t & 31, warp = t >> 5;
    const int wm = warp >> 1, wn = warp & 1;
    const int NK = K / KT2;

    const uint32_t asb = smem_u32(smem);
    const uint32_t bsb = asb + NSTG * STG2;

    const int frow = ((lane >> 3) & 1) * 8 + (lane & 7);
    const int fcol = ((lane >> 4) & 1) * 8;
    const int brow = lane & 7;
    const int bkof = ((lane >> 3) & 1) * 8;

    ldstage_bf(asb, bsb, Ap, Bp, K, 0);
    cp_commit();

    int st = 0;
    for (int kt = 0; kt < NK; kt++) {
        CP_WAIT(0);
        __syncthreads();
        if (kt + 1 < NK) {
            const int ps = st ^ 1;
            ldstage_bf(asb + ps * STG2, bsb + ps * STG2, Ap, Bp, K, kt + 1);
        }
        cp_commit();

        const uint32_t aB = asb + st * STG2 + ((wm*64 + frow) * SW2 + fcol) * 2;
        const uint32_t bB = bsb + st * STG2 + ((wn*64 + brow) * SW2 + bkof) * 2;
        #pragma unroll
        for (int kk = 0; kk < 4; kk++) {
            unsigned af[4][4], bf[8][2];
            #pragma unroll
            for (int mi = 0; mi < 4; mi++)
                ldmA(af[mi], aB + mi*16*SW2*2 + kk*32);
            #pragma unroll
            for (int ni = 0; ni < 8; ni++)
                ldmB(bf[ni], bB + ni*8*SW2*2 + kk*32);
            #pragma unroll
            for (int mi = 0; mi < 4; mi++)
                #pragma unroll
                for (int ni = 0; ni < 8; ni++)
                    mma16bf(acc[mi][ni], af[mi], bf[ni]);
        }
        st ^= 1;
    }
}

// ---- BF16 GEMM core (M64 tile): 4 CTA/SM ----
#define ASTG64 (64 * SW2 * 2)
#define SMEM_GEMM64 (NSTG * (ASTG64 + STG2))   // 55296 -> 4 CTAs/SM

__device__ __forceinline__ void ldstage_bf64(uint32_t ab, uint32_t bb,
    const __nv_bfloat16* __restrict__ Ap, const __nv_bfloat16* __restrict__ Bp,
    int K, int kt)
{
    const int t = threadIdx.x;
    const int k0 = kt * KT2;
    #pragma unroll
    for (int i = 0; i < 4; i++) {
        const int idx = t + i * 128;
        const int r = idx >> 3, cu = (idx & 7) * 8;
        cp16(ab + (r * SW2 + cu) * 2, Ap + (size_t)r * K + k0 + cu);
    }
    #pragma unroll
    for (int i = 0; i < 8; i++) {
        const int idx = t + i * 128;
        const int r = idx >> 3, cu = (idx & 7) * 8;
        cp16(bb + (r * SW2 + cu) * 2, Bp + (size_t)r * K + k0 + cu);
    }
}

// shared M64 mainloop
__device__ __forceinline__ void gemm_mainloop_bf64(
    const __nv_bfloat16* __restrict__ Ap, const __nv_bfloat16* __restrict__ Bp,
    int K, char* smem, float acc[2][8][4])
{
    const int t    = threadIdx.x;
    const int lane = t & 31, warp = t >> 5;
    const int wm = warp >> 1, wn = warp & 1;
    const int NK = K / KT2;

    const uint32_t asb = smem_u32(smem);
    const uint32_t bsb = asb + NSTG * ASTG64;

    const int frow = ((lane >> 3) & 1) * 8 + (lane & 7);
    const int fcol = ((lane >> 4) & 1) * 8;
    const int brow = lane & 7;
    const int bkof = ((lane >> 3) & 1) * 8;

    ldstage_bf64(asb, bsb, Ap, Bp, K, 0);
    cp_commit();

    int st = 0;
    for (int kt = 0; kt < NK; kt++) {
        CP_WAIT(0);
        __syncthreads();
        if (kt + 1 < NK) {
            const int ps = st ^ 1;
            ldstage_bf64(asb + ps * ASTG64, bsb + ps * STG2, Ap, Bp, K, kt + 1);
        }
        cp_commit();

        const uint32_t aB = asb + st * ASTG64 + ((wm*32 + frow) * SW2 + fcol) * 2;
        const uint32_t bB = bsb + st * STG2   + ((wn*64 + brow) * SW2 + bkof) * 2;
        #pragma unroll
        for (int kk = 0; kk < 4; kk++) {
            unsigned af[2][4], bf[8][2];
            #pragma unroll
            for (int mi = 0; mi < 2; mi++)
                ldmA(af[mi], aB + mi*16*SW2*2 + kk*32);
            #pragma unroll
            for (int ni = 0; ni < 8; ni++)
                ldmB(bf[ni], bB + ni*8*SW2*2 + kk*32);
            #pragma unroll
            for (int mi = 0; mi < 2; mi++)
                #pragma unroll
                for (int ni = 0; ni < 8; ni++)
                    mma16bf(acc[mi][ni], af[mi], bf[ni]);
        }
        st ^= 1;
    }
}

// M=64 tile, fp32 out + residual (O-proj, MLP2)
__global__ void __launch_bounds__(128, 4) tc_gemm_res64(
    const __nv_bfloat16* __restrict__ A, const __nv_bfloat16* __restrict__ BT,
    const float* __restrict__ bias, const float* __restrict__ res,
    float* __restrict__ C, int M, int N, int K)
{
    extern __shared__ char smem[];
    const int t = threadIdx.x;
    const int lane = t & 31, warp = t >> 5;
    const int wm = warp >> 1, wn = warp & 1;
    const int g  = lane >> 2, t4 = lane & 3;
    const int bm = blockIdx.y * 64, bn = blockIdx.x * 128;

    float acc[2][8][4];
    #pragma unroll
    for (int mi = 0; mi < 2; mi++)
        #pragma unroll
        for (int ni = 0; ni < 8; ni++)
            #pragma unroll
            for (int c = 0; c < 4; c++) acc[mi][ni][c] = 0.f;

    gemm_mainloop_bf64(A + (size_t)bm * K, BT + (size_t)bn * K, K, smem, acc);

    #pragma unroll
    for (int mi = 0; mi < 2; mi++) {
        #pragma unroll
        for (int half = 0; half < 2; half++) {
            const int row = bm + wm*32 + mi*16 + g + half*8;
            #pragma unroll
            for (int ni = 0; ni < 8; ni++) {
                const int col = bn + wn*64 + ni*8 + t4*2;
                float vx = acc[mi][ni][half*2 + 0] + __ldg(bias + col)
                         + __ldg(res + (size_t)row * N + col);
                float vy = acc[mi][ni][half*2 + 1] + __ldg(bias + col + 1)
                         + __ldg(res + (size_t)row * N + col + 1);
                float2 o; o.x = vx; o.y = vy;
                *reinterpret_cast<float2*>(C + (size_t)row * N + col) = o;
            }
        }
    }
}

// M=64 tile, gelu epilogue, bf16 output (MLP1)
__global__ void __launch_bounds__(128, 4) tc_gemm_gelu64(
    const __nv_bfloat16* __restrict__ A, const __nv_bfloat16* __restrict__ BT,
    const float* __restrict__ bias, __nv_bfloat16* __restrict__ C,
    int M, int N, int K)
{
    extern __shared__ char smem[];
    const int t = threadIdx.x;
    const int lane = t & 31, warp = t >> 5;
    const int wm = warp >> 1, wn = warp & 1;
    const int g  = lane >> 2, t4 = lane & 3;
    const int bm = blockIdx.y * 64, bn = blockIdx.x * 128;

    float acc[2][8][4];
    #pragma unroll
    for (int mi = 0; mi < 2; mi++)
        #pragma unroll
        for (int ni = 0; ni < 8; ni++)
            #pragma unroll
            for (int c = 0; c < 4; c++) acc[mi][ni][c] = 0.f;

    gemm_mainloop_bf64(A + (size_t)bm * K, BT + (size_t)bn * K, K, smem, acc);

    #pragma unroll
    for (int mi = 0; mi < 2; mi++) {
        #pragma unroll
        for (int half = 0; half < 2; half++) {
            const int row = bm + wm*32 + mi*16 + g + half*8;
            #pragma unroll
            for (int ni = 0; ni < 8; ni++) {
                const int col = bn + wn*64 + ni*8 + t4*2;
                float vx = acc[mi][ni][half*2 + 0] + __ldg(bias + col);
                float vy = acc[mi][ni][half*2 + 1] + __ldg(bias + col + 1);
                vx = 0.5f * vx * (1.f + erff(vx * 0.70710678118654752f));
                vy = 0.5f * vy * (1.f + erff(vy * 0.70710678118654752f));
                *reinterpret_cast<unsigned*>(C + (size_t)row * N + col) = pack_bf16(vx, vy);
            }
        }
    }
}

// fused QKV (M128 tile)
__global__ void __launch_bounds__(128, 3) tc_gemm_qkv(
    const __nv_bfloat16* __restrict__ A, const __nv_bfloat16* __restrict__ BT,
    const float* __restrict__ bq, const float* __restrict__ bk,
    const float* __restrict__ bv,
    __nv_bfloat16* __restrict__ q, __nv_bfloat16* __restrict__ k,
    __nv_bfloat16* __restrict__ v, int K)
{
    extern __shared__ char smem[];
    const int t = threadIdx.x;
    const int lane = t & 31, warp = t >> 5;
    const int wm = warp >> 1, wn = warp & 1;
    const int g  = lane >> 2, t4 = lane & 3;
    const int which = blockIdx.x >> 3;
    const int bn = (blockIdx.x & 7) * 128;
    const int bm = blockIdx.y * 128;
    const float* bias = (which == 0) ? bq : (which == 1) ? bk : bv;
    __nv_bfloat16* C  = (which == 0) ? q  : (which == 1) ? k  : v;

    float acc[4][8][4];
    #pragma unroll
    for (int mi = 0; mi < 4; mi++)
        #pragma unroll
        for (int ni = 0; ni < 8; ni++)
            #pragma unroll
            for (int c = 0; c < 4; c++) acc[mi][ni][c] = 0.f;

    gemm_mainloop_bf(A + (size_t)bm * K, BT + (size_t)(which * Ec + bn) * K, K, smem, acc);

    #pragma unroll
    for (int mi = 0; mi < 4; mi++) {
        #pragma unroll
        for (int half = 0; half < 2; half++) {
            const int row = bm + wm*64 + mi*16 + g + half*8;
            #pragma unroll
            for (int ni = 0; ni < 8; ni++) {
                const int col = bn + wn*64 + ni*8 + t4*2;
                float vx = acc[mi][ni][half*2 + 0] + __ldg(bias + col);
                float vy = acc[mi][ni][half*2 + 1] + __ldg(bias + col + 1);
                *reinterpret_cast<unsigned*>(C + (size_t)row * Ec + col) = pack_bf16(vx, vy);
            }
        }
    }
}

// -------- flash attention: all-bf16, register P (FA2), 2 Q-tiles/CTA ----------
#define QS2 72
#define KS2 72
#define VS2 72
#define Q_BYTES (128 * QS2 * 2)
#define K_BYTES (128 * KS2 * 2)
#define V_BYTES (128 * VS2 * 2)
#define ATTN_SMEM (Q_BYTES + 2*K_BYTES + V_BYTES)   // 73728 -> 2 CTAs/SM

__global__ void __launch_bounds__(256, 2) attn_kernel(
    const __nv_bfloat16* __restrict__ q, const __nv_bfloat16* __restrict__ kg,
    const __nv_bfloat16* __restrict__ vg, __nv_bfloat16* __restrict__ ctx)
{
    extern __shared__ char smc[];
    const uint32_t qb = smem_u32(smc);
    const uint32_t kb = qb + Q_BYTES;
    const uint32_t vb = kb + 2 * K_BYTES;

    const int t = threadIdx.x, lane = t & 31, warp = t >> 5;
    const int g = lane >> 2, t4 = lane & 3;
    const int b = blockIdx.y >> 4, h = blockIdx.y & 15;
    const size_t base = (size_t)b * Sc * Ec + (size_t)h * HDc;
    const __nv_bfloat16* kp = kg + base;
    const __nv_bfloat16* vp = vg + base;

    const int frow = ((lane >> 3) & 1) * 8 + (lane & 7);
    const int fcol = ((lane >> 4) & 1) * 8;
    const int brow = lane & 7;
    const int bkof = ((lane >> 3) & 1) * 8;

    const int pr0 = warp*16 + g;
    const uint32_t qA  = qb + ((warp*16 + frow)*QS2 + fcol)*2;
    const uint32_t vBb = vb + (frow*VS2)*2;

    for (int qt = 0; qt < 2; qt++) {
        const size_t qrow0 = (size_t)blockIdx.x * 256 + qt * 128;
        const __nv_bfloat16* qp = q + base + qrow0 * Ec;

        // prologue: Q + K0 (one group)
        #pragma unroll
        for (int i = 0; i < 4; i++) {
            const int idx = t + i*256;
            const int r = idx >> 3, cu = (idx & 7) * 8;
            cp16(qb + (r*QS2 + cu)*2, qp + (size_t)r * Ec + cu);
            cp16(kb + (r*KS2 + cu)*2, kp + (size_t)r * Ec + cu);
        }
        cp_commit();

        float o[8][4];
        #pragma unroll
        for (int ni = 0; ni < 8; ni++)
            #pragma unroll
            for (int c = 0; c < 4; c++) o[ni][c] = 0.f;
        float m0 = -INFINITY, m1 = -INFINITY, l0 = 0.f, l1 = 0.f;

        for (int kt = 0; kt < 16; kt++) {
            __syncthreads();
            #pragma unroll
            for (int i = 0; i < 4; i++) {
                const int idx = t + i*256;
                const int r = idx >> 3, cu = (idx & 7) * 8;
                cp16(vb + (r*VS2 + cu)*2, vp + (size_t)(kt*128 + r) * Ec + cu);
            }
            cp_commit();
            if (kt < 15) {
                const uint32_t kbn = kb + ((kt+1)&1) * K_BYTES;
                #pragma unroll
                for (int i = 0; i < 4; i++) {
                    const int idx = t + i*256;
                    const int r = idx >> 3, cu = (idx & 7) * 8;
                    cp16(kbn + (r*KS2 + cu)*2, kp + (size_t)((kt+1)*128 + r) * Ec + cu);
                }
            }
            cp_commit();
            CP_WAIT(2);
            __syncthreads();

            const uint32_t kB = kb + (kt & 1) * K_BYTES + (brow*KS2 + bkof)*2;

            // S = Q @ K^T (bf16)
            float sacc[16][4];
            #pragma unroll
            for (int ni = 0; ni < 16; ni++)
                #pragma unroll
                for (int c = 0; c < 4; c++) sacc[ni][c] = 0.f;
            #pragma unroll
            for (int kk = 0; kk < 4; kk++) {
                unsigned a[4];
                ldmA(a, qA + kk*32);
                #pragma unroll
                for (int ni = 0; ni < 16; ni++) {
                    unsigned bbf[2];
                    ldmB(bbf, kB + (ni*8*KS2)*2 + kk*32);
                    mma16bf(sacc[ni], a, bbf);
                }
            }

            // online softmax; P stays in registers
            float rm0 = -INFINITY, rm1 = -INFINITY;
            #pragma unroll
            for (int ni = 0; ni < 16; ni++) {
                sacc[ni][0] *= 0.125f; sacc[ni][1] *= 0.125f;
                sacc[ni][2] *= 0.125f; sacc[ni][3] *= 0.125f;
                rm0 = fmaxf(rm0, fmaxf(sacc[ni][0], sacc[ni][1]));
                rm1 = fmaxf(rm1, fmaxf(sacc[ni][2], sacc[ni][3]));
            }
            rm0 = fmaxf(rm0, __shfl_xor_sync(0xffffffffu, rm0, 1));
            rm0 = fmaxf(rm0, __shfl_xor_sync(0xffffffffu, rm0, 2));
            rm1 = fmaxf(rm1, __shfl_xor_sync(0xffffffffu, rm1, 1));
            rm1 = fmaxf(rm1, __shfl_xor_sync(0xffffffffu, rm1, 2));
            const float mn0 = fmaxf(m0, rm0), mn1 = fmaxf(m1, rm1);
            const float al0 = __expf(m0 - mn0), al1 = __expf(m1 - mn1);
            float ps0 = 0.f, ps1 = 0.f;
            #pragma unroll
            for (int ni = 0; ni < 16; ni++) {
                float p0 = __expf(sacc[ni][0] - mn0);
                float p1 = __expf(sacc[ni][1] - mn0);
                float p2 = __expf(sacc[ni][2] - mn1);
                float p3 = __expf(sacc[ni][3] - mn1);
                ps0 += p0 + p1; ps1 += p2 + p3;
                sacc[ni][0] = p0; sacc[ni][1] = p1;
                sacc[ni][2] = p2; sacc[ni][3] = p3;
            }
            ps0 += __shfl_xor_sync(0xffffffffu, ps0, 1);
            ps0 += __shfl_xor_sync(0xffffffffu, ps0, 2);
            ps1 += __shfl_xor_sync(0xffffffffu, ps1, 1);
            ps1 += __shfl_xor_sync(0xffffffffu, ps1, 2);
            l0 = l0 * al0 + ps0; l1 = l1 * al1 + ps1;
            m0 = mn0; m1 = mn1;
            #pragma unroll
            for (int ni = 0; ni < 8; ni++) {
                o[ni][0] *= al0; o[ni][1] *= al0;
                o[ni][2] *= al1; o[ni][3] *= al1;
            }

            CP_WAIT(1);
            __syncthreads();

            // O += P @ V (P A-frag from S accumulators)
            #pragma unroll
            for (int kk = 0; kk < 8; kk++) {
                unsigned a[4];
                a[0] = pack_bf16(sacc[2*kk  ][0], sacc[2*kk  ][1]);
                a[1] = pack_bf16(sacc[2*kk  ][2], sacc[2*kk  ][3]);
                a[2] = pack_bf16(sacc[2*kk+1][0], sacc[2*kk+1][1]);
                a[3] = pack_bf16(sacc[2*kk+1][2], sacc[2*kk+1][3]);
                const uint32_t vB = vBb + kk*16*VS2*2;
                #pragma unroll
                for (int ni = 0; ni < 8; ni++) {
                    unsigned bbf[2];
                    ldmBT(bbf, vB + ni*16);
                    mma16bf(o[ni], a, bbf);
                }
            }
        }

        const float inv0 = 1.f / l0, inv1 = 1.f / l1;
        __nv_bfloat16* cp = ctx + base + qrow0 * Ec;
        #pragma unroll
        for (int ni = 0; ni < 8; ni++) {
            const int d = ni*8 + t4*2;
            *reinterpret_cast<unsigned*>(cp + (size_t)pr0     * Ec + d) =
                pack_bf16(o[ni][0] * inv0, o[ni][1] * inv0);
            *reinterpret_cast<unsigned*>(cp + (size_t)(pr0+8) * Ec + d) =
                pack_bf16(o[ni][2] * inv1, o[ni][3] * inv1);
        }
        __syncthreads();   // fence next qt's Q prologue against stragglers
    }
}

// ---------------- launch ----------------
extern "C" void kernel_launch(void* const* d_in, const int* in_sizes, int n_in,
                              void* d_out, int out_size)
{
    const float* x   = (const float*)d_in[0];
    const float* wq  = (const float*)d_in[1];
    const float* bq  = (const float*)d_in[2];
    const float* wk  = (const float*)d_in[3];
    const float* bk  = (const float*)d_in[4];
    const float* wv  = (const float*)d_in[5];
    const float* bv  = (const float*)d_in[6];
    const float* wo  = (const float*)d_in[7];
    const float* bo  = (const float*)d_in[8];
    const float* w1  = (const float*)d_in[9];
    const float* b1  = (const float*)d_in[10];
    const float* w2  = (const float*)d_in[11];
    const float* b2  = (const float*)d_in[12];
    const float* g1  = (const float*)d_in[13];
    const float* be1 = (const float*)d_in[14];
    const float* g2  = (const float*)d_in[15];
    const float* be2 = (const float*)d_in[16];
    float* out = (float*)d_out;

    __nv_bfloat16 *z0, *z1, *q, *k, *v, *ctx, *h, *wqkvT, *woT, *w1T, *w2T;
    float* x1;
    cudaGetSymbolAddress((void**)&z0,  g_z0);
    cudaGetSymbolAddress((void**)&z1,  g_z1);
    cudaGetSymbolAddress((void**)&q,   g_q);
    cudaGetSymbolAddress((void**)&k,   g_k);
    cudaGetSymbolAddress((void**)&v,   g_v);
    cudaGetSymbolAddress((void**)&ctx, g_ctx);
    cudaGetSymbolAddress((void**)&h,   g_h);
    cudaGetSymbolAddress((void**)&x1,  g_x1);
    cudaGetSymbolAddress((void**)&wqkvT, g_wqkvT);
    cudaGetSymbolAddress((void**)&woT, g_woT);
    cudaGetSymbolAddress((void**)&w1T, g_w1T);
    cudaGetSymbolAddress((void**)&w2T, g_w2T);

    cudaFuncSetAttribute(attn_kernel,    cudaFuncAttributeMaxDynamicSharedMemorySize, ATTN_SMEM);
    cudaFuncSetAttribute(tc_gemm_res64,  cudaFuncAttributeMaxDynamicSharedMemorySize, SMEM_GEMM64);
    cudaFuncSetAttribute(tc_gemm_gelu64, cudaFuncAttributeMaxDynamicSharedMemorySize, SMEM_GEMM64);
    cudaFuncSetAttribute(tc_gemm_qkv,    cudaFuncAttributeMaxDynamicSharedMemorySize, SMEM_GEMM);

    // 1
    ln_kernel<<<TOK, 256>>>(x, g1, be1, z0);
    // 2
    transpose4_bf<<<dim3(32, 32, 4), 256>>>(
        wq, wk, wv, wo,
        wqkvT, wqkvT + (size_t)Ec*Ec, wqkvT + (size_t)2*Ec*Ec, woT);
    // 3
    transpose_bf<<<dim3(MLPc/32, Ec/32), 256>>>(w1, w1T, Ec, MLPc);
    // 4
    transpose_bf<<<dim3(Ec/32, MLPc/32), 256>>>(w2, w2T, MLPc, Ec);
    // 5
    tc_gemm_qkv<<<dim3(24, TOK/128), 128, SMEM_GEMM>>>(z0, wqkvT, bq, bk, bv, q, k, v, Ec);
    // 6: attention, single wave (256 CTAs, 2 Q-tiles each)
    attn_kernel<<<dim3(Sc/256, Bc*Hc), 256, ATTN_SMEM>>>(q, k, v, ctx);
    // 7
    tc_gemm_res64<<<dim3(Ec/128, TOK/64), 128, SMEM_GEMM64>>>(ctx, woT, bo, x, x1, TOK, Ec, Ec);
    // 8
    ln_kernel<<<TOK, 256>>>(x1, g2, be2, z1);
    // 9: MLP1, M64 tile
    tc_gemm_gelu64<<<dim3(MLPc/128, TOK/64), 128, SMEM_GEMM64>>>(z1, w1T, b1, h, TOK, MLPc, Ec);
    // 10
    tc_gemm_res64<<<dim3(Ec/128, TOK/64), 128, SMEM_GEMM64>>>(h, w2T, b2, x1, out, TOK, Ec, MLPc);
}

// round 17
// speedup vs baseline: 2.0548x; 1.0237x over previous
#include <cuda_runtime.h>
#include <cuda_bf16.h>
#include <cstdint>
#include <math.h>

#define Bc   2
#define Sc   2048
#define TOK  4096
#define Ec   1024
#define Hc   16
#define HDc  64
#define MLPc 4096

// ---------------- scratch (no allocations allowed) ----------------
__device__ __nv_bfloat16 g_z0[(size_t)TOK * Ec];
__device__ __nv_bfloat16 g_z1[(size_t)TOK * Ec];
__device__ __nv_bfloat16 g_q[(size_t)TOK * Ec];
__device__ __nv_bfloat16 g_k[(size_t)TOK * Ec];
__device__ __nv_bfloat16 g_v[(size_t)TOK * Ec];
__device__ __nv_bfloat16 g_ctx[(size_t)TOK * Ec];
__device__ __nv_bfloat16 g_h[(size_t)TOK * MLPc];
__device__ float g_x1[(size_t)TOK * Ec];
__device__ __nv_bfloat16 g_wqkvT[(size_t)3 * Ec * Ec];   // [3N][K]
__device__ __nv_bfloat16 g_woT[(size_t)Ec * Ec];         // [N][K]
__device__ __nv_bfloat16 g_w1T[(size_t)MLPc * Ec];       // [4096][1024]
__device__ __nv_bfloat16 g_w2T[(size_t)Ec * MLPc];       // [1024][4096]

// ---------------- helpers ----------------
__device__ __forceinline__ unsigned pack_bf16(float lo, float hi) {
    unsigned r;
    asm("cvt.rn.bf16x2.f32 %0, %1, %2;" : "=r"(r) : "f"(hi), "f"(lo));
    return r;
}
__device__ __forceinline__ uint32_t smem_u32(const void* p) {
    uint32_t a;
    asm("{ .reg .u64 t; cvta.to.shared.u64 t, %1; cvt.u32.u64 %0, t; }" : "=r"(a) : "l"(p));
    return a;
}
__device__ __forceinline__ void cp16(uint32_t d, const void* s) {
    asm volatile("cp.async.cg.shared.global [%0], [%1], 16;\n" :: "r"(d), "l"(s));
}
__device__ __forceinline__ void cp_commit() {
    asm volatile("cp.async.commit_group;\n" ::: "memory");
}
#define CP_WAIT(n) asm volatile("cp.async.wait_group %0;\n" :: "n"(n) : "memory")

__device__ __forceinline__ void mma16bf(float c[4], const unsigned a[4], const unsigned b[2]) {
    asm volatile(
        "mma.sync.aligned.m16n8k16.row.col.f32.bf16.bf16.f32 "
        "{%0,%1,%2,%3}, {%4,%5,%6,%7}, {%8,%9}, {%0,%1,%2,%3};\n"
        : "+f"(c[0]), "+f"(c[1]), "+f"(c[2]), "+f"(c[3])
        : "r"(a[0]), "r"(a[1]), "r"(a[2]), "r"(a[3]),
          "r"(b[0]), "r"(b[1]));
}
__device__ __forceinline__ void ldmA(unsigned a[4], uint32_t addr) {
    asm volatile("ldmatrix.sync.aligned.m8n8.x4.shared.b16 {%0,%1,%2,%3}, [%4];"
                 : "=r"(a[0]), "=r"(a[1]), "=r"(a[2]), "=r"(a[3]) : "r"(addr));
}
__device__ __forceinline__ void ldmB(unsigned b[2], uint32_t addr) {
    asm volatile("ldmatrix.sync.aligned.m8n8.x2.shared.b16 {%0,%1}, [%2];"
                 : "=r"(b[0]), "=r"(b[1]) : "r"(addr));
}
__device__ __forceinline__ void ldmBT(unsigned b[2], uint32_t addr) {
    asm volatile("ldmatrix.sync.aligned.m8n8.x2.trans.shared.b16 {%0,%1}, [%2];"
                 : "=r"(b[0]), "=r"(b[1]) : "r"(addr));
}

// -------- weight transpose + bf16 convert --------
__global__ void __launch_bounds__(256) transpose4_bf(
    const float* __restrict__ i0, const float* __restrict__ i1,
    const float* __restrict__ i2, const float* __restrict__ i3,
    __nv_bfloat16* __restrict__ o0, __nv_bfloat16* __restrict__ o1,
    __nv_bfloat16* __restrict__ o2, __nv_bfloat16* __restrict__ o3)
{
    const float* in = (blockIdx.z == 0) ? i0 : (blockIdx.z == 1) ? i1 : (blockIdx.z == 2) ? i2 : i3;
    __nv_bfloat16* out = (blockIdx.z == 0) ? o0 : (blockIdx.z == 1) ? o1 : (blockIdx.z == 2) ? o2 : o3;
    __shared__ float tile[32][33];
    const int bx = blockIdx.x * 32, by = blockIdx.y * 32;
    const int tx = threadIdx.x & 31, ty = threadIdx.x >> 5;
    #pragma unroll
    for (int i = 0; i < 32; i += 8)
        tile[ty + i][tx] = in[(size_t)(by + ty + i) * Ec + bx + tx];
    __syncthreads();
    #pragma unroll
    for (int i = 0; i < 32; i += 8)
        out[(size_t)(bx + ty + i) * Ec + by + tx] = __float2bfloat16(tile[tx][ty + i]);
}

__global__ void __launch_bounds__(256) transpose_bf(
    const float* __restrict__ in, __nv_bfloat16* __restrict__ out, int R, int C)
{
    __shared__ float tile[32][33];
    const int bx = blockIdx.x * 32, by = blockIdx.y * 32;
    const int tx = threadIdx.x & 31, ty = threadIdx.x >> 5;
    #pragma unroll
    for (int i = 0; i < 32; i += 8)
        tile[ty + i][tx] = in[(size_t)(by + ty + i) * C + bx + tx];
    __syncthreads();
    #pragma unroll
    for (int i = 0; i < 32; i += 8)
        out[(size_t)(bx + ty + i) * R + by + tx] = __float2bfloat16(tile[tx][ty + i]);
}

// ---------------- LayerNorm (fp32 exact, bf16 output) ----------------
__global__ void __launch_bounds__(256) ln_kernel(
    const float* __restrict__ x, const float* __restrict__ gam,
    const float* __restrict__ bet, __nv_bfloat16* __restrict__ y)
{
    const int row = blockIdx.x, t = threadIdx.x;
    const float4* xr = reinterpret_cast<const float4*>(x + (size_t)row * Ec);
    float4 v = xr[t];
    float s  = v.x + v.y + v.z + v.w;
    float ss = v.x*v.x + v.y*v.y + v.z*v.z + v.w*v.w;
    #pragma unroll
    for (int o = 16; o; o >>= 1) {
        s  += __shfl_xor_sync(0xffffffffu, s,  o);
        ss += __shfl_xor_sync(0xffffffffu, ss, o);
    }
    __shared__ float rs[8], rss[8];
    if ((t & 31) == 0) { rs[t >> 5] = s; rss[t >> 5] = ss; }
    __syncthreads();
    if (t < 32) {
        float a = (t < 8) ? rs[t]  : 0.f;
        float b = (t < 8) ? rss[t] : 0.f;
        #pragma unroll
        for (int o = 4; o; o >>= 1) {
            a += __shfl_xor_sync(0xffffffffu, a, o);
            b += __shfl_xor_sync(0xffffffffu, b, o);
        }
        if (t == 0) { rs[0] = a; rss[0] = b; }
    }
    __syncthreads();
    const float mu   = rs[0]  * (1.f / Ec);
    const float var  = rss[0] * (1.f / Ec) - mu * mu;
    const float rstd = rsqrtf(var + 1e-5f);
    float4 gv = reinterpret_cast<const float4*>(gam)[t];
    float4 bv = reinterpret_cast<const float4*>(bet)[t];
    uint2 u;
    u.x = pack_bf16((v.x - mu) * rstd * gv.x + bv.x, (v.y - mu) * rstd * gv.y + bv.y);
    u.y = pack_bf16((v.z - mu) * rstd * gv.z + bv.z, (v.w - mu) * rstd * gv.w + bv.w);
    reinterpret_cast<uint2*>(y + (size_t)row * Ec)[t] = u;
}

// ---- common tiling constants ----
#define KT2   64
#define SW2   72
#define STG2  (128 * SW2 * 2)
#define NSTG  2

// ---- BF16 GEMM core (M64 tile): 4 CTA/SM ----
#define ASTG64 (64 * SW2 * 2)
#define SMEM_GEMM64 (NSTG * (ASTG64 + STG2))   // 55296 -> 4 CTAs/SM

__device__ __forceinline__ void ldstage_bf64(uint32_t ab, uint32_t bb,
    const __nv_bfloat16* __restrict__ Ap, const __nv_bfloat16* __restrict__ Bp,
    int K, int kt)
{
    const int t = threadIdx.x;
    const int k0 = kt * KT2;
    #pragma unroll
    for (int i = 0; i < 4; i++) {
        const int idx = t + i * 128;
        const int r = idx >> 3, cu = (idx & 7) * 8;
        cp16(ab + (r * SW2 + cu) * 2, Ap + (size_t)r * K + k0 + cu);
    }
    #pragma unroll
    for (int i = 0; i < 8; i++) {
        const int idx = t + i * 128;
        const int r = idx >> 3, cu = (idx & 7) * 8;
        cp16(bb + (r * SW2 + cu) * 2, Bp + (size_t)r * K + k0 + cu);
    }
}

__device__ __forceinline__ void gemm_mainloop_bf64(
    const __nv_bfloat16* __restrict__ Ap, const __nv_bfloat16* __restrict__ Bp,
    int K, char* smem, float acc[2][8][4])
{
    const int t    = threadIdx.x;
    const int lane = t & 31, warp = t >> 5;
    const int wm = warp >> 1, wn = warp & 1;
    const int NK = K / KT2;

    const uint32_t asb = smem_u32(smem);
    const uint32_t bsb = asb + NSTG * ASTG64;

    const int frow = ((lane >> 3) & 1) * 8 + (lane & 7);
    const int fcol = ((lane >> 4) & 1) * 8;
    const int brow = lane & 7;
    const int bkof = ((lane >> 3) & 1) * 8;

    ldstage_bf64(asb, bsb, Ap, Bp, K, 0);
    cp_commit();

    int st = 0;
    for (int kt = 0; kt < NK; kt++) {
        CP_WAIT(0);
        __syncthreads();
        if (kt + 1 < NK) {
            const int ps = st ^ 1;
            ldstage_bf64(asb + ps * ASTG64, bsb + ps * STG2, Ap, Bp, K, kt + 1);
        }
        cp_commit();

        const uint32_t aB = asb + st * ASTG64 + ((wm*32 + frow) * SW2 + fcol) * 2;
        const uint32_t bB = bsb + st * STG2   + ((wn*64 + brow) * SW2 + bkof) * 2;
        #pragma unroll
        for (int kk = 0; kk < 4; kk++) {
            unsigned af[2][4], bf[8][2];
            #pragma unroll
            for (int mi = 0; mi < 2; mi++)
                ldmA(af[mi], aB + mi*16*SW2*2 + kk*32);
            #pragma unroll
            for (int ni = 0; ni < 8; ni++)
                ldmB(bf[ni], bB + ni*8*SW2*2 + kk*32);
            #pragma unroll
            for (int mi = 0; mi < 2; mi++)
                #pragma unroll
                for (int ni = 0; ni < 8; ni++)
                    mma16bf(acc[mi][ni], af[mi], bf[ni]);
        }
        st ^= 1;
    }
}

// M=64 tile, fp32 out + residual (O-proj, MLP2)
__global__ void __launch_bounds__(128, 4) tc_gemm_res64(
    const __nv_bfloat16* __restrict__ A, const __nv_bfloat16* __restrict__ BT,
    const float* __restrict__ bias, const float* __restrict__ res,
    float* __restrict__ C, int M, int N, int K)
{
    extern __shared__ char smem[];
    const int t = threadIdx.x;
    const int lane = t & 31, warp = t >> 5;
    const int wm = warp >> 1, wn = warp & 1;
    const int g  = lane >> 2, t4 = lane & 3;
    const int bm = blockIdx.y * 64, bn = blockIdx.x * 128;

    float acc[2][8][4];
    #pragma unroll
    for (int mi = 0; mi < 2; mi++)
        #pragma unroll
        for (int ni = 0; ni < 8; ni++)
            #pragma unroll
            for (int c = 0; c < 4; c++) acc[mi][ni][c] = 0.f;

    gemm_mainloop_bf64(A + (size_t)bm * K, BT + (size_t)bn * K, K, smem, acc);

    #pragma unroll
    for (int mi = 0; mi < 2; mi++) {
        #pragma unroll
        for (int half = 0; half < 2; half++) {
            const int row = bm + wm*32 + mi*16 + g + half*8;
            #pragma unroll
            for (int ni = 0; ni < 8; ni++) {
                const int col = bn + wn*64 + ni*8 + t4*2;
                float vx = acc[mi][ni][half*2 + 0] + __ldg(bias + col)
                         + __ldg(res + (size_t)row * N + col);
                float vy = acc[mi][ni][half*2 + 1] + __ldg(bias + col + 1)
                         + __ldg(res + (size_t)row * N + col + 1);
                float2 o; o.x = vx; o.y = vy;
                *reinterpret_cast<float2*>(C + (size_t)row * N + col) = o;
            }
        }
    }
}

// M=64 tile, gelu epilogue, bf16 output (MLP1)
__global__ void __launch_bounds__(128, 4) tc_gemm_gelu64(
    const __nv_bfloat16* __restrict__ A, const __nv_bfloat16* __restrict__ BT,
    const float* __restrict__ bias, __nv_bfloat16* __restrict__ C,
    int M, int N, int K)
{
    extern __shared__ char smem[];
    const int t = threadIdx.x;
    const int lane = t & 31, warp = t >> 5;
    const int wm = warp >> 1, wn = warp & 1;
    const int g  = lane >> 2, t4 = lane & 3;
    const int bm = blockIdx.y * 64, bn = blockIdx.x * 128;

    float acc[2][8][4];
    #pragma unroll
    for (int mi = 0; mi < 2; mi++)
        #pragma unroll
        for (int ni = 0; ni < 8; ni++)
            #pragma unroll
            for (int c = 0; c < 4; c++) acc[mi][ni][c] = 0.f;

    gemm_mainloop_bf64(A + (size_t)bm * K, BT + (size_t)bn * K, K, smem, acc);

    #pragma unroll
    for (int mi = 0; mi < 2; mi++) {
        #pragma unroll
        for (int half = 0; half < 2; half++) {
            const int row = bm + wm*32 + mi*16 + g + half*8;
            #pragma unroll
            for (int ni = 0; ni < 8; ni++) {
                const int col = bn + wn*64 + ni*8 + t4*2;
                float vx = acc[mi][ni][half*2 + 0] + __ldg(bias + col);
                float vy = acc[mi][ni][half*2 + 1] + __ldg(bias + col + 1);
                vx = 0.5f * vx * (1.f + erff(vx * 0.70710678118654752f));
                vy = 0.5f * vy * (1.f + erff(vy * 0.70710678118654752f));
                *reinterpret_cast<unsigned*>(C + (size_t)row * N + col) = pack_bf16(vx, vy);
            }
        }
    }
}

// M=64 tile, fused QKV epilogue (bf16 outputs)
__global__ void __launch_bounds__(128, 4) tc_gemm_qkv64(
    const __nv_bfloat16* __restrict__ A, const __nv_bfloat16* __restrict__ BT,
    const float* __restrict__ bq, const float* __restrict__ bk,
    const float* __restrict__ bv,
    __nv_bfloat16* __restrict__ q, __nv_bfloat16* __restrict__ k,
    __nv_bfloat16* __restrict__ v, int K)
{
    extern __shared__ char smem[];
    const int t = threadIdx.x;
    const int lane = t & 31, warp = t >> 5;
    const int wm = warp >> 1, wn = warp & 1;
    const int g  = lane >> 2, t4 = lane & 3;
    const int which = blockIdx.x >> 3;
    const int bn = (blockIdx.x & 7) * 128;
    const int bm = blockIdx.y * 64;
    const float* bias = (which == 0) ? bq : (which == 1) ? bk : bv;
    __nv_bfloat16* C  = (which == 0) ? q  : (which == 1) ? k  : v;

    float acc[2][8][4];
    #pragma unroll
    for (int mi = 0; mi < 2; mi++)
        #pragma unroll
        for (int ni = 0; ni < 8; ni++)
            #pragma unroll
            for (int c = 0; c < 4; c++) acc[mi][ni][c] = 0.f;

    gemm_mainloop_bf64(A + (size_t)bm * K, BT + (size_t)(which * Ec + bn) * K, K, smem, acc);

    #pragma unroll
    for (int mi = 0; mi < 2; mi++) {
        #pragma unroll
        for (int half = 0; half < 2; half++) {
            const int row = bm + wm*32 + mi*16 + g + half*8;
            #pragma unroll
            for (int ni = 0; ni < 8; ni++) {
                const int col = bn + wn*64 + ni*8 + t4*2;
                float vx = acc[mi][ni][half*2 + 0] + __ldg(bias + col);
                float vy = acc[mi][ni][half*2 + 1] + __ldg(bias + col + 1);
                *reinterpret_cast<unsigned*>(C + (size_t)row * Ec + col) = pack_bf16(vx, vy);
            }
        }
    }
}

// -------- flash attention: all-bf16, register P (FA2), 2 Q-tiles/CTA ----------
#define QS2 72
#define KS2 72
#define VS2 72
#define Q_BYTES (128 * QS2 * 2)
#define K_BYTES (128 * KS2 * 2)
#define V_BYTES (128 * VS2 * 2)
#define ATTN_SMEM (Q_BYTES + 2*K_BYTES + V_BYTES)   // 73728 -> 2 CTAs/SM

__global__ void __launch_bounds__(256, 2) attn_kernel(
    const __nv_bfloat16* __restrict__ q, const __nv_bfloat16* __restrict__ kg,
    const __nv_bfloat16* __restrict__ vg, __nv_bfloat16* __restrict__ ctx)
{
    extern __shared__ char smc[];
    const uint32_t qb = smem_u32(smc);
    const uint32_t kb = qb + Q_BYTES;
    const uint32_t vb = kb + 2 * K_BYTES;

    const int t = threadIdx.x, lane = t & 31, warp = t >> 5;
    const int g = lane >> 2, t4 = lane & 3;
    const int b = blockIdx.y >> 4, h = blockIdx.y & 15;
    const size_t base = (size_t)b * Sc * Ec + (size_t)h * HDc;
    const __nv_bfloat16* kp = kg + base;
    const __nv_bfloat16* vp = vg + base;

    const int frow = ((lane >> 3) & 1) * 8 + (lane & 7);
    const int fcol = ((lane >> 4) & 1) * 8;
    const int brow = lane & 7;
    const int bkof = ((lane >> 3) & 1) * 8;

    const int pr0 = warp*16 + g;
    const uint32_t qA  = qb + ((warp*16 + frow)*QS2 + fcol)*2;
    const uint32_t vBb = vb + (frow*VS2)*2;

    for (int qt = 0; qt < 2; qt++) {
        const size_t qrow0 = (size_t)blockIdx.x * 256 + qt * 128;
        const __nv_bfloat16* qp = q + base + qrow0 * Ec;

        #pragma unroll
        for (int i = 0; i < 4; i++) {
            const int idx = t + i*256;
            const int r = idx >> 3, cu = (idx & 7) * 8;
            cp16(qb + (r*QS2 + cu)*2, qp + (size_t)r * Ec + cu);
            cp16(kb + (r*KS2 + cu)*2, kp + (size_t)r * Ec + cu);
        }
        cp_commit();

        float o[8][4];
        #pragma unroll
        for (int ni = 0; ni < 8; ni++)
            #pragma unroll
            for (int c = 0; c < 4; c++) o[ni][c] = 0.f;
        float m0 = -INFINITY, m1 = -INFINITY, l0 = 0.f, l1 = 0.f;

        for (int kt = 0; kt < 16; kt++) {
            __syncthreads();
            #pragma unroll
            for (int i = 0; i < 4; i++) {
                const int idx = t + i*256;
                const int r = idx >> 3, cu = (idx & 7) * 8;
                cp16(vb + (r*VS2 + cu)*2, vp + (size_t)(kt*128 + r) * Ec + cu);
            }
            cp_commit();
            if (kt < 15) {
                const uint32_t kbn = kb + ((kt+1)&1) * K_BYTES;
                #pragma unroll
                for (int i = 0; i < 4; i++) {
                    const int idx = t + i*256;
                    const int r = idx >> 3, cu = (idx & 7) * 8;
                    cp16(kbn + (r*KS2 + cu)*2, kp + (size_t)((kt+1)*128 + r) * Ec + cu);
                }
            }
            cp_commit();
            CP_WAIT(2);
            __syncthreads();

            const uint32_t kB = kb + (kt & 1) * K_BYTES + (brow*KS2 + bkof)*2;

            float sacc[16][4];
            #pragma unroll
            for (int ni = 0; ni < 16; ni++)
                #pragma unroll
                for (int c = 0; c < 4; c++) sacc[ni][c] = 0.f;
            #pragma unroll
            for (int kk = 0; kk < 4; kk++) {
                unsigned a[4];
                ldmA(a, qA + kk*32);
                #pragma unroll
                for (int ni = 0; ni < 16; ni++) {
                    unsigned bbf[2];
                    ldmB(bbf, kB + (ni*8*KS2)*2 + kk*32);
                    mma16bf(sacc[ni], a, bbf);
                }
            }

            float rm0 = -INFINITY, rm1 = -INFINITY;
            #pragma unroll
            for (int ni = 0; ni < 16; ni++) {
                sacc[ni][0] *= 0.125f; sacc[ni][1] *= 0.125f;
                sacc[ni][2] *= 0.125f; sacc[ni][3] *= 0.125f;
                rm0 = fmaxf(rm0, fmaxf(sacc[ni][0], sacc[ni][1]));
                rm1 = fmaxf(rm1, fmaxf(sacc[ni][2], sacc[ni][3]));
            }
            rm0 = fmaxf(rm0, __shfl_xor_sync(0xffffffffu, rm0, 1));
            rm0 = fmaxf(rm0, __shfl_xor_sync(0xffffffffu, rm0, 2));
            rm1 = fmaxf(rm1, __shfl_xor_sync(0xffffffffu, rm1, 1));
            rm1 = fmaxf(rm1, __shfl_xor_sync(0xffffffffu, rm1, 2));
            const float mn0 = fmaxf(m0, rm0), mn1 = fmaxf(m1, rm1);
            const float al0 = __expf(m0 - mn0), al1 = __expf(m1 - mn1);
            float ps0 = 0.f, ps1 = 0.f;
            #pragma unroll
            for (int ni = 0; ni < 16; ni++) {
                float p0 = __expf(sacc[ni][0] - mn0);
                float p1 = __expf(sacc[ni][1] - mn0);
                float p2 = __expf(sacc[ni][2] - mn1);
                float p3 = __expf(sacc[ni][3] - mn1);
                ps0 += p0 + p1; ps1 += p2 + p3;
                sacc[ni][0] = p0; sacc[ni][1] = p1;
                sacc[ni][2] = p2; sacc[ni][3] = p3;
            }
            ps0 += __shfl_xor_sync(0xffffffffu, ps0, 1);
            ps0 += __shfl_xor_sync(0xffffffffu, ps0, 2);
            ps1 += __shfl_xor_sync(0xffffffffu, ps1, 1);
            ps1 += __shfl_xor_sync(0xffffffffu, ps1, 2);
            l0 = l0 * al0 + ps0; l1 = l1 * al1 + ps1;
            m0 = mn0; m1 = mn1;
            #pragma unroll
            for (int ni = 0; ni < 8; ni++) {
                o[ni][0] *= al0; o[ni][1] *= al0;
                o[ni][2] *= al1; o[ni][3] *= al1;
            }

            CP_WAIT(1);
            __syncthreads();

            #pragma unroll
            for (int kk = 0; kk < 8; kk++) {
                unsigned a[4];
                a[0] = pack_bf16(sacc[2*kk  ][0], sacc[2*kk  ][1]);
                a[1] = pack_bf16(sacc[2*kk  ][2], sacc[2*kk  ][3]);
                a[2] = pack_bf16(sacc[2*kk+1][0], sacc[2*kk+1][1]);
                a[3] = pack_bf16(sacc[2*kk+1][2], sacc[2*kk+1][3]);
                const uint32_t vB = vBb + kk*16*VS2*2;
                #pragma unroll
                for (int ni = 0; ni < 8; ni++) {
                    unsigned bbf[2];
                    ldmBT(bbf, vB + ni*16);
                    mma16bf(o[ni], a, bbf);
                }
            }
        }

        const float inv0 = 1.f / l0, inv1 = 1.f / l1;
        __nv_bfloat16* cp = ctx + base + qrow0 * Ec;
        #pragma unroll
        for (int ni = 0; ni < 8; ni++) {
            const int d = ni*8 + t4*2;
            *reinterpret_cast<unsigned*>(cp + (size_t)pr0     * Ec + d) =
                pack_bf16(o[ni][0] * inv0, o[ni][1] * inv0);
            *reinterpret_cast<unsigned*>(cp + (size_t)(pr0+8) * Ec + d) =
                pack_bf16(o[ni][2] * inv1, o[ni][3] * inv1);
        }
        __syncthreads();
    }
}

// ---------------- launch ----------------
extern "C" void kernel_launch(void* const* d_in, const int* in_sizes, int n_in,
                              void* d_out, int out_size)
{
    const float* x   = (const float*)d_in[0];
    const float* wq  = (const float*)d_in[1];
    const float* bq  = (const float*)d_in[2];
    const float* wk  = (const float*)d_in[3];
    const float* bk  = (const float*)d_in[4];
    const float* wv  = (const float*)d_in[5];
    const float* bv  = (const float*)d_in[6];
    const float* wo  = (const float*)d_in[7];
    const float* bo  = (const float*)d_in[8];
    const float* w1  = (const float*)d_in[9];
    const float* b1  = (const float*)d_in[10];
    const float* w2  = (const float*)d_in[11];
    const float* b2  = (const float*)d_in[12];
    const float* g1  = (const float*)d_in[13];
    const float* be1 = (const float*)d_in[14];
    const float* g2  = (const float*)d_in[15];
    const float* be2 = (const float*)d_in[16];
    float* out = (float*)d_out;

    __nv_bfloat16 *z0, *z1, *q, *k, *v, *ctx, *h, *wqkvT, *woT, *w1T, *w2T;
    float* x1;
    cudaGetSymbolAddress((void**)&z0,  g_z0);
    cudaGetSymbolAddress((void**)&z1,  g_z1);
    cudaGetSymbolAddress((void**)&q,   g_q);
    cudaGetSymbolAddress((void**)&k,   g_k);
    cudaGetSymbolAddress((void**)&v,   g_v);
    cudaGetSymbolAddress((void**)&ctx, g_ctx);
    cudaGetSymbolAddress((void**)&h,   g_h);
    cudaGetSymbolAddress((void**)&x1,  g_x1);
    cudaGetSymbolAddress((void**)&wqkvT, g_wqkvT);
    cudaGetSymbolAddress((void**)&woT, g_woT);
    cudaGetSymbolAddress((void**)&w1T, g_w1T);
    cudaGetSymbolAddress((void**)&w2T, g_w2T);

    cudaFuncSetAttribute(attn_kernel,    cudaFuncAttributeMaxDynamicSharedMemorySize, ATTN_SMEM);
    cudaFuncSetAttribute(tc_gemm_res64,  cudaFuncAttributeMaxDynamicSharedMemorySize, SMEM_GEMM64);
    cudaFuncSetAttribute(tc_gemm_gelu64, cudaFuncAttributeMaxDynamicSharedMemorySize, SMEM_GEMM64);
    cudaFuncSetAttribute(tc_gemm_qkv64,  cudaFuncAttributeMaxDynamicSharedMemorySize, SMEM_GEMM64);

    // 1
    ln_kernel<<<TOK, 256>>>(x, g1, be1, z0);
    // 2
    transpose4_bf<<<dim3(32, 32, 4), 256>>>(
        wq, wk, wv, wo,
        wqkvT, wqkvT + (size_t)Ec*Ec, wqkvT + (size_t)2*Ec*Ec, woT);
    // 3
    transpose_bf<<<dim3(MLPc/32, Ec/32), 256>>>(w1, w1T, Ec, MLPc);
    // 4
    transpose_bf<<<dim3(Ec/32, MLPc/32), 256>>>(w2, w2T, MLPc, Ec);
    // 5: QKV, M64 tile (grid 1536)
    tc_gemm_qkv64<<<dim3(24, TOK/64), 128, SMEM_GEMM64>>>(z0, wqkvT, bq, bk, bv, q, k, v, Ec);
    // 6: attention, single wave
    attn_kernel<<<dim3(Sc/256, Bc*Hc), 256, ATTN_SMEM>>>(q, k, v, ctx);
    // 7
    tc_gemm_res64<<<dim3(Ec/128, TOK/64), 128, SMEM_GEMM64>>>(ctx, woT, bo, x, x1, TOK, Ec, Ec);
    // 8
    ln_kernel<<<TOK, 256>>>(x1, g2, be2, z1);
    // 9
    tc_gemm_gelu64<<<dim3(MLPc/128, TOK/64), 128, SMEM_GEMM64>>>(z1, w1T, b1, h, TOK, MLPc, Ec);
    // 10
    tc_gemm_res64<<<dim3(Ec/128, TOK/64), 128, SMEM_GEMM64>>>(h, w2T, b2, x1, out, TOK, Ec, MLPc);
}